// round 7
// baseline (speedup 1.0000x reference)
#include <cuda_runtime.h>
#include <math.h>
#include <stdint.h>

// ---------------- problem constants ----------------
#define Bn   4
#define Sn   512
#define Dm   1024
#define Hn   16
#define HD   64
#define En   8
#define FF   2048
#define Ln   2
#define VT   32000
#define TOK  (Bn*Sn)      // 2048 tokens

#define KT   32           // K-tile
#define AST  36           // [m][k] smem stride (u32): g*36+t4 ≡ g*4+t4 distinct mod 32
#define BWST 136          // [k][n] smem stride (u32): t4*8+g distinct mod 32

#define ASZ   (128*AST)           // 4608 u32 (per hi or lo)
#define B0SZ  (KT*BWST)           // 4352 u32 (raw fp32 B)
#define STG0  (2*ASZ + B0SZ)      // 13568 u32
#define STG1  (2*ASZ + 2*ASZ)     // 18432 u32
#define SMEM0_BYTES (2*STG0*4)    // 108544
#define SMEM1_BYTES (2*STG1*4)    // 147456

// ---------------- device scratch (no allocations allowed) ----------------
__device__ float    g_x[TOK*Dm];
__device__ float    g_y[TOK*Dm];
__device__ uint32_t g_xh[TOK*Dm], g_xl[TOK*Dm];
__device__ uint32_t g_yh[TOK*Dm], g_yl[TOK*Dm];
__device__ float    g_lin0[TOK*Dm];
__device__ float    g_lin1[TOK*Dm];
__device__ float    g_lin2[TOK*Dm];
__device__ uint32_t g_qh[TOK*Dm], g_ql[TOK*Dm];
__device__ uint32_t g_kh[TOK*Dm], g_kl[TOK*Dm];
__device__ float    g_v[TOK*Dm];                               // raw fp32 V (B-side)
__device__ float    g_sc[(size_t)Bn*Hn*Sn*Sn];
__device__ uint32_t g_sch[(size_t)Bn*Hn*Sn*Sn], g_scl[(size_t)Bn*Hn*Sn*Sn];
__device__ float    g_att[TOK*Dm];
__device__ uint32_t g_atth[TOK*Dm], g_attl[TOK*Dm];
__device__ float    g_proj[TOK*Dm];
__device__ uint32_t g_h1h[(size_t)En*TOK*FF], g_h1l[(size_t)En*TOK*FF];
__device__ float    g_moe0[TOK*Dm];
__device__ float    g_moe1[TOK*Dm];
__device__ float    g_gate[TOK*En];
__device__ float    g_topw[TOK*2];
__device__ int      g_list[En*TOK];
__device__ int      g_cnt[En];
__device__ float    g_cos[Sn*HD];
__device__ float    g_sin[Sn*HD];

// ---------------- tf32 / cp.async helpers ----------------
__device__ __forceinline__ uint32_t f2tf(float f) {
    uint32_t r;
    asm("cvt.rna.tf32.f32 %0, %1;" : "=r"(r) : "f"(f));
    return r;
}
__device__ __forceinline__ void sp(float v, uint32_t& h, uint32_t& l) {
    h = f2tf(v);
    l = f2tf(v - __uint_as_float(h));
}
__device__ __forceinline__ uint32_t smem_u32(const void* p) {
    return (uint32_t)__cvta_generic_to_shared(p);
}
__device__ __forceinline__ void cp16(uint32_t dst, const void* src) {
    asm volatile("cp.async.cg.shared.global [%0], [%1], 16;" :: "r"(dst), "l"(src));
}
__device__ __forceinline__ void cp16z(uint32_t dst, const void* src, bool ok) {
    int sz = ok ? 16 : 0;
    asm volatile("cp.async.cg.shared.global [%0], [%1], 16, %2;" :: "r"(dst), "l"(src), "r"(sz));
}
#define CP_COMMIT() asm volatile("cp.async.commit_group;")
#define CP_WAIT1()  asm volatile("cp.async.wait_group 1;")
#define CP_WAIT0()  asm volatile("cp.async.wait_group 0;")

__device__ __forceinline__ void mma_tf32(float* c, const uint32_t* a, const uint32_t* b) {
    asm volatile(
        "mma.sync.aligned.m16n8k8.row.col.f32.tf32.tf32.f32 "
        "{%0,%1,%2,%3}, {%4,%5,%6,%7}, {%8,%9}, {%0,%1,%2,%3};"
        : "+f"(c[0]), "+f"(c[1]), "+f"(c[2]), "+f"(c[3])
        : "r"(a[0]), "r"(a[1]), "r"(a[2]), "r"(a[3]), "r"(b[0]), "r"(b[1]));
}

// 16 warps: wm = warp>>2 (m), wn = warp&3 (n). Warp tile 32x32: mt 0..1, nt 0..3.
// Per k-tile: ks 0..3, each covers k8 pair (kr, kr+4).
// BGETH/BGETL produce the hi/lo B fragment values for (kr_, nb_).
#define MMA_COMPUTE_512(BH0, BL0, BH1, BL1)                                        \
  { const int moff = wm * 32, noff = wn * 32;                                      \
    _Pragma("unroll")                                                              \
    for (int ks = 0; ks < 4; ks++) {                                               \
        const int kr = ks * 8 + t4;                                                \
        uint32_t afH[2][4], afL[2][4], bfH[4][2], bfL[4][2];                       \
        _Pragma("unroll")                                                          \
        for (int mt = 0; mt < 2; mt++) {                                           \
            int mb = moff + mt * 16 + g;                                           \
            afH[mt][0] = Ah_s[mb * AST + kr];                                      \
            afL[mt][0] = Al_s[mb * AST + kr];                                      \
            afH[mt][1] = Ah_s[(mb + 8) * AST + kr];                                \
            afL[mt][1] = Al_s[(mb + 8) * AST + kr];                                \
            afH[mt][2] = Ah_s[mb * AST + kr + 4];                                  \
            afL[mt][2] = Al_s[mb * AST + kr + 4];                                  \
            afH[mt][3] = Ah_s[(mb + 8) * AST + kr + 4];                            \
            afL[mt][3] = Al_s[(mb + 8) * AST + kr + 4];                            \
        }                                                                          \
        _Pragma("unroll")                                                          \
        for (int nt = 0; nt < 4; nt++) {                                           \
            int nb = noff + nt * 8 + g;                                            \
            bfH[nt][0] = (BH0); bfL[nt][0] = (BL0);                                \
            bfH[nt][1] = (BH1); bfL[nt][1] = (BL1);                                \
        }                                                                          \
        _Pragma("unroll")                                                          \
        for (int mt = 0; mt < 2; mt++)                                             \
            _Pragma("unroll")                                                      \
            for (int nt = 0; nt < 4; nt++) {                                       \
                mma_tf32(acc[mt][nt], afH[mt], bfL[nt]);                           \
                mma_tf32(acc[mt][nt], afL[mt], bfH[nt]);                           \
                mma_tf32(acc[mt][nt], afH[mt], bfH[nt]);                           \
            }                                                                      \
    } }

// =====================================================================
// hi/lo 3xTF32 GEMM, 512 threads, KT=32, 2-stage cp.async.
// BT=0: A pre-split hi/lo, B raw fp32 [K,N] (split in-kernel).
// BT=1: A and B both pre-split hi/lo, B [N,K] (NT).
// M%128==0, K%32==0. N guarded for BT=0.
// =====================================================================
template<int BT>
__global__ void __launch_bounds__(512) mma_gemm_hl(
    const uint32_t* __restrict__ Ah, const uint32_t* __restrict__ Al,
    const uint32_t* __restrict__ Bh, const uint32_t* __restrict__ Bl,
    const float* __restrict__ Braw,
    const float* __restrict__ bias, float* __restrict__ C,
    int M, int N, int K, float alpha,
    long long sA, long long sB, long long sC)
{
    constexpr int STG = BT ? STG1 : STG0;
    extern __shared__ uint32_t dsm[];
    Ah += (long long)blockIdx.z * sA;  Al += (long long)blockIdx.z * sA;
    if (BT) { Bh += (long long)blockIdx.z * sB; Bl += (long long)blockIdx.z * sB; }
    else    { Braw += (long long)blockIdx.z * sB; }
    C  += (long long)blockIdx.z * sC;
    const int tid  = threadIdx.x;
    const int lane = tid & 31;
    const int warp = tid >> 5;
    const int wm = warp >> 2, wn = warp & 3;
    const int g  = lane >> 2, t4 = lane & 3;
    const int bm = blockIdx.y * 128, bn = blockIdx.x * 128;

    float acc[2][4][4];
#pragma unroll
    for (int i = 0; i < 2; i++)
#pragma unroll
        for (int j = 0; j < 4; j++)
#pragma unroll
            for (int q = 0; q < 4; q++) acc[i][j][q] = 0.f;

    auto issue_tile = [&](int kt, int st) {
        uint32_t* Ah_d = dsm + st * STG;
        uint32_t* Al_d = Ah_d + ASZ;
        uint32_t* B_d  = Al_d + ASZ;           // raw (BT=0) or Bh (BT=1)
        long long k0 = (long long)kt * KT;
#pragma unroll
        for (int i = 0; i < 2; i++) {
            int c = tid + i * 512;
            int m = c >> 3, cq = c & 7;
            long long go = (long long)(bm + m) * K + k0 + cq * 4;
            cp16(smem_u32(&Ah_d[m * AST + cq * 4]), Ah + go);
            cp16(smem_u32(&Al_d[m * AST + cq * 4]), Al + go);
        }
        if (BT == 0) {
#pragma unroll
            for (int i = 0; i < 2; i++) {
                int c = tid + i * 512;
                int kk = c >> 5, nq = c & 31;
                int gc = bn + nq * 4;
                long long go = (long long)(k0 + kk) * N + gc;
                cp16z(smem_u32(&B_d[kk * BWST + nq * 4]), Braw + go, gc < N);
            }
        } else {
            uint32_t* Bl_d = B_d + ASZ;
#pragma unroll
            for (int i = 0; i < 2; i++) {
                int c = tid + i * 512;
                int n = c >> 3, cq = c & 7;
                long long go = (long long)(bn + n) * K + k0 + cq * 4;
                cp16(smem_u32(&B_d[n * AST + cq * 4]), Bh + go);
                cp16(smem_u32(&Bl_d[n * AST + cq * 4]), Bl + go);
            }
        }
        CP_COMMIT();
    };

    const int nk = K / KT;
    issue_tile(0, 0);
    for (int kt = 0; kt < nk; kt++) {
        if (kt + 1 < nk) { issue_tile(kt + 1, (kt + 1) & 1); CP_WAIT1(); }
        else             { CP_WAIT0(); }
        __syncthreads();
        const uint32_t* Ah_s = dsm + (kt & 1) * STG;
        const uint32_t* Al_s = Ah_s + ASZ;
        if (BT == 0) {
            const float* Bf_s = (const float*)(Al_s + ASZ);
            const int moff = wm * 32, noff = wn * 32;
#pragma unroll
            for (int ks = 0; ks < 4; ks++) {
                const int kr = ks * 8 + t4;
                uint32_t afH[2][4], afL[2][4], bfH[4][2], bfL[4][2];
#pragma unroll
                for (int mt = 0; mt < 2; mt++) {
                    int mb = moff + mt * 16 + g;
                    afH[mt][0] = Ah_s[mb * AST + kr];
                    afL[mt][0] = Al_s[mb * AST + kr];
                    afH[mt][1] = Ah_s[(mb + 8) * AST + kr];
                    afL[mt][1] = Al_s[(mb + 8) * AST + kr];
                    afH[mt][2] = Ah_s[mb * AST + kr + 4];
                    afL[mt][2] = Al_s[mb * AST + kr + 4];
                    afH[mt][3] = Ah_s[(mb + 8) * AST + kr + 4];
                    afL[mt][3] = Al_s[(mb + 8) * AST + kr + 4];
                }
#pragma unroll
                for (int nt = 0; nt < 4; nt++) {
                    int nb = noff + nt * 8 + g;
                    sp(Bf_s[kr * BWST + nb],       bfH[nt][0], bfL[nt][0]);
                    sp(Bf_s[(kr + 4) * BWST + nb], bfH[nt][1], bfL[nt][1]);
                }
#pragma unroll
                for (int mt = 0; mt < 2; mt++)
#pragma unroll
                    for (int nt = 0; nt < 4; nt++) {
                        mma_tf32(acc[mt][nt], afH[mt], bfL[nt]);
                        mma_tf32(acc[mt][nt], afL[mt], bfH[nt]);
                        mma_tf32(acc[mt][nt], afH[mt], bfH[nt]);
                    }
            }
        } else {
            const uint32_t* Bh_s = Al_s + ASZ;
            const uint32_t* Bl_s = Bh_s + ASZ;
            MMA_COMPUTE_512(Bh_s[nb * AST + kr], Bl_s[nb * AST + kr],
                            Bh_s[nb * AST + kr + 4], Bl_s[nb * AST + kr + 4])
        }
        __syncthreads();
    }

    // ---- epilogue ----
#pragma unroll
    for (int mt = 0; mt < 2; mt++) {
        int m0 = bm + wm * 32 + mt * 16 + g;
#pragma unroll
        for (int nt = 0; nt < 4; nt++) {
            int n0 = bn + wn * 32 + nt * 8 + t4 * 2;
            if (n0 < N) {
                float b0v = bias ? bias[n0] : 0.f;
                float b1v = bias ? bias[n0 + 1] : 0.f;
                C[(long long)m0 * N + n0]           = acc[mt][nt][0] * alpha + b0v;
                C[(long long)m0 * N + n0 + 1]       = acc[mt][nt][1] * alpha + b1v;
                C[(long long)(m0 + 8) * N + n0]     = acc[mt][nt][2] * alpha + b0v;
                C[(long long)(m0 + 8) * N + n0 + 1] = acc[mt][nt][3] * alpha + b1v;
            }
        }
    }
}

// =====================================================================
// MoE GEMM 1 (z=expert): H1hl[e] = split(relu(Xhl[toks_e] @ W1raw[e] + b1[e]))
// =====================================================================
__global__ void __launch_bounds__(512) moe_mma1_hl(
    const uint32_t* __restrict__ Xh, const uint32_t* __restrict__ Xl,
    const float* __restrict__ W1, const float* __restrict__ b1,
    uint32_t* __restrict__ H1h, uint32_t* __restrict__ H1l,
    const int* __restrict__ list, const int* __restrict__ cnt)
{
    extern __shared__ uint32_t dsm[];
    __shared__ int toks[128];
    const int e = blockIdx.z;
    const int nrows = cnt[e];
    const int bm = blockIdx.y * 128, bn = blockIdx.x * 128;
    if (bm >= nrows) return;
    const float* __restrict__ W = W1 + (long long)e * Dm * FF;
    const float* __restrict__ bias = b1 + e * FF;
    uint32_t* __restrict__ Hh = H1h + (size_t)e * TOK * FF;
    uint32_t* __restrict__ Hl = H1l + (size_t)e * TOK * FF;
    const int* __restrict__ lst = list + e * TOK;

    const int tid = threadIdx.x;
    const int lane = tid & 31, warp = tid >> 5;
    const int wm = warp >> 2, wn = warp & 3;
    const int g = lane >> 2, t4 = lane & 3;
    if (tid < 128) {
        int gr = bm + tid;
        toks[tid] = (gr < nrows) ? (lst[gr] >> 1) : 0;
    }
    __syncthreads();

    float acc[2][4][4];
#pragma unroll
    for (int i = 0; i < 2; i++)
#pragma unroll
        for (int j = 0; j < 4; j++)
#pragma unroll
            for (int q = 0; q < 4; q++) acc[i][j][q] = 0.f;

    auto issue_tile = [&](int kt, int st) {
        uint32_t* Ah_d = dsm + st * STG0;
        uint32_t* Al_d = Ah_d + ASZ;
        uint32_t* B_d  = Al_d + ASZ;
        long long k0 = (long long)kt * KT;
#pragma unroll
        for (int i = 0; i < 2; i++) {
            int c = tid + i * 512;
            int m = c >> 3, cq = c & 7;
            long long go = (long long)toks[m] * Dm + k0 + cq * 4;
            cp16(smem_u32(&Ah_d[m * AST + cq * 4]), Xh + go);
            cp16(smem_u32(&Al_d[m * AST + cq * 4]), Xl + go);
        }
#pragma unroll
        for (int i = 0; i < 2; i++) {
            int c = tid + i * 512;
            int kk = c >> 5, nq = c & 31;
            long long go = (long long)(k0 + kk) * FF + bn + nq * 4;
            cp16(smem_u32(&B_d[kk * BWST + nq * 4]), W + go);
        }
        CP_COMMIT();
    };

    const int nk = Dm / KT;
    issue_tile(0, 0);
    for (int kt = 0; kt < nk; kt++) {
        if (kt + 1 < nk) { issue_tile(kt + 1, (kt + 1) & 1); CP_WAIT1(); }
        else             { CP_WAIT0(); }
        __syncthreads();
        const uint32_t* Ah_s = dsm + (kt & 1) * STG0;
        const uint32_t* Al_s = Ah_s + ASZ;
        const float* Bf_s = (const float*)(Al_s + ASZ);
        const int moff = wm * 32, noff = wn * 32;
#pragma unroll
        for (int ks = 0; ks < 4; ks++) {
            const int kr = ks * 8 + t4;
            uint32_t afH[2][4], afL[2][4], bfH[4][2], bfL[4][2];
#pragma unroll
            for (int mt = 0; mt < 2; mt++) {
                int mb = moff + mt * 16 + g;
                afH[mt][0] = Ah_s[mb * AST + kr];
                afL[mt][0] = Al_s[mb * AST + kr];
                afH[mt][1] = Ah_s[(mb + 8) * AST + kr];
                afL[mt][1] = Al_s[(mb + 8) * AST + kr];
                afH[mt][2] = Ah_s[mb * AST + kr + 4];
                afL[mt][2] = Al_s[mb * AST + kr + 4];
                afH[mt][3] = Ah_s[(mb + 8) * AST + kr + 4];
                afL[mt][3] = Al_s[(mb + 8) * AST + kr + 4];
            }
#pragma unroll
            for (int nt = 0; nt < 4; nt++) {
                int nb = noff + nt * 8 + g;
                sp(Bf_s[kr * BWST + nb],       bfH[nt][0], bfL[nt][0]);
                sp(Bf_s[(kr + 4) * BWST + nb], bfH[nt][1], bfL[nt][1]);
            }
#pragma unroll
            for (int mt = 0; mt < 2; mt++)
#pragma unroll
                for (int nt = 0; nt < 4; nt++) {
                    mma_tf32(acc[mt][nt], afH[mt], bfL[nt]);
                    mma_tf32(acc[mt][nt], afL[mt], bfH[nt]);
                    mma_tf32(acc[mt][nt], afH[mt], bfH[nt]);
                }
        }
        __syncthreads();
    }

#pragma unroll
    for (int mt = 0; mt < 2; mt++) {
        int lr = wm * 32 + mt * 16 + g;
#pragma unroll
        for (int nt = 0; nt < 4; nt++) {
            int n0 = bn + wn * 32 + nt * 8 + t4 * 2;
            float b0v = bias[n0], b1v = bias[n0 + 1];
            if (bm + lr < nrows) {
                size_t o = (size_t)(bm + lr) * FF + n0;
                uint32_t h, l;
                sp(fmaxf(acc[mt][nt][0] + b0v, 0.f), h, l); Hh[o] = h; Hl[o] = l;
                sp(fmaxf(acc[mt][nt][1] + b1v, 0.f), h, l); Hh[o + 1] = h; Hl[o + 1] = l;
            }
            if (bm + lr + 8 < nrows) {
                size_t o = (size_t)(bm + lr + 8) * FF + n0;
                uint32_t h, l;
                sp(fmaxf(acc[mt][nt][2] + b0v, 0.f), h, l); Hh[o] = h; Hl[o] = l;
                sp(fmaxf(acc[mt][nt][3] + b1v, 0.f), h, l); Hh[o + 1] = h; Hl[o + 1] = l;
            }
        }
    }
}

// =====================================================================
// MoE GEMM 2 (z=expert, scatter): out_slot[token] = w * (H1hl[e] @ W2raw[e] + b2[e])
// =====================================================================
__global__ void __launch_bounds__(512) moe_mma2_hl(
    const uint32_t* __restrict__ H1h, const uint32_t* __restrict__ H1l,
    const float* __restrict__ W2, const float* __restrict__ b2,
    float* __restrict__ out0, float* __restrict__ out1,
    const float* __restrict__ topw,
    const int* __restrict__ list, const int* __restrict__ cnt)
{
    extern __shared__ uint32_t dsm[];
    __shared__ int ents[128];
    const int e = blockIdx.z;
    const int nrows = cnt[e];
    const int bm = blockIdx.y * 128, bn = blockIdx.x * 128;
    if (bm >= nrows) return;
    const float* __restrict__ W = W2 + (long long)e * FF * Dm;
    const float* __restrict__ bias = b2 + e * Dm;
    const uint32_t* __restrict__ Hh = H1h + (size_t)e * TOK * FF;
    const uint32_t* __restrict__ Hl = H1l + (size_t)e * TOK * FF;
    const int* __restrict__ lst = list + e * TOK;

    const int tid = threadIdx.x;
    const int lane = tid & 31, warp = tid >> 5;
    const int wm = warp >> 2, wn = warp & 3;
    const int g = lane >> 2, t4 = lane & 3;
    if (tid < 128) {
        int gr = bm + tid;
        ents[tid] = (gr < nrows) ? lst[gr] : -1;
    }
    __syncthreads();

    float acc[2][4][4];
#pragma unroll
    for (int i = 0; i < 2; i++)
#pragma unroll
        for (int j = 0; j < 4; j++)
#pragma unroll
            for (int q = 0; q < 4; q++) acc[i][j][q] = 0.f;

    auto issue_tile = [&](int kt, int st) {
        uint32_t* Ah_d = dsm + st * STG0;
        uint32_t* Al_d = Ah_d + ASZ;
        uint32_t* B_d  = Al_d + ASZ;
        long long k0 = (long long)kt * KT;
#pragma unroll
        for (int i = 0; i < 2; i++) {
            int c = tid + i * 512;
            int m = c >> 3, cq = c & 7;
            size_t go = (size_t)(bm + m) * FF + k0 + cq * 4;
            cp16(smem_u32(&Ah_d[m * AST + cq * 4]), Hh + go);
            cp16(smem_u32(&Al_d[m * AST + cq * 4]), Hl + go);
        }
#pragma unroll
        for (int i = 0; i < 2; i++) {
            int c = tid + i * 512;
            int kk = c >> 5, nq = c & 31;
            long long go = (long long)(k0 + kk) * Dm + bn + nq * 4;
            cp16(smem_u32(&B_d[kk * BWST + nq * 4]), W + go);
        }
        CP_COMMIT();
    };

    const int nk = FF / KT;
    issue_tile(0, 0);
    for (int kt = 0; kt < nk; kt++) {
        if (kt + 1 < nk) { issue_tile(kt + 1, (kt + 1) & 1); CP_WAIT1(); }
        else             { CP_WAIT0(); }
        __syncthreads();
        const uint32_t* Ah_s = dsm + (kt & 1) * STG0;
        const uint32_t* Al_s = Ah_s + ASZ;
        const float* Bf_s = (const float*)(Al_s + ASZ);
        const int moff = wm * 32, noff = wn * 32;
#pragma unroll
        for (int ks = 0; ks < 4; ks++) {
            const int kr = ks * 8 + t4;
            uint32_t afH[2][4], afL[2][4], bfH[4][2], bfL[4][2];
#pragma unroll
            for (int mt = 0; mt < 2; mt++) {
                int mb = moff + mt * 16 + g;
                afH[mt][0] = Ah_s[mb * AST + kr];
                afL[mt][0] = Al_s[mb * AST + kr];
                afH[mt][1] = Ah_s[(mb + 8) * AST + kr];
                afL[mt][1] = Al_s[(mb + 8) * AST + kr];
                afH[mt][2] = Ah_s[mb * AST + kr + 4];
                afL[mt][2] = Al_s[mb * AST + kr + 4];
                afH[mt][3] = Ah_s[(mb + 8) * AST + kr + 4];
                afL[mt][3] = Al_s[(mb + 8) * AST + kr + 4];
            }
#pragma unroll
            for (int nt = 0; nt < 4; nt++) {
                int nb = noff + nt * 8 + g;
                sp(Bf_s[kr * BWST + nb],       bfH[nt][0], bfL[nt][0]);
                sp(Bf_s[(kr + 4) * BWST + nb], bfH[nt][1], bfL[nt][1]);
            }
#pragma unroll
            for (int mt = 0; mt < 2; mt++)
#pragma unroll
                for (int nt = 0; nt < 4; nt++) {
                    mma_tf32(acc[mt][nt], afH[mt], bfL[nt]);
                    mma_tf32(acc[mt][nt], afL[mt], bfH[nt]);
                    mma_tf32(acc[mt][nt], afH[mt], bfH[nt]);
                }
        }
        __syncthreads();
    }

#pragma unroll
    for (int mt = 0; mt < 2; mt++) {
        int lr = wm * 32 + mt * 16 + g;
        int e0 = ents[lr], e2 = ents[lr + 8];
#pragma unroll
        for (int nt = 0; nt < 4; nt++) {
            int n0 = bn + wn * 32 + nt * 8 + t4 * 2;
            float b0v = bias[n0], b1v = bias[n0 + 1];
            if (e0 >= 0) {
                float w = topw[e0];
                float* o = (e0 & 1) ? out1 : out0;
                long long t = (long long)(e0 >> 1) * Dm;
                o[t + n0]     = w * (acc[mt][nt][0] + b0v);
                o[t + n0 + 1] = w * (acc[mt][nt][1] + b1v);
            }
            if (e2 >= 0) {
                float w = topw[e2];
                float* o = (e2 & 1) ? out1 : out0;
                long long t = (long long)(e2 >> 1) * Dm;
                o[t + n0]     = w * (acc[mt][nt][2] + b0v);
                o[t + n0 + 1] = w * (acc[mt][nt][3] + b1v);
            }
        }
    }
}

// ---------------- RoPE tables ----------------
__global__ void rope_init_kernel() {
    int idx = blockIdx.x * blockDim.x + threadIdx.x;
    if (idx >= Sn * HD) return;
    int s = idx >> 6;
    int j = idx & 63;
    int jj = j & 31;
    double inv = pow(10000.0, -((double)(2 * jj)) / 64.0);
    double ang = (double)s * inv;
    g_cos[idx] = (float)cos(ang);
    g_sin[idx] = (float)sin(ang);
}

// ---------------- embedding gather (+ hi/lo) ----------------
__global__ void embed_kernel(const int* __restrict__ ids, const float* __restrict__ table,
                             float* __restrict__ out,
                             uint32_t* __restrict__ oh, uint32_t* __restrict__ ol) {
    int idx = blockIdx.x * blockDim.x + threadIdx.x;
    int t = idx >> 10;
    int d = idx & 1023;
    float v = table[(long long)ids[t] * Dm + d];
    out[idx] = v;
    uint32_t h, l;
    sp(v, h, l);
    oh[idx] = h;
    ol[idx] = l;
}

// ---------------- fp32 scalar SGEMM (tiny gate GEMM; exact routing) ----------------
__global__ void sgemm_kernel(const float* __restrict__ A, const float* __restrict__ W,
                             const float* __restrict__ bias, float* __restrict__ C,
                             int M, int N, int K) {
    const int tid = threadIdx.x;
    const int bm = blockIdx.y * 64, bn = blockIdx.x * 64;
    __shared__ float As[16][68];
    __shared__ float Ws[16][68];
    float acc[4][4] = {};
    const int ty = tid >> 4, tx = tid & 15;
    for (int k0 = 0; k0 < K; k0 += 16) {
#pragma unroll
        for (int i = 0; i < 4; i++) {
            int e = tid + i * 256;
            int r = e >> 4, kk = e & 15;
            int gr = bm + r, gk = k0 + kk;
            As[kk][r] = (gr < M && gk < K) ? A[(long long)gr * K + gk] : 0.f;
        }
#pragma unroll
        for (int i = 0; i < 4; i++) {
            int e = tid + i * 256;
            int kk = e >> 6, c = e & 63;
            int gk = k0 + kk, gc = bn + c;
            Ws[kk][c] = (gk < K && gc < N) ? W[(long long)gk * N + gc] : 0.f;
        }
        __syncthreads();
#pragma unroll
        for (int kk = 0; kk < 16; kk++) {
            float4 a4 = *(const float4*)&As[kk][ty * 4];
            float4 b4 = *(const float4*)&Ws[kk][tx * 4];
            float av[4] = {a4.x, a4.y, a4.z, a4.w};
            float bv[4] = {b4.x, b4.y, b4.z, b4.w};
#pragma unroll
            for (int i = 0; i < 4; i++)
#pragma unroll
                for (int j = 0; j < 4; j++) acc[i][j] += av[i] * bv[j];
        }
        __syncthreads();
    }
#pragma unroll
    for (int i = 0; i < 4; i++) {
        int r = bm + ty * 4 + i;
        if (r >= M) continue;
#pragma unroll
        for (int j = 0; j < 4; j++) {
            int c = bn + tx * 4 + j;
            if (c >= N) continue;
            C[(long long)r * N + c] = acc[i][j] + (bias ? bias[c] : 0.f);
        }
    }
}

// ---------------- RoPE + permute, hi/lo out (Q, K) ----------------
__global__ void rope_perm_hl_kernel(const float* __restrict__ lin,
                                    uint32_t* __restrict__ oh, uint32_t* __restrict__ ol) {
    int idx = blockIdx.x * blockDim.x + threadIdx.x;
    int t = idx >> 10;
    int col = idx & 1023;
    int b = t >> 9;
    int s = t & 511;
    int h = col >> 6;
    int d = col & 63;
    float v = lin[idx];
    float other = (d < 32) ? -lin[idx + 32] : lin[idx - 32];
    float o = v * g_cos[s * 64 + d] + other * g_sin[s * 64 + d];
    long long oi = ((long long)(b * Hn + h) * Sn + s) * HD + d;
    uint32_t hh, ll;
    sp(o, hh, ll);
    oh[oi] = hh;
    ol[oi] = ll;
}

// ---------------- permute only, raw out (V) ----------------
__global__ void perm_raw_kernel(const float* __restrict__ lin, float* __restrict__ out) {
    int idx = blockIdx.x * blockDim.x + threadIdx.x;
    int t = idx >> 10;
    int col = idx & 1023;
    int b = t >> 9;
    int s = t & 511;
    int h = col >> 6;
    int d = col & 63;
    out[((long long)(b * Hn + h) * Sn + s) * HD + d] = lin[idx];
}

// ---------------- [b,h,s,hd] -> [tok,D] permute (hi/lo out) ----------------
__global__ void perm_back_kernel(const float* __restrict__ att,
                                 uint32_t* __restrict__ oh, uint32_t* __restrict__ ol) {
    int idx = blockIdx.x * blockDim.x + threadIdx.x;
    int d = idx & 63;
    int s = (idx >> 6) & 511;
    int h = (idx >> 15) & 15;
    int b = idx >> 19;
    long long oi = (long long)(b * Sn + s) * Dm + h * HD + d;
    uint32_t hh, ll;
    sp(att[idx], hh, ll);
    oh[oi] = hh;
    ol[oi] = ll;
}

// ---------------- row softmax (hi/lo out) ----------------
__global__ void softmax_rows_kernel(const float* __restrict__ sc,
                                    uint32_t* __restrict__ oh, uint32_t* __restrict__ ol,
                                    int causal) {
    int row = blockIdx.x;
    long long base = ((long long)blockIdx.y * Sn + row) * Sn;
    int tid = threadIdx.x;
    float v0 = sc[base + tid];
    float v1 = sc[base + tid + 256];
    if (causal) {
        if (tid > row) v0 = -1e9f;
        if (tid + 256 > row) v1 = -1e9f;
    }
    __shared__ float red[256];
    float m = fmaxf(v0, v1);
    red[tid] = m;
    __syncthreads();
    for (int s = 128; s > 0; s >>= 1) {
        if (tid < s) red[tid] = fmaxf(red[tid], red[tid + s]);
        __syncthreads();
    }
    m = red[0];
    __syncthreads();
    float e0 = expf(v0 - m), e1 = expf(v1 - m);
    red[tid] = e0 + e1;
    __syncthreads();
    for (int s = 128; s > 0; s >>= 1) {
        if (tid < s) red[tid] += red[tid + s];
        __syncthreads();
    }
    float inv = 1.f / red[0];
    uint32_t h, l;
    sp(e0 * inv, h, l);
    oh[base + tid] = h;
    ol[base + tid] = l;
    sp(e1 * inv, h, l);
    oh[base + tid + 256] = h;
    ol[base + tid + 256] = l;
}

// ---------------- fused residual add(+add2) + layernorm (+ hi/lo) ----------------
__global__ void add_ln_kernel(const float* __restrict__ x, const float* __restrict__ a,
                              const float* __restrict__ a2,
                              const float* __restrict__ g, const float* __restrict__ b,
                              float* __restrict__ out,
                              uint32_t* __restrict__ oh, uint32_t* __restrict__ ol) {
    int t = blockIdx.x;
    int tid = threadIdx.x;
    long long base = (long long)t * Dm;
    float v[4];
#pragma unroll
    for (int i = 0; i < 4; i++) {
        int c = tid + i * 256;
        float s = x[base + c] + a[base + c];
        if (a2) s += a2[base + c];
        v[i] = s;
    }
    __shared__ float red[256];
    red[tid] = v[0] + v[1] + v[2] + v[3];
    __syncthreads();
    for (int k = 128; k > 0; k >>= 1) {
        if (tid < k) red[tid] += red[tid + k];
        __syncthreads();
    }
    float mu = red[0] * (1.f / Dm);
    __syncthreads();
    float q = 0.f;
#pragma unroll
    for (int i = 0; i < 4; i++) { float d = v[i] - mu; q += d * d; }
    red[tid] = q;
    __syncthreads();
    for (int k = 128; k > 0; k >>= 1) {
        if (tid < k) red[tid] += red[tid + k];
        __syncthreads();
    }
    float var = red[0] * (1.f / Dm);
    float inv = rsqrtf(var + 1e-5f);
#pragma unroll
    for (int i = 0; i < 4; i++) {
        int c = tid + i * 256;
        float o = (v[i] - mu) * inv * g[c] + b[c];
        out[base + c] = o;
        uint32_t h, l;
        sp(o, h, l);
        oh[base + c] = h;
        ol[base + c] = l;
    }
}

// ---------------- MoE gating ----------------
__global__ void zero_cnt_kernel(int* c) { if (threadIdx.x < En) c[threadIdx.x] = 0; }

__global__ void gate_route_kernel(const float* __restrict__ logits, float* __restrict__ topw,
                                  int* __restrict__ list, int* __restrict__ cnt) {
    int t = blockIdx.x * blockDim.x + threadIdx.x;
    if (t >= TOK) return;
    float p[En];
    float m = -1e30f;
#pragma unroll
    for (int e = 0; e < En; e++) { p[e] = logits[t * En + e]; m = fmaxf(m, p[e]); }
    float s = 0.f;
#pragma unroll
    for (int e = 0; e < En; e++) { p[e] = expf(p[e] - m); s += p[e]; }
    float invs = 1.f / s;
#pragma unroll
    for (int e = 0; e < En; e++) p[e] *= invs;
    int i0 = 0;
#pragma unroll
    for (int e = 1; e < En; e++) if (p[e] > p[i0]) i0 = e;
    int i1 = (i0 == 0) ? 1 : 0;
#pragma unroll
    for (int e = 0; e < En; e++) if (e != i0 && p[e] > p[i1]) i1 = e;
    float s2 = p[i0] + p[i1];
    topw[t * 2 + 0] = p[i0] / s2;
    topw[t * 2 + 1] = p[i1] / s2;
    int pos = atomicAdd(&cnt[i0], 1);
    list[i0 * TOK + pos] = t * 2 + 0;
    pos = atomicAdd(&cnt[i1], 1);
    list[i1 * TOK + pos] = t * 2 + 1;
}

// ================= host orchestration =================
struct DevPtrs {
    float *x, *y, *lin0, *lin1, *lin2, *v, *sc, *att, *proj, *moe0, *moe1, *gate, *topw;
    uint32_t *xh, *xl, *yh, *yl, *qh, *ql, *kh, *kl;
    uint32_t *sch, *scl, *atth, *attl, *h1h, *h1l;
    int *list, *cnt;
};

// C = alpha*(Ahl @ Braw) + bias
static void hgemm(const uint32_t* Ah, const uint32_t* Al, const float* Braw,
                  const float* bias, float* C,
                  int M, int N, int K, float alpha = 1.f, int batch = 1,
                  long long sA = 0, long long sB = 0, long long sC = 0) {
    dim3 g((N + 127) / 128, M / 128, batch);
    mma_gemm_hl<0><<<g, 512, SMEM0_BYTES>>>(Ah, Al, nullptr, nullptr, Braw, bias, C,
                                            M, N, K, alpha, sA, sB, sC);
}

// C = alpha*(Ahl @ Bhl^T)   (B [N,K] pre-split)
static void hgemm_nt(const uint32_t* Ah, const uint32_t* Al,
                     const uint32_t* Bh, const uint32_t* Bl, float* C,
                     int M, int N, int K, float alpha, int batch,
                     long long sA, long long sB, long long sC) {
    dim3 g((N + 127) / 128, M / 128, batch);
    mma_gemm_hl<1><<<g, 512, SMEM1_BYTES>>>(Ah, Al, Bh, Bl, nullptr, nullptr, C,
                                            M, N, K, alpha, sA, sB, sC);
}

static void run_mha(DevPtrs& P, float* xio, uint32_t* xh, uint32_t* xl,
                    const uint32_t* kvh, const uint32_t* kvl,
                    const float* wqkv, const float* bqkv,
                    const float* wo, const float* bo,
                    const float* lng, const float* lnb, int causal) {
    hgemm(xh,  xl,  wqkv,               bqkv,          P.lin0, TOK, Dm, Dm);
    hgemm(kvh, kvl, wqkv + Dm * Dm,     bqkv + Dm,     P.lin1, TOK, Dm, Dm);
    hgemm(kvh, kvl, wqkv + 2 * Dm * Dm, bqkv + 2 * Dm, P.lin2, TOK, Dm, Dm);
    int nb = (TOK * Dm) / 256;
    rope_perm_hl_kernel<<<nb, 256>>>(P.lin0, P.qh, P.ql);
    rope_perm_hl_kernel<<<nb, 256>>>(P.lin1, P.kh, P.kl);
    perm_raw_kernel<<<nb, 256>>>(P.lin2, P.v);
    hgemm_nt(P.qh, P.ql, P.kh, P.kl, P.sc, Sn, Sn, HD, 0.125f, Bn * Hn,
             (long long)Sn * HD, (long long)Sn * HD, (long long)Sn * Sn);
    softmax_rows_kernel<<<dim3(Sn, Bn * Hn), 256>>>(P.sc, P.sch, P.scl, causal);
    hgemm(P.sch, P.scl, P.v, nullptr, P.att, Sn, HD, Sn, 1.f, Bn * Hn,
          (long long)Sn * Sn, (long long)Sn * HD, (long long)Sn * HD);
    perm_back_kernel<<<nb, 256>>>(P.att, P.atth, P.attl);
    hgemm(P.atth, P.attl, wo, bo, P.proj, TOK, Dm, Dm);
    add_ln_kernel<<<TOK, 256>>>(xio, P.proj, nullptr, lng, lnb, xio, xh, xl);
}

static void run_moe(DevPtrs& P, float* xio, uint32_t* xh, uint32_t* xl,
                    const float* gw, const float* gb,
                    const float* w1, const float* b1, const float* w2, const float* b2,
                    const float* lng, const float* lnb) {
    sgemm_kernel<<<dim3(1, TOK / 64), 256>>>(xio, gw, gb, P.gate, TOK, En, Dm);
    zero_cnt_kernel<<<1, 32>>>(P.cnt);
    gate_route_kernel<<<TOK / 256, 256>>>(P.gate, P.topw, P.list, P.cnt);
    moe_mma1_hl<<<dim3(FF / 128, TOK / 128, En), 512, SMEM0_BYTES>>>(
        xh, xl, w1, b1, P.h1h, P.h1l, P.list, P.cnt);
    moe_mma2_hl<<<dim3(Dm / 128, TOK / 128, En), 512, SMEM0_BYTES>>>(
        P.h1h, P.h1l, w2, b2, P.moe0, P.moe1, P.topw, P.list, P.cnt);
    add_ln_kernel<<<TOK, 256>>>(xio, P.moe0, P.moe1, lng, lnb, xio, xh, xl);
}

extern "C" void kernel_launch(void* const* d_in, const int* in_sizes, int n_in,
                              void* d_out, int out_size) {
    (void)in_sizes; (void)n_in; (void)out_size;
    const int*   src           = (const int*)  d_in[0];
    const int*   tgt           = (const int*)  d_in[1];
    const float* emb_src       = (const float*)d_in[2];
    const float* emb_tgt       = (const float*)d_in[3];
    const float* enc_wqkv      = (const float*)d_in[4];
    const float* enc_bqkv      = (const float*)d_in[5];
    const float* enc_wo        = (const float*)d_in[6];
    const float* enc_bo        = (const float*)d_in[7];
    const float* enc_gate_w    = (const float*)d_in[8];
    const float* enc_gate_b    = (const float*)d_in[9];
    const float* enc_w1        = (const float*)d_in[10];
    const float* enc_b1        = (const float*)d_in[11];
    const float* enc_w2        = (const float*)d_in[12];
    const float* enc_b2        = (const float*)d_in[13];
    const float* enc_ln        = (const float*)d_in[14];
    const float* dec_self_wqkv = (const float*)d_in[15];
    const float* dec_self_bqkv = (const float*)d_in[16];
    const float* dec_self_wo   = (const float*)d_in[17];
    const float* dec_self_bo   = (const float*)d_in[18];
    const float* dec_cross_wqkv= (const float*)d_in[19];
    const float* dec_cross_bqkv= (const float*)d_in[20];
    const float* dec_cross_wo  = (const float*)d_in[21];
    const float* dec_cross_bo  = (const float*)d_in[22];
    const float* dec_gate_w    = (const float*)d_in[23];
    const float* dec_gate_b    = (const float*)d_in[24];
    const float* dec_w1        = (const float*)d_in[25];
    const float* dec_b1        = (const float*)d_in[26];
    const float* dec_w2        = (const float*)d_in[27];
    const float* dec_b2        = (const float*)d_in[28];
    const float* dec_ln        = (const float*)d_in[29];
    const float* final_w       = (const float*)d_in[30];
    const float* final_b       = (const float*)d_in[31];
    float* out = (float*)d_out;

    cudaFuncSetAttribute(mma_gemm_hl<0>, cudaFuncAttributeMaxDynamicSharedMemorySize, SMEM0_BYTES);
    cudaFuncSetAttribute(mma_gemm_hl<1>, cudaFuncAttributeMaxDynamicSharedMemorySize, SMEM1_BYTES);
    cudaFuncSetAttribute(moe_mma1_hl,    cudaFuncAttributeMaxDynamicSharedMemorySize, SMEM0_BYTES);
    cudaFuncSetAttribute(moe_mma2_hl,    cudaFuncAttributeMaxDynamicSharedMemorySize, SMEM0_BYTES);

    DevPtrs P;
    cudaGetSymbolAddress((void**)&P.x, g_x);
    cudaGetSymbolAddress((void**)&P.y, g_y);
    cudaGetSymbolAddress((void**)&P.xh, g_xh);
    cudaGetSymbolAddress((void**)&P.xl, g_xl);
    cudaGetSymbolAddress((void**)&P.yh, g_yh);
    cudaGetSymbolAddress((void**)&P.yl, g_yl);
    cudaGetSymbolAddress((void**)&P.lin0, g_lin0);
    cudaGetSymbolAddress((void**)&P.lin1, g_lin1);
    cudaGetSymbolAddress((void**)&P.lin2, g_lin2);
    cudaGetSymbolAddress((void**)&P.qh, g_qh);
    cudaGetSymbolAddress((void**)&P.ql, g_ql);
    cudaGetSymbolAddress((void**)&P.kh, g_kh);
    cudaGetSymbolAddress((void**)&P.kl, g_kl);
    cudaGetSymbolAddress((void**)&P.v, g_v);
    cudaGetSymbolAddress((void**)&P.sc, g_sc);
    cudaGetSymbolAddress((void**)&P.sch, g_sch);
    cudaGetSymbolAddress((void**)&P.scl, g_scl);
    cudaGetSymbolAddress((void**)&P.att, g_att);
    cudaGetSymbolAddress((void**)&P.atth, g_atth);
    cudaGetSymbolAddress((void**)&P.attl, g_attl);
    cudaGetSymbolAddress((void**)&P.proj, g_proj);
    cudaGetSymbolAddress((void**)&P.h1h, g_h1h);
    cudaGetSymbolAddress((void**)&P.h1l, g_h1l);
    cudaGetSymbolAddress((void**)&P.moe0, g_moe0);
    cudaGetSymbolAddress((void**)&P.moe1, g_moe1);
    cudaGetSymbolAddress((void**)&P.gate, g_gate);
    cudaGetSymbolAddress((void**)&P.topw, g_topw);
    cudaGetSymbolAddress((void**)&P.list, g_list);
    cudaGetSymbolAddress((void**)&P.cnt, g_cnt);

    rope_init_kernel<<<(Sn * HD) / 256, 256>>>();

    // ---------- encoder ----------
    embed_kernel<<<(TOK * Dm) / 256, 256>>>(src, emb_src, P.x, P.xh, P.xl);
    for (int l = 0; l < Ln; l++) {
        run_mha(P, P.x, P.xh, P.xl, P.xh, P.xl,
                enc_wqkv + (long long)l * 3 * Dm * Dm, enc_bqkv + l * 3 * Dm,
                enc_wo + (long long)l * Dm * Dm, enc_bo + l * Dm,
                enc_ln + ((l * 2 + 0) * 2 + 0) * Dm, enc_ln + ((l * 2 + 0) * 2 + 1) * Dm, 0);
        run_moe(P, P.x, P.xh, P.xl,
                enc_gate_w + l * Dm * En, enc_gate_b + l * En,
                enc_w1 + (long long)l * En * Dm * FF, enc_b1 + l * En * FF,
                enc_w2 + (long long)l * En * FF * Dm, enc_b2 + l * En * Dm,
                enc_ln + ((l * 2 + 1) * 2 + 0) * Dm, enc_ln + ((l * 2 + 1) * 2 + 1) * Dm);
    }

    // ---------- decoder ----------
    embed_kernel<<<(TOK * Dm) / 256, 256>>>(tgt, emb_tgt, P.y, P.yh, P.yl);
    for (int l = 0; l < Ln; l++) {
        run_mha(P, P.y, P.yh, P.yl, P.yh, P.yl,
                dec_self_wqkv + (long long)l * 3 * Dm * Dm, dec_self_bqkv + l * 3 * Dm,
                dec_self_wo + (long long)l * Dm * Dm, dec_self_bo + l * Dm,
                dec_ln + ((l * 3 + 0) * 2 + 0) * Dm, dec_ln + ((l * 3 + 0) * 2 + 1) * Dm, 1);
        run_mha(P, P.y, P.yh, P.yl, P.xh, P.xl,
                dec_cross_wqkv + (long long)l * 3 * Dm * Dm, dec_cross_bqkv + l * 3 * Dm,
                dec_cross_wo + (long long)l * Dm * Dm, dec_cross_bo + l * Dm,
                dec_ln + ((l * 3 + 1) * 2 + 0) * Dm, dec_ln + ((l * 3 + 1) * 2 + 1) * Dm, 0);
        run_moe(P, P.y, P.yh, P.yl,
                dec_gate_w + l * Dm * En, dec_gate_b + l * En,
                dec_w1 + (long long)l * En * Dm * FF, dec_b1 + l * En * FF,
                dec_w2 + (long long)l * En * FF * Dm, dec_b2 + l * En * Dm,
                dec_ln + ((l * 3 + 2) * 2 + 0) * Dm, dec_ln + ((l * 3 + 2) * 2 + 1) * Dm);
    }

    // ---------- final projection ----------
    hgemm(P.yh, P.yl, final_w, final_b, out, TOK, VT, Dm);
}

// round 9
// speedup vs baseline: 1.3054x; 1.3054x over previous
#include <cuda_runtime.h>
#include <cuda_fp16.h>
#include <math.h>
#include <stdint.h>

// ---------------- problem constants ----------------
#define Bn   4
#define Sn   512
#define Dm   1024
#define Hn   16
#define HD   64
#define En   8
#define FF   2048
#define Ln   2
#define VT   32000
#define TOK  (Bn*Sn)      // 2048 tokens

// ---- fp16-pair weight GEMM tiling (512 thr, tile 128x128, KT=32 -> 16 pairs) ----
#define KPT  16           // u32 pairs per K-tile
#define PST  20           // smem stride (u32): g*20+t4 distinct mod 32
#define PASZ (128*PST)    // 2560 u32 per array
#define STG16 (4*PASZ)    // Ah,Al,Bh,Bl per stage = 10240 u32
#define SMEM16_BYTES (2*STG16*4)   // 81920

// ---- tf32 attention GEMM tiling (256 thr, round-5 proven) ----
#define KT5  16
#define AST5 20
#define BST5 136
#define ASZ5  (128*AST5)
#define BSZ50 (KT5*BST5)
#define BSZ51 (128*AST5)
#define STG50 (2*ASZ5 + 2*BSZ50)
#define STG51 (2*ASZ5 + 2*BSZ51)
#define SMEM50_BYTES (2*STG50*4)
#define SMEM51_BYTES (2*STG51*4)

// ---------------- device scratch (no allocations allowed) ----------------
__device__ float    g_x[TOK*Dm];
__device__ float    g_y[TOK*Dm];
__device__ uint32_t g_xh[TOK*Dm/2], g_xl[TOK*Dm/2];          // fp16 pairs
__device__ uint32_t g_yh[TOK*Dm/2], g_yl[TOK*Dm/2];
__device__ float    g_lin0[TOK*Dm];
__device__ float    g_lin1[TOK*Dm];
__device__ float    g_lin2[TOK*Dm];
__device__ uint32_t g_qh[TOK*Dm], g_ql[TOK*Dm];              // tf32 hi/lo
__device__ uint32_t g_kh[TOK*Dm], g_kl[TOK*Dm];
__device__ uint32_t g_vh[TOK*Dm], g_vl[TOK*Dm];
__device__ float    g_sc[(size_t)Bn*Hn*Sn*Sn];
__device__ uint32_t g_sch[(size_t)Bn*Hn*Sn*Sn], g_scl[(size_t)Bn*Hn*Sn*Sn];
__device__ float    g_att[TOK*Dm];
__device__ uint32_t g_atth[TOK*Dm/2], g_attl[TOK*Dm/2];      // fp16 pairs
__device__ float    g_proj[TOK*Dm];
__device__ uint32_t g_h1h[(size_t)En*TOK*FF/2], g_h1l[(size_t)En*TOK*FF/2];  // fp16 pairs
__device__ float    g_moe0[TOK*Dm];
__device__ float    g_moe1[TOK*Dm];
__device__ float    g_gate[TOK*En];
__device__ float    g_topw[TOK*2];
__device__ int      g_list[En*TOK];
__device__ int      g_cnt[En];
__device__ float    g_cos[Sn*HD];
__device__ float    g_sin[Sn*HD];
__device__ uint32_t g_wth[16777216], g_wtl[16777216];        // weight pairs [N][K/2] (64MB ea)

// ---------------- helpers ----------------
__device__ __forceinline__ uint32_t f2tf(float f) {
    uint32_t r;
    asm("cvt.rna.tf32.f32 %0, %1;" : "=r"(r) : "f"(f));
    return r;
}
__device__ __forceinline__ void sp(float v, uint32_t& h, uint32_t& l) {
    h = f2tf(v);
    l = f2tf(v - __uint_as_float(h));
}
// fp16 pair split with scaled lo (x2048 keeps lo normal)
__device__ __forceinline__ void sp16pair(float v0, float v1, uint32_t& hp, uint32_t& lp) {
    __half h0 = __float2half_rn(v0);
    __half h1 = __float2half_rn(v1);
    __half l0 = __float2half_rn((v0 - __half2float(h0)) * 2048.f);
    __half l1 = __float2half_rn((v1 - __half2float(h1)) * 2048.f);
    hp = (uint32_t)__half_as_ushort(h0) | ((uint32_t)__half_as_ushort(h1) << 16);
    lp = (uint32_t)__half_as_ushort(l0) | ((uint32_t)__half_as_ushort(l1) << 16);
}
__device__ __forceinline__ uint32_t smem_u32(const void* p) {
    return (uint32_t)__cvta_generic_to_shared(p);
}
__device__ __forceinline__ void cp16(uint32_t dst, const void* src) {
    asm volatile("cp.async.cg.shared.global [%0], [%1], 16;" :: "r"(dst), "l"(src));
}
__device__ __forceinline__ void cp16z(uint32_t dst, const void* src, bool ok) {
    int sz = ok ? 16 : 0;
    asm volatile("cp.async.cg.shared.global [%0], [%1], 16, %2;" :: "r"(dst), "l"(src), "r"(sz));
}
#define CP_COMMIT() asm volatile("cp.async.commit_group;")
#define CP_WAIT1()  asm volatile("cp.async.wait_group 1;")
#define CP_WAIT0()  asm volatile("cp.async.wait_group 0;")

__device__ __forceinline__ void mma_f16(float* c, const uint32_t* a, const uint32_t* b) {
    asm volatile(
        "mma.sync.aligned.m16n8k16.row.col.f32.f16.f16.f32 "
        "{%0,%1,%2,%3}, {%4,%5,%6,%7}, {%8,%9}, {%0,%1,%2,%3};"
        : "+f"(c[0]), "+f"(c[1]), "+f"(c[2]), "+f"(c[3])
        : "r"(a[0]), "r"(a[1]), "r"(a[2]), "r"(a[3]), "r"(b[0]), "r"(b[1]));
}
__device__ __forceinline__ void mma_tf32(float* c, const uint32_t* a, const uint32_t* b) {
    asm volatile(
        "mma.sync.aligned.m16n8k8.row.col.f32.tf32.tf32.f32 "
        "{%0,%1,%2,%3}, {%4,%5,%6,%7}, {%8,%9}, {%0,%1,%2,%3};"
        : "+f"(c[0]), "+f"(c[1]), "+f"(c[2]), "+f"(c[3])
        : "r"(a[0]), "r"(a[1]), "r"(a[2]), "r"(a[3]), "r"(b[0]), "r"(b[1]));
}

// =====================================================================
// fp16x3 weight GEMM: acc = A @ B^T with A [M][K/2] pairs, B [N][K/2] pairs.
// result = accM + accC/2048 (+bias).  512 thr, 16 warps, warp tile 32x32.
// MODE0: plain fp32 out.  MODE1: gather rows by list, relu, pack pairs out.
// MODE2: scatter out_slot = topw * (acc + bias).
// M%128==0, N%128==0, K%32==0.
// =====================================================================
template<int MODE>
__global__ void __launch_bounds__(512) hgemm16(
    const uint32_t* __restrict__ Ah, const uint32_t* __restrict__ Al,
    const uint32_t* __restrict__ Bh, const uint32_t* __restrict__ Bl,
    const float* __restrict__ bias, float* __restrict__ C,
    uint32_t* __restrict__ Oh, uint32_t* __restrict__ Ol,
    float* __restrict__ out0, float* __restrict__ out1, const float* __restrict__ topw,
    const int* __restrict__ list, const int* __restrict__ cnt,
    int M, int N, int K,
    long long sAz, long long sBz, long long sOz)
{
    const int z = blockIdx.z;
    const int bm = blockIdx.y * 128, bn = blockIdx.x * 128;
    int nrows = M;
    const int* lst = nullptr;
    if (MODE >= 1) {
        nrows = cnt[z];
        if (bm >= nrows) return;
        lst = list + z * TOK;
        bias += (long long)z * N;
    }
    Ah += (long long)z * sAz;  Al += (long long)z * sAz;
    Bh += (long long)z * sBz;  Bl += (long long)z * sBz;
    if (MODE == 1) { Oh += (long long)z * sOz; Ol += (long long)z * sOz; }

    extern __shared__ uint32_t dsm[];
    __shared__ int ents[128];
    const int tid  = threadIdx.x;
    const int lane = tid & 31;
    const int warp = tid >> 5;
    const int wm = warp >> 2, wn = warp & 3;
    const int g  = lane >> 2, t4 = lane & 3;
    const int Kp = K >> 1;

    if (MODE >= 1 && tid < 128) {
        int gr = bm + tid;
        ents[tid] = (gr < nrows) ? lst[gr] : -1;
    }
    __syncthreads();

    float accM[2][4][4], accC[2][4][4];
#pragma unroll
    for (int i = 0; i < 2; i++)
#pragma unroll
        for (int j = 0; j < 4; j++)
#pragma unroll
            for (int q = 0; q < 4; q++) { accM[i][j][q] = 0.f; accC[i][j][q] = 0.f; }

    const int r = tid >> 2, ch = tid & 3;            // 128 rows x 4 chunks
    long long arow;
    if (MODE == 1) {
        int e = ents[r];
        arow = (e >= 0) ? (long long)(e >> 1) : 0;   // token index
    } else {
        arow = bm + r;
    }
    const long long brow = bn + r;

    auto issue_tile = [&](int kt, int st) {
        uint32_t* AhS = dsm + st * STG16;
        uint32_t* AlS = AhS + PASZ;
        uint32_t* BhS = AlS + PASZ;
        uint32_t* BlS = BhS + PASZ;
        const long long kp0 = (long long)kt * KPT + ch * 4;
        const uint32_t d = r * PST + ch * 4;
        cp16(smem_u32(&AhS[d]), Ah + arow * Kp + kp0);
        cp16(smem_u32(&AlS[d]), Al + arow * Kp + kp0);
        cp16(smem_u32(&BhS[d]), Bh + brow * Kp + kp0);
        cp16(smem_u32(&BlS[d]), Bl + brow * Kp + kp0);
        CP_COMMIT();
    };

    const int nk = K / 32;
    issue_tile(0, 0);
    for (int kt = 0; kt < nk; kt++) {
        if (kt + 1 < nk) { issue_tile(kt + 1, (kt + 1) & 1); CP_WAIT1(); }
        else             { CP_WAIT0(); }
        __syncthreads();
        const uint32_t* AhS = dsm + (kt & 1) * STG16;
        const uint32_t* AlS = AhS + PASZ;
        const uint32_t* BhS = AlS + PASZ;
        const uint32_t* BlS = BhS + PASZ;
        const int moff = wm * 32, noff = wn * 32;
#pragma unroll
        for (int ks = 0; ks < 2; ks++) {
            const int kp0 = ks * 8 + t4;
            uint32_t aH[2][4], aL[2][4], bH[4][2], bL[4][2];
#pragma unroll
            for (int mt = 0; mt < 2; mt++) {
                int mb = moff + mt * 16 + g;
                aH[mt][0] = AhS[mb * PST + kp0];
                aH[mt][1] = AhS[(mb + 8) * PST + kp0];
                aH[mt][2] = AhS[mb * PST + kp0 + 4];
                aH[mt][3] = AhS[(mb + 8) * PST + kp0 + 4];
                aL[mt][0] = AlS[mb * PST + kp0];
                aL[mt][1] = AlS[(mb + 8) * PST + kp0];
                aL[mt][2] = AlS[mb * PST + kp0 + 4];
                aL[mt][3] = AlS[(mb + 8) * PST + kp0 + 4];
            }
#pragma unroll
            for (int nt = 0; nt < 4; nt++) {
                int nb = noff + nt * 8 + g;
                bH[nt][0] = BhS[nb * PST + kp0];
                bH[nt][1] = BhS[nb * PST + kp0 + 4];
                bL[nt][0] = BlS[nb * PST + kp0];
                bL[nt][1] = BlS[nb * PST + kp0 + 4];
            }
#pragma unroll
            for (int mt = 0; mt < 2; mt++)
#pragma unroll
                for (int nt = 0; nt < 4; nt++) {
                    mma_f16(accM[mt][nt], aH[mt], bH[nt]);
                    mma_f16(accC[mt][nt], aH[mt], bL[nt]);
                    mma_f16(accC[mt][nt], aL[mt], bH[nt]);
                }
        }
        __syncthreads();
    }

    // ---- epilogue ----
    const float s = 1.f / 2048.f;
#pragma unroll
    for (int mt = 0; mt < 2; mt++) {
        int lr = wm * 32 + mt * 16 + g;
#pragma unroll
        for (int nt = 0; nt < 4; nt++) {
            int n0 = bn + wn * 32 + nt * 8 + t4 * 2;
            float b0v = bias[n0], b1v = bias[n0 + 1];
            float v0 = accM[mt][nt][0] + accC[mt][nt][0] * s + b0v;
            float v1 = accM[mt][nt][1] + accC[mt][nt][1] * s + b1v;
            float v2 = accM[mt][nt][2] + accC[mt][nt][2] * s + b0v;
            float v3 = accM[mt][nt][3] + accC[mt][nt][3] * s + b1v;
            if (MODE == 0) {
                long long m0 = bm + lr;
                C[m0 * N + n0] = v0;
                C[m0 * N + n0 + 1] = v1;
                C[(m0 + 8) * N + n0] = v2;
                C[(m0 + 8) * N + n0 + 1] = v3;
            } else if (MODE == 1) {
                if (bm + lr < nrows) {
                    uint32_t hp, lp;
                    sp16pair(fmaxf(v0, 0.f), fmaxf(v1, 0.f), hp, lp);
                    size_t o = (size_t)(bm + lr) * (N >> 1) + (n0 >> 1);
                    Oh[o] = hp; Ol[o] = lp;
                }
                if (bm + lr + 8 < nrows) {
                    uint32_t hp, lp;
                    sp16pair(fmaxf(v2, 0.f), fmaxf(v3, 0.f), hp, lp);
                    size_t o = (size_t)(bm + lr + 8) * (N >> 1) + (n0 >> 1);
                    Oh[o] = hp; Ol[o] = lp;
                }
            } else {
                int e0 = ents[lr], e2 = ents[lr + 8];
                if (e0 >= 0) {
                    float w = topw[e0];
                    float* o = (e0 & 1) ? out1 : out0;
                    long long t = (long long)(e0 >> 1) * N;
                    o[t + n0] = w * v0;
                    o[t + n0 + 1] = w * v1;
                }
                if (e2 >= 0) {
                    float w = topw[e2];
                    float* o = (e2 & 1) ? out1 : out0;
                    long long t = (long long)(e2 >> 1) * N;
                    o[t + n0] = w * v2;
                    o[t + n0 + 1] = w * v3;
                }
            }
        }
    }
}

// =====================================================================
// transpose+split+pack: W [K,N] fp32 -> Wh/Wl [N][K/2] fp16-pair u32.
// grid (N/32, K/32, batch); block (32, 8)
// =====================================================================
__global__ void tsp_kernel(const float* __restrict__ W,
                           uint32_t* __restrict__ h, uint32_t* __restrict__ l,
                           int K, int N, long long zsrc, long long zdst) {
    __shared__ float t[32][33];
    const long long so = (long long)blockIdx.z * zsrc;
    const long long dz = (long long)blockIdx.z * zdst;
    const int bk = blockIdx.y * 32, bnn = blockIdx.x * 32;
    const int tx = threadIdx.x, ty = threadIdx.y;
#pragma unroll
    for (int r = 0; r < 4; r++)
        t[ty + r * 8][tx] = W[so + (long long)(bk + ty + r * 8) * N + bnn + tx];
    __syncthreads();
    const int Kp = K >> 1;
#pragma unroll
    for (int r = 0; r < 2; r++) {
        int kpl = ty * 2 + r;          // 0..15
        float v0 = t[2 * kpl][tx];
        float v1 = t[2 * kpl + 1][tx];
        uint32_t hp, lp;
        sp16pair(v0, v1, hp, lp);
        long long o = dz + (long long)(bnn + tx) * Kp + (bk >> 1) + kpl;
        h[o] = hp;
        l[o] = lp;
    }
}

// =====================================================================
// tf32 attention GEMM (mma.sync 3xTF32, pre-split operands), 256 thr
// BT=0: B [K,N].  BT=1: B [N,K] (NT).
// =====================================================================
#define MMA_COMPUTE_HL5(BIDX0, BIDX1)                                              \
  { const int moff = wm * 64, noff = wn * 32;                                      \
    _Pragma("unroll")                                                              \
    for (int ks = 0; ks < 2; ks++) {                                               \
        const int kr = ks * 8 + t4;                                                \
        uint32_t afH[4][4], afL[4][4], bfH[4][2], bfL[4][2];                       \
        _Pragma("unroll")                                                          \
        for (int mt = 0; mt < 4; mt++) {                                           \
            int mb = moff + mt * 16 + g;                                           \
            afH[mt][0] = Ah_s[mb * AST5 + kr];                                     \
            afL[mt][0] = Al_s[mb * AST5 + kr];                                     \
            afH[mt][1] = Ah_s[(mb + 8) * AST5 + kr];                               \
            afL[mt][1] = Al_s[(mb + 8) * AST5 + kr];                               \
            afH[mt][2] = Ah_s[mb * AST5 + kr + 4];                                 \
            afL[mt][2] = Al_s[mb * AST5 + kr + 4];                                 \
            afH[mt][3] = Ah_s[(mb + 8) * AST5 + kr + 4];                           \
            afL[mt][3] = Al_s[(mb + 8) * AST5 + kr + 4];                           \
        }                                                                          \
        _Pragma("unroll")                                                          \
        for (int nt = 0; nt < 4; nt++) {                                           \
            int nb = noff + nt * 8 + g;                                            \
            bfH[nt][0] = Bh_s[BIDX0]; bfL[nt][0] = Bl_s[BIDX0];                    \
            bfH[nt][1] = Bh_s[BIDX1]; bfL[nt][1] = Bl_s[BIDX1];                    \
        }                                                                          \
        _Pragma("unroll")                                                          \
        for (int mt = 0; mt < 4; mt++)                                             \
            _Pragma("unroll")                                                      \
            for (int nt = 0; nt < 4; nt++) {                                       \
                mma_tf32(acc[mt][nt], afH[mt], bfL[nt]);                           \
                mma_tf32(acc[mt][nt], afL[mt], bfH[nt]);                           \
                mma_tf32(acc[mt][nt], afH[mt], bfH[nt]);                           \
            }                                                                      \
    } }

template<int BT>
__global__ void __launch_bounds__(256) mma_gemm_hl(
    const uint32_t* __restrict__ Ah, const uint32_t* __restrict__ Al,
    const uint32_t* __restrict__ Bh, const uint32_t* __restrict__ Bl,
    float* __restrict__ C,
    int M, int N, int K, float alpha,
    long long sA, long long sB, long long sC)
{
    constexpr int BSZ = BT ? BSZ51 : BSZ50;
    constexpr int STG = 2 * ASZ5 + 2 * BSZ;
    extern __shared__ uint32_t dsm[];
    Ah += (long long)blockIdx.z * sA;  Al += (long long)blockIdx.z * sA;
    Bh += (long long)blockIdx.z * sB;  Bl += (long long)blockIdx.z * sB;
    C  += (long long)blockIdx.z * sC;
    const int tid  = threadIdx.x;
    const int lane = tid & 31;
    const int warp = tid >> 5;
    const int wm = warp >> 2, wn = warp & 3;
    const int g  = lane >> 2, t4 = lane & 3;
    const int bm = blockIdx.y * 128, bn = blockIdx.x * 128;

    float acc[4][4][4];
#pragma unroll
    for (int i = 0; i < 4; i++)
#pragma unroll
        for (int j = 0; j < 4; j++)
#pragma unroll
            for (int q = 0; q < 4; q++) acc[i][j][q] = 0.f;

    auto issue_tile = [&](int kt, int st) {
        uint32_t* Ah_d = dsm + st * STG;
        uint32_t* Al_d = Ah_d + ASZ5;
        uint32_t* Bh_d = Al_d + ASZ5;
        uint32_t* Bl_d = Bh_d + BSZ;
        long long k0 = (long long)kt * KT5;
#pragma unroll
        for (int i = 0; i < 2; i++) {
            int c = tid + i * 256;
            int m = c >> 2, cq = c & 3;
            long long go = (long long)(bm + m) * K + k0 + cq * 4;
            cp16(smem_u32(&Ah_d[m * AST5 + cq * 4]), Ah + go);
            cp16(smem_u32(&Al_d[m * AST5 + cq * 4]), Al + go);
        }
        if (BT == 0) {
#pragma unroll
            for (int i = 0; i < 2; i++) {
                int c = tid + i * 256;
                int kk = c >> 5, nq = c & 31;
                int gc = bn + nq * 4;
                long long go = (long long)(k0 + kk) * N + gc;
                cp16z(smem_u32(&Bh_d[kk * BST5 + nq * 4]), Bh + go, gc < N);
                cp16z(smem_u32(&Bl_d[kk * BST5 + nq * 4]), Bl + go, gc < N);
            }
        } else {
#pragma unroll
            for (int i = 0; i < 2; i++) {
                int c = tid + i * 256;
                int n = c >> 2, cq = c & 3;
                long long go = (long long)(bn + n) * K + k0 + cq * 4;
                cp16(smem_u32(&Bh_d[n * AST5 + cq * 4]), Bh + go);
                cp16(smem_u32(&Bl_d[n * AST5 + cq * 4]), Bl + go);
            }
        }
        CP_COMMIT();
    };

    const int nk = K / KT5;
    issue_tile(0, 0);
    for (int kt = 0; kt < nk; kt++) {
        if (kt + 1 < nk) { issue_tile(kt + 1, (kt + 1) & 1); CP_WAIT1(); }
        else             { CP_WAIT0(); }
        __syncthreads();
        const uint32_t* Ah_s = dsm + (kt & 1) * STG;
        const uint32_t* Al_s = Ah_s + ASZ5;
        const uint32_t* Bh_s = Al_s + ASZ5;
        const uint32_t* Bl_s = Bh_s + BSZ;
        if (BT == 0) {
            MMA_COMPUTE_HL5(kr * BST5 + nb, (kr + 4) * BST5 + nb)
        } else {
            MMA_COMPUTE_HL5(nb * AST5 + kr, nb * AST5 + kr + 4)
        }
        __syncthreads();
    }

#pragma unroll
    for (int mt = 0; mt < 4; mt++) {
        int m0 = bm + wm * 64 + mt * 16 + g;
#pragma unroll
        for (int nt = 0; nt < 4; nt++) {
            int n0 = bn + wn * 32 + nt * 8 + t4 * 2;
            if (n0 < N) {
                C[(long long)m0 * N + n0]           = acc[mt][nt][0] * alpha;
                C[(long long)m0 * N + n0 + 1]       = acc[mt][nt][1] * alpha;
                C[(long long)(m0 + 8) * N + n0]     = acc[mt][nt][2] * alpha;
                C[(long long)(m0 + 8) * N + n0 + 1] = acc[mt][nt][3] * alpha;
            }
        }
    }
}

// ---------------- RoPE tables ----------------
__global__ void rope_init_kernel() {
    int idx = blockIdx.x * blockDim.x + threadIdx.x;
    if (idx >= Sn * HD) return;
    int s = idx >> 6;
    int j = idx & 63;
    int jj = j & 31;
    double inv = pow(10000.0, -((double)(2 * jj)) / 64.0);
    double ang = (double)s * inv;
    g_cos[idx] = (float)cos(ang);
    g_sin[idx] = (float)sin(ang);
}

// ---------------- embedding gather (raw + fp16 pairs) ----------------
__global__ void embed_kernel(const int* __restrict__ ids, const float* __restrict__ table,
                             float* __restrict__ out,
                             uint32_t* __restrict__ oh, uint32_t* __restrict__ ol) {
    int p = blockIdx.x * blockDim.x + threadIdx.x;   // TOK*Dm/2 pairs
    int t = p >> 9;
    int d2 = p & 511;
    const float2 v = *(const float2*)&table[(long long)ids[t] * Dm + 2 * d2];
    *(float2*)&out[(long long)t * Dm + 2 * d2] = v;
    uint32_t hp, lp;
    sp16pair(v.x, v.y, hp, lp);
    oh[p] = hp;
    ol[p] = lp;
}

// ---------------- fp32 scalar SGEMM (tiny gate GEMM; exact routing) ----------------
__global__ void sgemm_kernel(const float* __restrict__ A, const float* __restrict__ W,
                             const float* __restrict__ bias, float* __restrict__ C,
                             int M, int N, int K) {
    const int tid = threadIdx.x;
    const int bm = blockIdx.y * 64, bn = blockIdx.x * 64;
    __shared__ float As[16][68];
    __shared__ float Ws[16][68];
    float acc[4][4] = {};
    const int ty = tid >> 4, tx = tid & 15;
    for (int k0 = 0; k0 < K; k0 += 16) {
#pragma unroll
        for (int i = 0; i < 4; i++) {
            int e = tid + i * 256;
            int r = e >> 4, kk = e & 15;
            int gr = bm + r, gk = k0 + kk;
            As[kk][r] = (gr < M && gk < K) ? A[(long long)gr * K + gk] : 0.f;
        }
#pragma unroll
        for (int i = 0; i < 4; i++) {
            int e = tid + i * 256;
            int kk = e >> 6, c = e & 63;
            int gk = k0 + kk, gc = bn + c;
            Ws[kk][c] = (gk < K && gc < N) ? W[(long long)gk * N + gc] : 0.f;
        }
        __syncthreads();
#pragma unroll
        for (int kk = 0; kk < 16; kk++) {
            float4 a4 = *(const float4*)&As[kk][ty * 4];
            float4 b4 = *(const float4*)&Ws[kk][tx * 4];
            float av[4] = {a4.x, a4.y, a4.z, a4.w};
            float bv[4] = {b4.x, b4.y, b4.z, b4.w};
#pragma unroll
            for (int i = 0; i < 4; i++)
#pragma unroll
                for (int j = 0; j < 4; j++) acc[i][j] += av[i] * bv[j];
        }
        __syncthreads();
    }
#pragma unroll
    for (int i = 0; i < 4; i++) {
        int r = bm + ty * 4 + i;
        if (r >= M) continue;
#pragma unroll
        for (int j = 0; j < 4; j++) {
            int c = bn + tx * 4 + j;
            if (c >= N) continue;
            C[(long long)r * N + c] = acc[i][j] + (bias ? bias[c] : 0.f);
        }
    }
}

// ---------------- RoPE + permute (tf32 hi/lo out for Q/K/V) ----------------
__global__ void rope_perm_kernel(const float* __restrict__ lin,
                                 uint32_t* __restrict__ oh, uint32_t* __restrict__ ol,
                                 int do_rope) {
    int idx = blockIdx.x * blockDim.x + threadIdx.x;
    int t = idx >> 10;
    int col = idx & 1023;
    int b = t >> 9;
    int s = t & 511;
    int h = col >> 6;
    int d = col & 63;
    float v = lin[idx];
    float o = v;
    if (do_rope) {
        float other = (d < 32) ? -lin[idx + 32] : lin[idx - 32];
        o = v * g_cos[s * 64 + d] + other * g_sin[s * 64 + d];
    }
    long long oi = ((long long)(b * Hn + h) * Sn + s) * HD + d;
    uint32_t hh, ll;
    sp(o, hh, ll);
    oh[oi] = hh;
    ol[oi] = ll;
}

// ---------------- [b,h,s,hd] -> [tok,D] permute (fp16 pairs out) ----------------
__global__ void perm_back_kernel(const float* __restrict__ att,
                                 uint32_t* __restrict__ oh, uint32_t* __restrict__ ol) {
    int idx = blockIdx.x * blockDim.x + threadIdx.x;   // TOK*Dm/2 pairs
    int d2 = idx & 31;
    int s = (idx >> 5) & 511;
    int h = (idx >> 14) & 15;
    int b = idx >> 18;
    const float2 v = *(const float2*)&att[(((long long)(b * Hn + h) * Sn + s) * HD) + 2 * d2];
    long long oi = (long long)(b * Sn + s) * (Dm / 2) + h * 32 + d2;
    uint32_t hp, lp;
    sp16pair(v.x, v.y, hp, lp);
    oh[oi] = hp;
    ol[oi] = lp;
}

// ---------------- row softmax (tf32 hi/lo out) ----------------
__global__ void softmax_rows_kernel(const float* __restrict__ sc,
                                    uint32_t* __restrict__ oh, uint32_t* __restrict__ ol,
                                    int causal) {
    int row = blockIdx.x;
    long long base = ((long long)blockIdx.y * Sn + row) * Sn;
    int tid = threadIdx.x;
    float v0 = sc[base + tid];
    float v1 = sc[base + tid + 256];
    if (causal) {
        if (tid > row) v0 = -1e9f;
        if (tid + 256 > row) v1 = -1e9f;
    }
    __shared__ float red[256];
    float m = fmaxf(v0, v1);
    red[tid] = m;
    __syncthreads();
    for (int s = 128; s > 0; s >>= 1) {
        if (tid < s) red[tid] = fmaxf(red[tid], red[tid + s]);
        __syncthreads();
    }
    m = red[0];
    __syncthreads();
    float e0 = expf(v0 - m), e1 = expf(v1 - m);
    red[tid] = e0 + e1;
    __syncthreads();
    for (int s = 128; s > 0; s >>= 1) {
        if (tid < s) red[tid] += red[tid + s];
        __syncthreads();
    }
    float inv = 1.f / red[0];
    uint32_t h, l;
    sp(e0 * inv, h, l);
    oh[base + tid] = h;
    ol[base + tid] = l;
    sp(e1 * inv, h, l);
    oh[base + tid + 256] = h;
    ol[base + tid + 256] = l;
}

// ---------------- fused residual add(+add2) + layernorm (raw + fp16 pairs) ----------------
__global__ void add_ln_kernel(const float* __restrict__ x, const float* __restrict__ a,
                              const float* __restrict__ a2,
                              const float* __restrict__ g, const float* __restrict__ b,
                              float* __restrict__ out,
                              uint32_t* __restrict__ oh, uint32_t* __restrict__ ol) {
    int t = blockIdx.x;
    int tid = threadIdx.x;
    long long base = (long long)t * Dm;
    int c0 = tid * 4;
    float v[4];
#pragma unroll
    for (int i = 0; i < 4; i++) {
        float s = x[base + c0 + i] + a[base + c0 + i];
        if (a2) s += a2[base + c0 + i];
        v[i] = s;
    }
    __shared__ float red[256];
    red[tid] = v[0] + v[1] + v[2] + v[3];
    __syncthreads();
    for (int k = 128; k > 0; k >>= 1) {
        if (tid < k) red[tid] += red[tid + k];
        __syncthreads();
    }
    float mu = red[0] * (1.f / Dm);
    __syncthreads();
    float q = 0.f;
#pragma unroll
    for (int i = 0; i < 4; i++) { float d = v[i] - mu; q += d * d; }
    red[tid] = q;
    __syncthreads();
    for (int k = 128; k > 0; k >>= 1) {
        if (tid < k) red[tid] += red[tid + k];
        __syncthreads();
    }
    float var = red[0] * (1.f / Dm);
    float inv = rsqrtf(var + 1e-5f);
    float o[4];
#pragma unroll
    for (int i = 0; i < 4; i++)
        o[i] = (v[i] - mu) * inv * g[c0 + i] + b[c0 + i];
    *(float4*)&out[base + c0] = make_float4(o[0], o[1], o[2], o[3]);
    long long pb = (long long)t * (Dm / 2) + tid * 2;
    uint32_t hp, lp;
    sp16pair(o[0], o[1], hp, lp);
    oh[pb] = hp;
    ol[pb] = lp;
    sp16pair(o[2], o[3], hp, lp);
    oh[pb + 1] = hp;
    ol[pb + 1] = lp;
}

// ---------------- MoE gating ----------------
__global__ void zero_cnt_kernel(int* c) { if (threadIdx.x < En) c[threadIdx.x] = 0; }

__global__ void gate_route_kernel(const float* __restrict__ logits, float* __restrict__ topw,
                                  int* __restrict__ list, int* __restrict__ cnt) {
    int t = blockIdx.x * blockDim.x + threadIdx.x;
    if (t >= TOK) return;
    float p[En];
    float m = -1e30f;
#pragma unroll
    for (int e = 0; e < En; e++) { p[e] = logits[t * En + e]; m = fmaxf(m, p[e]); }
    float s = 0.f;
#pragma unroll
    for (int e = 0; e < En; e++) { p[e] = expf(p[e] - m); s += p[e]; }
    float invs = 1.f / s;
#pragma unroll
    for (int e = 0; e < En; e++) p[e] *= invs;
    int i0 = 0;
#pragma unroll
    for (int e = 1; e < En; e++) if (p[e] > p[i0]) i0 = e;
    int i1 = (i0 == 0) ? 1 : 0;
#pragma unroll
    for (int e = 0; e < En; e++) if (e != i0 && p[e] > p[i1]) i1 = e;
    float s2 = p[i0] + p[i1];
    topw[t * 2 + 0] = p[i0] / s2;
    topw[t * 2 + 1] = p[i1] / s2;
    int pos = atomicAdd(&cnt[i0], 1);
    list[i0 * TOK + pos] = t * 2 + 0;
    pos = atomicAdd(&cnt[i1], 1);
    list[i1 * TOK + pos] = t * 2 + 1;
}

// ================= host orchestration =================
struct DevPtrs {
    float *x, *y, *lin0, *lin1, *lin2, *sc, *att, *proj, *moe0, *moe1, *gate, *topw;
    uint32_t *xh, *xl, *yh, *yl, *qh, *ql, *kh, *kl, *vh, *vl;
    uint32_t *sch, *scl, *atth, *attl, *h1h, *h1l, *wth, *wtl;
    int *list, *cnt;
};

static void tsp(const float* W, uint32_t* h, uint32_t* l, int K, int N, int batch,
                long long zsrc, long long zdst) {
    dim3 g(N / 32, K / 32, batch);
    tsp_kernel<<<g, dim3(32, 8)>>>(W, h, l, K, N, zsrc, zdst);
}

// fp16x3 plain GEMM: C = Apairs @ Wt^T + bias
static void wgemm(const uint32_t* Ah, const uint32_t* Al,
                  const uint32_t* Bh, const uint32_t* Bl,
                  const float* bias, float* C, int M, int N, int K) {
    dim3 g(N / 128, M / 128, 1);
    hgemm16<0><<<g, 512, SMEM16_BYTES>>>(Ah, Al, Bh, Bl, bias, C,
                                         nullptr, nullptr, nullptr, nullptr, nullptr,
                                         nullptr, nullptr, M, N, K, 0, 0, 0);
}

static void run_mha(DevPtrs& P, float* xio, uint32_t* xh, uint32_t* xl,
                    const uint32_t* kvh, const uint32_t* kvl,
                    const float* wqkv, const float* bqkv,
                    const float* wo, const float* bo,
                    const float* lng, const float* lnb, int causal) {
    tsp(wqkv, P.wth, P.wtl, Dm, Dm, 3, (long long)Dm * Dm, (long long)Dm * Dm / 2);
    wgemm(xh,  xl,  P.wth,                  P.wtl,                  bqkv,          P.lin0, TOK, Dm, Dm);
    wgemm(kvh, kvl, P.wth + Dm * Dm / 2,    P.wtl + Dm * Dm / 2,    bqkv + Dm,     P.lin1, TOK, Dm, Dm);
    wgemm(kvh, kvl, P.wth + Dm * Dm,        P.wtl + Dm * Dm,        bqkv + 2 * Dm, P.lin2, TOK, Dm, Dm);
    int nb = (TOK * Dm) / 256;
    rope_perm_kernel<<<nb, 256>>>(P.lin0, P.qh, P.ql, 1);
    rope_perm_kernel<<<nb, 256>>>(P.lin1, P.kh, P.kl, 1);
    rope_perm_kernel<<<nb, 256>>>(P.lin2, P.vh, P.vl, 0);
    {   // scores = Q @ K^T * scale
        dim3 g(Sn / 128, Sn / 128, Bn * Hn);
        mma_gemm_hl<1><<<g, 256, SMEM51_BYTES>>>(P.qh, P.ql, P.kh, P.kl, P.sc,
                                                 Sn, Sn, HD, 0.125f,
                                                 (long long)Sn * HD, (long long)Sn * HD,
                                                 (long long)Sn * Sn);
    }
    softmax_rows_kernel<<<dim3(Sn, Bn * Hn), 256>>>(P.sc, P.sch, P.scl, causal);
    {   // att = P @ V
        dim3 g(1, Sn / 128, Bn * Hn);
        mma_gemm_hl<0><<<g, 256, SMEM50_BYTES>>>(P.sch, P.scl, P.vh, P.vl, P.att,
                                                 Sn, HD, Sn, 1.f,
                                                 (long long)Sn * Sn, (long long)Sn * HD,
                                                 (long long)Sn * HD);
    }
    perm_back_kernel<<<(TOK * Dm / 2) / 256, 256>>>(P.att, P.atth, P.attl);
    tsp(wo, P.wth, P.wtl, Dm, Dm, 1, 0, 0);
    wgemm(P.atth, P.attl, P.wth, P.wtl, bo, P.proj, TOK, Dm, Dm);
    add_ln_kernel<<<TOK, 256>>>(xio, P.proj, nullptr, lng, lnb, xio, xh, xl);
}

static void run_moe(DevPtrs& P, float* xio, uint32_t* xh, uint32_t* xl,
                    const float* gw, const float* gb,
                    const float* w1, const float* b1, const float* w2, const float* b2,
                    const float* lng, const float* lnb) {
    sgemm_kernel<<<dim3(1, TOK / 64), 256>>>(xio, gw, gb, P.gate, TOK, En, Dm);
    zero_cnt_kernel<<<1, 32>>>(P.cnt);
    gate_route_kernel<<<TOK / 256, 256>>>(P.gate, P.topw, P.list, P.cnt);
    // GEMM1: H1 = relu(X[toks] @ W1 + b1), W1 [Dm,FF] -> pairs [FF][Dm/2]
    tsp(w1, P.wth, P.wtl, Dm, FF, En, (long long)Dm * FF, (long long)Dm * FF / 2);
    {
        dim3 g(FF / 128, TOK / 128, En);
        hgemm16<1><<<g, 512, SMEM16_BYTES>>>(
            xh, xl, P.wth, P.wtl, b1, nullptr, P.h1h, P.h1l,
            nullptr, nullptr, nullptr, P.list, P.cnt,
            TOK, FF, Dm, 0, (long long)Dm * FF / 2, (long long)TOK * FF / 2);
    }
    // GEMM2: scatter w * (H1 @ W2 + b2), W2 [FF,Dm] -> pairs [Dm][FF/2]
    tsp(w2, P.wth, P.wtl, FF, Dm, En, (long long)FF * Dm, (long long)FF * Dm / 2);
    {
        dim3 g(Dm / 128, TOK / 128, En);
        hgemm16<2><<<g, 512, SMEM16_BYTES>>>(
            P.h1h, P.h1l, P.wth, P.wtl, b2, nullptr, nullptr, nullptr,
            P.moe0, P.moe1, P.topw, P.list, P.cnt,
            TOK, Dm, FF, (long long)TOK * FF / 2, (long long)FF * Dm / 2, 0);
    }
    add_ln_kernel<<<TOK, 256>>>(xio, P.moe0, P.moe1, lng, lnb, xio, xh, xl);
}

extern "C" void kernel_launch(void* const* d_in, const int* in_sizes, int n_in,
                              void* d_out, int out_size) {
    (void)in_sizes; (void)n_in; (void)out_size;
    const int*   src           = (const int*)  d_in[0];
    const int*   tgt           = (const int*)  d_in[1];
    const float* emb_src       = (const float*)d_in[2];
    const float* emb_tgt       = (const float*)d_in[3];
    const float* enc_wqkv      = (const float*)d_in[4];
    const float* enc_bqkv      = (const float*)d_in[5];
    const float* enc_wo        = (const float*)d_in[6];
    const float* enc_bo        = (const float*)d_in[7];
    const float* enc_gate_w    = (const float*)d_in[8];
    const float* enc_gate_b    = (const float*)d_in[9];
    const float* enc_w1        = (const float*)d_in[10];
    const float* enc_b1        = (const float*)d_in[11];
    const float* enc_w2        = (const float*)d_in[12];
    const float* enc_b2        = (const float*)d_in[13];
    const float* enc_ln        = (const float*)d_in[14];
    const float* dec_self_wqkv = (const float*)d_in[15];
    const float* dec_self_bqkv = (const float*)d_in[16];
    const float* dec_self_wo   = (const float*)d_in[17];
    const float* dec_self_bo   = (const float*)d_in[18];
    const float* dec_cross_wqkv= (const float*)d_in[19];
    const float* dec_cross_bqkv= (const float*)d_in[20];
    const float* dec_cross_wo  = (const float*)d_in[21];
    const float* dec_cross_bo  = (const float*)d_in[22];
    const float* dec_gate_w    = (const float*)d_in[23];
    const float* dec_gate_b    = (const float*)d_in[24];
    const float* dec_w1        = (const float*)d_in[25];
    const float* dec_b1        = (const float*)d_in[26];
    const float* dec_w2        = (const float*)d_in[27];
    const float* dec_b2        = (const float*)d_in[28];
    const float* dec_ln        = (const float*)d_in[29];
    const float* final_w       = (const float*)d_in[30];
    const float* final_b       = (const float*)d_in[31];
    float* out = (float*)d_out;

    cudaFuncSetAttribute(hgemm16<0>, cudaFuncAttributeMaxDynamicSharedMemorySize, SMEM16_BYTES);
    cudaFuncSetAttribute(hgemm16<1>, cudaFuncAttributeMaxDynamicSharedMemorySize, SMEM16_BYTES);
    cudaFuncSetAttribute(hgemm16<2>, cudaFuncAttributeMaxDynamicSharedMemorySize, SMEM16_BYTES);
    cudaFuncSetAttribute(mma_gemm_hl<0>, cudaFuncAttributeMaxDynamicSharedMemorySize, SMEM50_BYTES);
    cudaFuncSetAttribute(mma_gemm_hl<1>, cudaFuncAttributeMaxDynamicSharedMemorySize, SMEM51_BYTES);

    DevPtrs P;
    cudaGetSymbolAddress((void**)&P.x, g_x);
    cudaGetSymbolAddress((void**)&P.y, g_y);
    cudaGetSymbolAddress((void**)&P.xh, g_xh);
    cudaGetSymbolAddress((void**)&P.xl, g_xl);
    cudaGetSymbolAddress((void**)&P.yh, g_yh);
    cudaGetSymbolAddress((void**)&P.yl, g_yl);
    cudaGetSymbolAddress((void**)&P.lin0, g_lin0);
    cudaGetSymbolAddress((void**)&P.lin1, g_lin1);
    cudaGetSymbolAddress((void**)&P.lin2, g_lin2);
    cudaGetSymbolAddress((void**)&P.qh, g_qh);
    cudaGetSymbolAddress((void**)&P.ql, g_ql);
    cudaGetSymbolAddress((void**)&P.kh, g_kh);
    cudaGetSymbolAddress((void**)&P.kl, g_kl);
    cudaGetSymbolAddress((void**)&P.vh, g_vh);
    cudaGetSymbolAddress((void**)&P.vl, g_vl);
    cudaGetSymbolAddress((void**)&P.sc, g_sc);
    cudaGetSymbolAddress((void**)&P.sch, g_sch);
    cudaGetSymbolAddress((void**)&P.scl, g_scl);
    cudaGetSymbolAddress((void**)&P.att, g_att);
    cudaGetSymbolAddress((void**)&P.atth, g_atth);
    cudaGetSymbolAddress((void**)&P.attl, g_attl);
    cudaGetSymbolAddress((void**)&P.proj, g_proj);
    cudaGetSymbolAddress((void**)&P.h1h, g_h1h);
    cudaGetSymbolAddress((void**)&P.h1l, g_h1l);
    cudaGetSymbolAddress((void**)&P.moe0, g_moe0);
    cudaGetSymbolAddress((void**)&P.moe1, g_moe1);
    cudaGetSymbolAddress((void**)&P.gate, g_gate);
    cudaGetSymbolAddress((void**)&P.topw, g_topw);
    cudaGetSymbolAddress((void**)&P.list, g_list);
    cudaGetSymbolAddress((void**)&P.cnt, g_cnt);
    cudaGetSymbolAddress((void**)&P.wth, g_wth);
    cudaGetSymbolAddress((void**)&P.wtl, g_wtl);

    rope_init_kernel<<<(Sn * HD) / 256, 256>>>();

    // ---------- encoder ----------
    embed_kernel<<<(TOK * Dm / 2) / 256, 256>>>(src, emb_src, P.x, P.xh, P.xl);
    for (int l = 0; l < Ln; l++) {
        run_mha(P, P.x, P.xh, P.xl, P.xh, P.xl,
                enc_wqkv + (long long)l * 3 * Dm * Dm, enc_bqkv + l * 3 * Dm,
                enc_wo + (long long)l * Dm * Dm, enc_bo + l * Dm,
                enc_ln + ((l * 2 + 0) * 2 + 0) * Dm, enc_ln + ((l * 2 + 0) * 2 + 1) * Dm, 0);
        run_moe(P, P.x, P.xh, P.xl,
                enc_gate_w + l * Dm * En, enc_gate_b + l * En,
                enc_w1 + (long long)l * En * Dm * FF, enc_b1 + l * En * FF,
                enc_w2 + (long long)l * En * FF * Dm, enc_b2 + l * En * Dm,
                enc_ln + ((l * 2 + 1) * 2 + 0) * Dm, enc_ln + ((l * 2 + 1) * 2 + 1) * Dm);
    }

    // ---------- decoder ----------
    embed_kernel<<<(TOK * Dm / 2) / 256, 256>>>(tgt, emb_tgt, P.y, P.yh, P.yl);
    for (int l = 0; l < Ln; l++) {
        run_mha(P, P.y, P.yh, P.yl, P.yh, P.yl,
                dec_self_wqkv + (long long)l * 3 * Dm * Dm, dec_self_bqkv + l * 3 * Dm,
                dec_self_wo + (long long)l * Dm * Dm, dec_self_bo + l * Dm,
                dec_ln + ((l * 3 + 0) * 2 + 0) * Dm, dec_ln + ((l * 3 + 0) * 2 + 1) * Dm, 1);
        run_mha(P, P.y, P.yh, P.yl, P.xh, P.xl,
                dec_cross_wqkv + (long long)l * 3 * Dm * Dm, dec_cross_bqkv + l * 3 * Dm,
                dec_cross_wo + (long long)l * Dm * Dm, dec_cross_bo + l * Dm,
                dec_ln + ((l * 3 + 1) * 2 + 0) * Dm, dec_ln + ((l * 3 + 1) * 2 + 1) * Dm, 0);
        run_moe(P, P.y, P.yh, P.yl,
                dec_gate_w + l * Dm * En, dec_gate_b + l * En,
                dec_w1 + (long long)l * En * Dm * FF, dec_b1 + l * En * FF,
                dec_w2 + (long long)l * En * FF * Dm, dec_b2 + l * En * Dm,
                dec_ln + ((l * 3 + 2) * 2 + 0) * Dm, dec_ln + ((l * 3 + 2) * 2 + 1) * Dm);
    }

    // ---------- final projection ----------
    tsp(final_w, P.wth, P.wtl, Dm, VT, 1, 0, 0);
    wgemm(P.yh, P.yl, P.wth, P.wtl, final_b, out, TOK, VT, Dm);
}

// round 10
// speedup vs baseline: 1.4009x; 1.0732x over previous
#include <cuda_runtime.h>
#include <cuda_fp16.h>
#include <math.h>
#include <stdint.h>

// ---------------- problem constants ----------------
#define Bn   4
#define Sn   512
#define Dm   1024
#define Hn   16
#define HD   64
#define En   8
#define FF   2048
#define Ln   2
#define VT   32000
#define TOK  (Bn*Sn)      // 2048 tokens
#define BH   (Bn*Hn)      // 64 attention batches

// ---- fp16-pair GEMM tiling (512 thr, tile 128x128, KT=32 -> 16 pairs) ----
#define KPT  16           // u32 pairs per K-tile
#define PST  20           // smem stride (u32)
#define PASZ (128*PST)    // 2560 u32 per array
#define STG16 (4*PASZ)    // Ah,Al,Bh,Bl per stage = 10240 u32 = 40960 B
#define NSTAGE 3
#define SMEM16_BYTES (NSTAGE*STG16*4)   // 122880

// ---------------- device scratch (no allocations allowed) ----------------
__device__ float    g_x[TOK*Dm];
__device__ float    g_y[TOK*Dm];
__device__ uint32_t g_xh[TOK*Dm/2], g_xl[TOK*Dm/2];          // fp16 pairs
__device__ uint32_t g_yh[TOK*Dm/2], g_yl[TOK*Dm/2];
__device__ float    g_lin0[TOK*Dm];
__device__ float    g_lin1[TOK*Dm];
__device__ float    g_lin2[TOK*Dm];
__device__ uint32_t g_qph[TOK*Dm/2], g_qpl[TOK*Dm/2];        // Q pairs [bh*512+s][32]
__device__ uint32_t g_kph[TOK*Dm/2], g_kpl[TOK*Dm/2];        // K pairs
__device__ uint32_t g_vth[BH*128*(Sn/2)], g_vtl[BH*128*(Sn/2)];  // V^T pairs [bh][128 d][256]
__device__ float    g_sc[(size_t)BH*Sn*Sn];
__device__ uint32_t g_sph[(size_t)BH*Sn*(Sn/2)], g_spl[(size_t)BH*Sn*(Sn/2)];  // prob pairs
__device__ float    g_att[TOK*Dm];
__device__ uint32_t g_atth[TOK*Dm/2], g_attl[TOK*Dm/2];      // fp16 pairs
__device__ float    g_proj[TOK*Dm];
__device__ uint32_t g_h1h[(size_t)En*TOK*FF/2], g_h1l[(size_t)En*TOK*FF/2];
__device__ float    g_moe0[TOK*Dm];
__device__ float    g_moe1[TOK*Dm];
__device__ float    g_gate[TOK*En];
__device__ float    g_topw[TOK*2];
__device__ int      g_list[En*TOK];
__device__ int      g_cnt[En];
__device__ float    g_cos[Sn*HD];
__device__ float    g_sin[Sn*HD];
__device__ uint32_t g_wth[16777216], g_wtl[16777216];        // weight pairs [N][K/2]

// ---------------- helpers ----------------
__device__ __forceinline__ void sp16pair(float v0, float v1, uint32_t& hp, uint32_t& lp) {
    __half h0 = __float2half_rn(v0);
    __half h1 = __float2half_rn(v1);
    __half l0 = __float2half_rn((v0 - __half2float(h0)) * 2048.f);
    __half l1 = __float2half_rn((v1 - __half2float(h1)) * 2048.f);
    hp = (uint32_t)__half_as_ushort(h0) | ((uint32_t)__half_as_ushort(h1) << 16);
    lp = (uint32_t)__half_as_ushort(l0) | ((uint32_t)__half_as_ushort(l1) << 16);
}
__device__ __forceinline__ uint32_t smem_u32(const void* p) {
    return (uint32_t)__cvta_generic_to_shared(p);
}
__device__ __forceinline__ void cp16(uint32_t dst, const void* src) {
    asm volatile("cp.async.cg.shared.global [%0], [%1], 16;" :: "r"(dst), "l"(src));
}
#define CP_COMMIT() asm volatile("cp.async.commit_group;")
#define CP_WAITG(n) asm volatile("cp.async.wait_group %0;" :: "n"(n))

__device__ __forceinline__ void mma_f16(float* c, const uint32_t* a, const uint32_t* b) {
    asm volatile(
        "mma.sync.aligned.m16n8k16.row.col.f32.f16.f16.f32 "
        "{%0,%1,%2,%3}, {%4,%5,%6,%7}, {%8,%9}, {%0,%1,%2,%3};"
        : "+f"(c[0]), "+f"(c[1]), "+f"(c[2]), "+f"(c[3])
        : "r"(a[0]), "r"(a[1]), "r"(a[2]), "r"(a[3]), "r"(b[0]), "r"(b[1]));
}
#define LDSM4(r0, r1, r2, r3, addr) \
    asm volatile("ldmatrix.sync.aligned.m8n8.x4.shared.b16 {%0,%1,%2,%3}, [%4];" \
                 : "=r"(r0), "=r"(r1), "=r"(r2), "=r"(r3) : "r"(addr))

// =====================================================================
// fp16x3 GEMM: acc = A @ B^T, A [M][K/2] pairs, B [N][K/2] pairs.
// result = (accM + accC/2048)*alpha (+bias). 512 thr, 16 warps, 32x32 warp tile.
// ldmatrix fragment loads, 3-stage cp.async pipeline.
// MODE0: plain fp32 out (Nstore = store bound & C row stride).
// MODE1: gather rows by list (z=expert), relu, pack pairs out.
// MODE2: scatter out_slot = topw * (acc + bias) (z=expert).
// M%128==0, K%32==0. Tile-N rows bn..bn+127 must be readable in B.
// =====================================================================
template<int MODE>
__global__ void __launch_bounds__(512) hgemm16(
    const uint32_t* __restrict__ Ah, const uint32_t* __restrict__ Al,
    const uint32_t* __restrict__ Bh, const uint32_t* __restrict__ Bl,
    const float* __restrict__ bias, float* __restrict__ C,
    uint32_t* __restrict__ Oh, uint32_t* __restrict__ Ol,
    float* __restrict__ out0, float* __restrict__ out1, const float* __restrict__ topw,
    const int* __restrict__ list, const int* __restrict__ cnt,
    int M, int Nstore, int K, float alpha,
    long long sAz, long long sBz, long long sCz)
{
    const int z = blockIdx.z;
    const int bm = blockIdx.y * 128, bn = blockIdx.x * 128;
    int nrows = M;
    const int* lst = nullptr;
    if (MODE >= 1) {
        nrows = cnt[z];
        if (bm >= nrows) return;
        lst = list + z * TOK;
        bias += (long long)z * Nstore;
    }
    Ah += (long long)z * sAz;  Al += (long long)z * sAz;
    Bh += (long long)z * sBz;  Bl += (long long)z * sBz;
    if (MODE == 0) C += (long long)z * sCz;
    if (MODE == 1) { Oh += (long long)z * sCz; Ol += (long long)z * sCz; }

    extern __shared__ uint32_t dsm[];
    __shared__ int ents[128];
    const int tid  = threadIdx.x;
    const int lane = tid & 31;
    const int warp = tid >> 5;
    const int wm = warp >> 2, wn = warp & 3;
    const int g  = lane >> 2, t4 = lane & 3;
    const int lrow = lane & 7, seg = lane >> 3;
    const int Kp = K >> 1;

    if (MODE >= 1 && tid < 128) {
        int gr = bm + tid;
        ents[tid] = (gr < nrows) ? lst[gr] : -1;
    }
    __syncthreads();

    float accM[2][4][4], accC[2][4][4];
#pragma unroll
    for (int i = 0; i < 2; i++)
#pragma unroll
        for (int j = 0; j < 4; j++)
#pragma unroll
            for (int q = 0; q < 4; q++) { accM[i][j][q] = 0.f; accC[i][j][q] = 0.f; }

    const int r = tid >> 2, ch = tid & 3;            // 128 rows x 4 16B-chunks
    long long arow;
    if (MODE == 1) {
        int e = ents[r];
        arow = (e >= 0) ? (long long)(e >> 1) : 0;
    } else {
        arow = bm + r;
    }
    const long long brow = bn + r;

    auto issue_tile = [&](int kt) {
        uint32_t* AhS = dsm + (kt % NSTAGE) * STG16;
        uint32_t* AlS = AhS + PASZ;
        uint32_t* BhS = AlS + PASZ;
        uint32_t* BlS = BhS + PASZ;
        const long long kp0 = (long long)kt * KPT + ch * 4;
        const uint32_t d = r * PST + ch * 4;
        cp16(smem_u32(&AhS[d]), Ah + arow * Kp + kp0);
        cp16(smem_u32(&AlS[d]), Al + arow * Kp + kp0);
        cp16(smem_u32(&BhS[d]), Bh + brow * Kp + kp0);
        cp16(smem_u32(&BlS[d]), Bl + brow * Kp + kp0);
        CP_COMMIT();
    };

    const int nk = K / 32;
    issue_tile(0);
    if (nk > 1) issue_tile(1);
    for (int kt = 0; kt < nk; kt++) {
        if (kt + 2 < nk)      { issue_tile(kt + 2); CP_WAITG(2); }
        else if (kt + 1 < nk) { CP_WAITG(1); }
        else                  { CP_WAITG(0); }
        __syncthreads();
        const uint32_t* AhS = dsm + (kt % NSTAGE) * STG16;
        const uint32_t* AlS = AhS + PASZ;
        const uint32_t* BhS = AlS + PASZ;
        const uint32_t* BlS = BhS + PASZ;
        const int moff = wm * 32, noff = wn * 32;
#pragma unroll
        for (int ks = 0; ks < 2; ks++) {
            const int kb = ks * 8;
            uint32_t aH[2][4], aL[2][4], bH[4][2], bL[4][2];
            // A fragments via ldmatrix x4: segs = {rows+0,k0},{rows+8,k0},{rows+0,k4},{rows+8,k4}
            const int akc = kb + ((seg >> 1) << 2);
#pragma unroll
            for (int mt = 0; mt < 2; mt++) {
                int mrow = moff + mt * 16 + lrow + ((seg & 1) << 3);
                LDSM4(aH[mt][0], aH[mt][1], aH[mt][2], aH[mt][3],
                      smem_u32(&AhS[mrow * PST + akc]));
                LDSM4(aL[mt][0], aL[mt][1], aL[mt][2], aL[mt][3],
                      smem_u32(&AlS[mrow * PST + akc]));
            }
            // B fragments via ldmatrix x4: segs = {nt,k0},{nt,k4},{nt+1,k0},{nt+1,k4}
            const int bkc = kb + ((seg & 1) << 2);
#pragma unroll
            for (int nt2 = 0; nt2 < 2; nt2++) {
                int nrow = noff + (nt2 * 2 + (seg >> 1)) * 8 + lrow;
                LDSM4(bH[nt2*2][0], bH[nt2*2][1], bH[nt2*2+1][0], bH[nt2*2+1][1],
                      smem_u32(&BhS[nrow * PST + bkc]));
                LDSM4(bL[nt2*2][0], bL[nt2*2][1], bL[nt2*2+1][0], bL[nt2*2+1][1],
                      smem_u32(&BlS[nrow * PST + bkc]));
            }
#pragma unroll
            for (int mt = 0; mt < 2; mt++)
#pragma unroll
                for (int nt = 0; nt < 4; nt++) {
                    mma_f16(accM[mt][nt], aH[mt], bH[nt]);
                    mma_f16(accC[mt][nt], aH[mt], bL[nt]);
                    mma_f16(accC[mt][nt], aL[mt], bH[nt]);
                }
        }
        __syncthreads();
    }

    // ---- epilogue ----
    const float s = 1.f / 2048.f;
#pragma unroll
    for (int mt = 0; mt < 2; mt++) {
        int lr = wm * 32 + mt * 16 + g;
#pragma unroll
        for (int nt = 0; nt < 4; nt++) {
            int n0 = bn + wn * 32 + nt * 8 + t4 * 2;
            if (n0 >= Nstore) continue;
            float b0v = bias ? bias[n0] : 0.f;
            float b1v = bias ? bias[n0 + 1] : 0.f;
            float v0 = (accM[mt][nt][0] + accC[mt][nt][0] * s) * alpha + b0v;
            float v1 = (accM[mt][nt][1] + accC[mt][nt][1] * s) * alpha + b1v;
            float v2 = (accM[mt][nt][2] + accC[mt][nt][2] * s) * alpha + b0v;
            float v3 = (accM[mt][nt][3] + accC[mt][nt][3] * s) * alpha + b1v;
            if (MODE == 0) {
                long long m0 = bm + lr;
                C[m0 * Nstore + n0] = v0;
                C[m0 * Nstore + n0 + 1] = v1;
                C[(m0 + 8) * Nstore + n0] = v2;
                C[(m0 + 8) * Nstore + n0 + 1] = v3;
            } else if (MODE == 1) {
                if (bm + lr < nrows) {
                    uint32_t hp, lp;
                    sp16pair(fmaxf(v0, 0.f), fmaxf(v1, 0.f), hp, lp);
                    size_t o = (size_t)(bm + lr) * (Nstore >> 1) + (n0 >> 1);
                    Oh[o] = hp; Ol[o] = lp;
                }
                if (bm + lr + 8 < nrows) {
                    uint32_t hp, lp;
                    sp16pair(fmaxf(v2, 0.f), fmaxf(v3, 0.f), hp, lp);
                    size_t o = (size_t)(bm + lr + 8) * (Nstore >> 1) + (n0 >> 1);
                    Oh[o] = hp; Ol[o] = lp;
                }
            } else {
                int e0 = ents[lr], e2 = ents[lr + 8];
                if (e0 >= 0) {
                    float w = topw[e0];
                    float* o = (e0 & 1) ? out1 : out0;
                    long long t = (long long)(e0 >> 1) * Nstore;
                    o[t + n0] = w * v0;
                    o[t + n0 + 1] = w * v1;
                }
                if (e2 >= 0) {
                    float w = topw[e2];
                    float* o = (e2 & 1) ? out1 : out0;
                    long long t = (long long)(e2 >> 1) * Nstore;
                    o[t + n0] = w * v2;
                    o[t + n0 + 1] = w * v3;
                }
            }
        }
    }
}

// =====================================================================
// transpose+split+pack: W [K,N] fp32 -> Wh/Wl [N][K/2] fp16-pair u32.
// =====================================================================
__global__ void tsp_kernel(const float* __restrict__ W,
                           uint32_t* __restrict__ h, uint32_t* __restrict__ l,
                           int K, int N, long long zsrc, long long zdst) {
    __shared__ float t[32][33];
    const long long so = (long long)blockIdx.z * zsrc;
    const long long dz = (long long)blockIdx.z * zdst;
    const int bk = blockIdx.y * 32, bnn = blockIdx.x * 32;
    const int tx = threadIdx.x, ty = threadIdx.y;
#pragma unroll
    for (int r = 0; r < 4; r++)
        t[ty + r * 8][tx] = W[so + (long long)(bk + ty + r * 8) * N + bnn + tx];
    __syncthreads();
    const int Kp = K >> 1;
#pragma unroll
    for (int r = 0; r < 2; r++) {
        int kpl = ty * 2 + r;
        float v0 = t[2 * kpl][tx];
        float v1 = t[2 * kpl + 1][tx];
        uint32_t hp, lp;
        sp16pair(v0, v1, hp, lp);
        long long o = dz + (long long)(bnn + tx) * Kp + (bk >> 1) + kpl;
        h[o] = hp;
        l[o] = lp;
    }
}

// ---------------- RoPE tables ----------------
__global__ void rope_init_kernel() {
    int idx = blockIdx.x * blockDim.x + threadIdx.x;
    if (idx >= Sn * HD) return;
    int s = idx >> 6;
    int j = idx & 63;
    int jj = j & 31;
    double inv = pow(10000.0, -((double)(2 * jj)) / 64.0);
    double ang = (double)s * inv;
    g_cos[idx] = (float)cos(ang);
    g_sin[idx] = (float)sin(ang);
}

// ---------------- embedding gather (raw + fp16 pairs) ----------------
__global__ void embed_kernel(const int* __restrict__ ids, const float* __restrict__ table,
                             float* __restrict__ out,
                             uint32_t* __restrict__ oh, uint32_t* __restrict__ ol) {
    int p = blockIdx.x * blockDim.x + threadIdx.x;
    int t = p >> 9;
    int d2 = p & 511;
    const float2 v = *(const float2*)&table[(long long)ids[t] * Dm + 2 * d2];
    *(float2*)&out[(long long)t * Dm + 2 * d2] = v;
    uint32_t hp, lp;
    sp16pair(v.x, v.y, hp, lp);
    oh[p] = hp;
    ol[p] = lp;
}

// ---------------- fp32 scalar SGEMM (tiny gate GEMM; exact routing) ----------------
__global__ void sgemm_kernel(const float* __restrict__ A, const float* __restrict__ W,
                             const float* __restrict__ bias, float* __restrict__ C,
                             int M, int N, int K) {
    const int tid = threadIdx.x;
    const int bm = blockIdx.y * 64, bn = blockIdx.x * 64;
    __shared__ float As[16][68];
    __shared__ float Ws[16][68];
    float acc[4][4] = {};
    const int ty = tid >> 4, tx = tid & 15;
    for (int k0 = 0; k0 < K; k0 += 16) {
#pragma unroll
        for (int i = 0; i < 4; i++) {
            int e = tid + i * 256;
            int r = e >> 4, kk = e & 15;
            int gr = bm + r, gk = k0 + kk;
            As[kk][r] = (gr < M && gk < K) ? A[(long long)gr * K + gk] : 0.f;
        }
#pragma unroll
        for (int i = 0; i < 4; i++) {
            int e = tid + i * 256;
            int kk = e >> 6, c = e & 63;
            int gk = k0 + kk, gc = bn + c;
            Ws[kk][c] = (gk < K && gc < N) ? W[(long long)gk * N + gc] : 0.f;
        }
        __syncthreads();
#pragma unroll
        for (int kk = 0; kk < 16; kk++) {
            float4 a4 = *(const float4*)&As[kk][ty * 4];
            float4 b4 = *(const float4*)&Ws[kk][tx * 4];
            float av[4] = {a4.x, a4.y, a4.z, a4.w};
            float bv[4] = {b4.x, b4.y, b4.z, b4.w};
#pragma unroll
            for (int i = 0; i < 4; i++)
#pragma unroll
                for (int j = 0; j < 4; j++) acc[i][j] += av[i] * bv[j];
        }
        __syncthreads();
    }
#pragma unroll
    for (int i = 0; i < 4; i++) {
        int r = bm + ty * 4 + i;
        if (r >= M) continue;
#pragma unroll
        for (int j = 0; j < 4; j++) {
            int c = bn + tx * 4 + j;
            if (c >= N) continue;
            C[(long long)r * N + c] = acc[i][j] + (bias ? bias[c] : 0.f);
        }
    }
}

// ---------------- RoPE + permute, fp16 pairs out: [bh*512+s][32 hd-pairs] ----------------
__global__ void rope_pair_kernel(const float* __restrict__ lin,
                                 uint32_t* __restrict__ oh, uint32_t* __restrict__ ol) {
    int idx = blockIdx.x * blockDim.x + threadIdx.x;   // TOK*Dm/2
    int t = idx >> 9;
    int p = idx & 511;
    int h = p >> 5;
    int d2 = p & 31;
    int b = t >> 9;
    int s = t & 511;
    int d0 = 2 * d2, d1 = d0 + 1;
    float v0 = lin[(long long)t * Dm + h * 64 + d0];
    float v1 = lin[(long long)t * Dm + h * 64 + d1];
    float o0, o1;
    {
        float other = (d0 < 32) ? -lin[(long long)t * Dm + h * 64 + d0 + 32]
                                :  lin[(long long)t * Dm + h * 64 + d0 - 32];
        o0 = v0 * g_cos[s * 64 + d0] + other * g_sin[s * 64 + d0];
    }
    {
        float other = (d1 < 32) ? -lin[(long long)t * Dm + h * 64 + d1 + 32]
                                :  lin[(long long)t * Dm + h * 64 + d1 - 32];
        o1 = v1 * g_cos[s * 64 + d1] + other * g_sin[s * 64 + d1];
    }
    long long oi = ((long long)(b * Hn + h) * Sn + s) * 32 + d2;
    uint32_t hp, lp;
    sp16pair(o0, o1, hp, lp);
    oh[oi] = hp;
    ol[oi] = lp;
}

// ---------------- V transpose: lin [t][h*64+d] -> vt [bh][d][s-pairs] ----------------
__global__ void v_transpose_kernel(const float* __restrict__ lin,
                                   uint32_t* __restrict__ oh, uint32_t* __restrict__ ol) {
    __shared__ float sm[64][65];
    const int s0 = blockIdx.x * 64;
    const int bh = blockIdx.y;
    const int b = bh >> 4, h = bh & 15;
    const int tid = threadIdx.x;
    for (int i = tid; i < 64 * 64; i += 256) {
        int si = i >> 6, d = i & 63;
        sm[si][d] = lin[(long long)(b * Sn + s0 + si) * Dm + h * 64 + d];
    }
    __syncthreads();
    for (int i = tid; i < 32 * 64; i += 256) {
        int d = i >> 5, spi = i & 31;
        float v0 = sm[2 * spi][d];
        float v1 = sm[2 * spi + 1][d];
        uint32_t hp, lp;
        sp16pair(v0, v1, hp, lp);
        long long o = ((long long)bh * 128 + d) * (Sn / 2) + (s0 >> 1) + spi;
        oh[o] = hp;
        ol[o] = lp;
    }
}

// ---------------- [b,h,s,hd] -> [tok][Dm/2] pairs ----------------
__global__ void perm_back_kernel(const float* __restrict__ att,
                                 uint32_t* __restrict__ oh, uint32_t* __restrict__ ol) {
    int idx = blockIdx.x * blockDim.x + threadIdx.x;   // TOK*Dm/2 pairs
    int d2 = idx & 31;
    int s = (idx >> 5) & 511;
    int h = (idx >> 14) & 15;
    int b = idx >> 18;
    const float2 v = *(const float2*)&att[(((long long)(b * Hn + h) * Sn + s) * HD) + 2 * d2];
    long long oi = (long long)(b * Sn + s) * (Dm / 2) + h * 32 + d2;
    uint32_t hp, lp;
    sp16pair(v.x, v.y, hp, lp);
    oh[oi] = hp;
    ol[oi] = lp;
}

// ---------------- row softmax (fp16 pairs out) ----------------
__global__ void softmax_pair_kernel(const float* __restrict__ sc,
                                    uint32_t* __restrict__ oh, uint32_t* __restrict__ ol,
                                    int causal) {
    int row = blockIdx.x;
    long long base = ((long long)blockIdx.y * Sn + row) * Sn;
    int tid = threadIdx.x;
    float v0 = sc[base + 2 * tid];
    float v1 = sc[base + 2 * tid + 1];
    if (causal) {
        if (2 * tid > row) v0 = -1e9f;
        if (2 * tid + 1 > row) v1 = -1e9f;
    }
    __shared__ float red[256];
    float m = fmaxf(v0, v1);
    red[tid] = m;
    __syncthreads();
    for (int s = 128; s > 0; s >>= 1) {
        if (tid < s) red[tid] = fmaxf(red[tid], red[tid + s]);
        __syncthreads();
    }
    m = red[0];
    __syncthreads();
    float e0 = expf(v0 - m), e1 = expf(v1 - m);
    red[tid] = e0 + e1;
    __syncthreads();
    for (int s = 128; s > 0; s >>= 1) {
        if (tid < s) red[tid] += red[tid + s];
        __syncthreads();
    }
    float inv = 1.f / red[0];
    uint32_t hp, lp;
    sp16pair(e0 * inv, e1 * inv, hp, lp);
    long long pb = ((long long)blockIdx.y * Sn + row) * (Sn / 2) + tid;
    oh[pb] = hp;
    ol[pb] = lp;
}

// ---------------- fused residual add(+add2) + layernorm (raw + fp16 pairs) ----------------
__global__ void add_ln_kernel(const float* __restrict__ x, const float* __restrict__ a,
                              const float* __restrict__ a2,
                              const float* __restrict__ g, const float* __restrict__ b,
                              float* __restrict__ out,
                              uint32_t* __restrict__ oh, uint32_t* __restrict__ ol) {
    int t = blockIdx.x;
    int tid = threadIdx.x;
    long long base = (long long)t * Dm;
    int c0 = tid * 4;
    float v[4];
#pragma unroll
    for (int i = 0; i < 4; i++) {
        float s = x[base + c0 + i] + a[base + c0 + i];
        if (a2) s += a2[base + c0 + i];
        v[i] = s;
    }
    __shared__ float red[256];
    red[tid] = v[0] + v[1] + v[2] + v[3];
    __syncthreads();
    for (int k = 128; k > 0; k >>= 1) {
        if (tid < k) red[tid] += red[tid + k];
        __syncthreads();
    }
    float mu = red[0] * (1.f / Dm);
    __syncthreads();
    float q = 0.f;
#pragma unroll
    for (int i = 0; i < 4; i++) { float d = v[i] - mu; q += d * d; }
    red[tid] = q;
    __syncthreads();
    for (int k = 128; k > 0; k >>= 1) {
        if (tid < k) red[tid] += red[tid + k];
        __syncthreads();
    }
    float var = red[0] * (1.f / Dm);
    float inv = rsqrtf(var + 1e-5f);
    float o[4];
#pragma unroll
    for (int i = 0; i < 4; i++)
        o[i] = (v[i] - mu) * inv * g[c0 + i] + b[c0 + i];
    *(float4*)&out[base + c0] = make_float4(o[0], o[1], o[2], o[3]);
    long long pb = (long long)t * (Dm / 2) + tid * 2;
    uint32_t hp, lp;
    sp16pair(o[0], o[1], hp, lp);
    oh[pb] = hp;
    ol[pb] = lp;
    sp16pair(o[2], o[3], hp, lp);
    oh[pb + 1] = hp;
    ol[pb + 1] = lp;
}

// ---------------- MoE gating ----------------
__global__ void zero_cnt_kernel(int* c) { if (threadIdx.x < En) c[threadIdx.x] = 0; }

__global__ void gate_route_kernel(const float* __restrict__ logits, float* __restrict__ topw,
                                  int* __restrict__ list, int* __restrict__ cnt) {
    int t = blockIdx.x * blockDim.x + threadIdx.x;
    if (t >= TOK) return;
    float p[En];
    float m = -1e30f;
#pragma unroll
    for (int e = 0; e < En; e++) { p[e] = logits[t * En + e]; m = fmaxf(m, p[e]); }
    float s = 0.f;
#pragma unroll
    for (int e = 0; e < En; e++) { p[e] = expf(p[e] - m); s += p[e]; }
    float invs = 1.f / s;
#pragma unroll
    for (int e = 0; e < En; e++) p[e] *= invs;
    int i0 = 0;
#pragma unroll
    for (int e = 1; e < En; e++) if (p[e] > p[i0]) i0 = e;
    int i1 = (i0 == 0) ? 1 : 0;
#pragma unroll
    for (int e = 0; e < En; e++) if (e != i0 && p[e] > p[i1]) i1 = e;
    float s2 = p[i0] + p[i1];
    topw[t * 2 + 0] = p[i0] / s2;
    topw[t * 2 + 1] = p[i1] / s2;
    int pos = atomicAdd(&cnt[i0], 1);
    list[i0 * TOK + pos] = t * 2 + 0;
    pos = atomicAdd(&cnt[i1], 1);
    list[i1 * TOK + pos] = t * 2 + 1;
}

// ================= host orchestration =================
struct DevPtrs {
    float *x, *y, *lin0, *lin1, *lin2, *sc, *att, *proj, *moe0, *moe1, *gate, *topw;
    uint32_t *xh, *xl, *yh, *yl, *qph, *qpl, *kph, *kpl, *vth, *vtl;
    uint32_t *sph, *spl, *atth, *attl, *h1h, *h1l, *wth, *wtl;
    int *list, *cnt;
};

static void tsp(const float* W, uint32_t* h, uint32_t* l, int K, int N, int batch,
                long long zsrc, long long zdst) {
    dim3 g(N / 32, K / 32, batch);
    tsp_kernel<<<g, dim3(32, 8)>>>(W, h, l, K, N, zsrc, zdst);
}

// plain GEMM: C = Apairs @ Bpairs^T + bias
static void wgemm(const uint32_t* Ah, const uint32_t* Al,
                  const uint32_t* Bh, const uint32_t* Bl,
                  const float* bias, float* C, int M, int N, int K,
                  float alpha = 1.f, int batch = 1, int gridN = -1,
                  long long sA = 0, long long sB = 0, long long sC = 0) {
    if (gridN < 0) gridN = (N + 127) / 128;
    dim3 g(gridN, M / 128, batch);
    hgemm16<0><<<g, 512, SMEM16_BYTES>>>(Ah, Al, Bh, Bl, bias, C,
                                         nullptr, nullptr, nullptr, nullptr, nullptr,
                                         nullptr, nullptr, M, N, K, alpha, sA, sB, sC);
}

static void run_mha(DevPtrs& P, float* xio, uint32_t* xh, uint32_t* xl,
                    const uint32_t* kvh, const uint32_t* kvl,
                    const float* wqkv, const float* bqkv,
                    const float* wo, const float* bo,
                    const float* lng, const float* lnb, int causal) {
    tsp(wqkv, P.wth, P.wtl, Dm, Dm, 3, (long long)Dm * Dm, (long long)Dm * Dm / 2);
    wgemm(xh,  xl,  P.wth,               P.wtl,               bqkv,          P.lin0, TOK, Dm, Dm);
    wgemm(kvh, kvl, P.wth + Dm * Dm / 2, P.wtl + Dm * Dm / 2, bqkv + Dm,     P.lin1, TOK, Dm, Dm);
    wgemm(kvh, kvl, P.wth + Dm * Dm,     P.wtl + Dm * Dm,     bqkv + 2 * Dm, P.lin2, TOK, Dm, Dm);
    int nbp = (TOK * Dm / 2) / 256;
    rope_pair_kernel<<<nbp, 256>>>(P.lin0, P.qph, P.qpl);
    rope_pair_kernel<<<nbp, 256>>>(P.lin1, P.kph, P.kpl);
    v_transpose_kernel<<<dim3(Sn / 64, BH), 256>>>(P.lin2, P.vth, P.vtl);
    // scores = Q @ K^T * scale  (batched over BH)
    wgemm(P.qph, P.qpl, P.kph, P.kpl, nullptr, P.sc, Sn, Sn, HD, 0.125f, BH, -1,
          (long long)Sn * 32, (long long)Sn * 32, (long long)Sn * Sn);
    softmax_pair_kernel<<<dim3(Sn, BH), 256>>>(P.sc, P.sph, P.spl, causal);
    // att = P @ V  (B = V^T [128 rows, 64 valid], single N-tile)
    wgemm(P.sph, P.spl, P.vth, P.vtl, nullptr, P.att, Sn, HD, Sn, 1.f, BH, 1,
          (long long)Sn * (Sn / 2), (long long)128 * (Sn / 2), (long long)Sn * HD);
    perm_back_kernel<<<nbp, 256>>>(P.att, P.atth, P.attl);
    tsp(wo, P.wth, P.wtl, Dm, Dm, 1, 0, 0);
    wgemm(P.atth, P.attl, P.wth, P.wtl, bo, P.proj, TOK, Dm, Dm);
    add_ln_kernel<<<TOK, 256>>>(xio, P.proj, nullptr, lng, lnb, xio, xh, xl);
}

static void run_moe(DevPtrs& P, float* xio, uint32_t* xh, uint32_t* xl,
                    const float* gw, const float* gb,
                    const float* w1, const float* b1, const float* w2, const float* b2,
                    const float* lng, const float* lnb) {
    sgemm_kernel<<<dim3(1, TOK / 64), 256>>>(xio, gw, gb, P.gate, TOK, En, Dm);
    zero_cnt_kernel<<<1, 32>>>(P.cnt);
    gate_route_kernel<<<TOK / 256, 256>>>(P.gate, P.topw, P.list, P.cnt);
    tsp(w1, P.wth, P.wtl, Dm, FF, En, (long long)Dm * FF, (long long)Dm * FF / 2);
    {
        dim3 g(FF / 128, TOK / 128, En);
        hgemm16<1><<<g, 512, SMEM16_BYTES>>>(
            xh, xl, P.wth, P.wtl, b1, nullptr, P.h1h, P.h1l,
            nullptr, nullptr, nullptr, P.list, P.cnt,
            TOK, FF, Dm, 1.f, 0, (long long)Dm * FF / 2, (long long)TOK * FF / 2);
    }
    tsp(w2, P.wth, P.wtl, FF, Dm, En, (long long)FF * Dm, (long long)FF * Dm / 2);
    {
        dim3 g(Dm / 128, TOK / 128, En);
        hgemm16<2><<<g, 512, SMEM16_BYTES>>>(
            P.h1h, P.h1l, P.wth, P.wtl, b2, nullptr, nullptr, nullptr,
            P.moe0, P.moe1, P.topw, P.list, P.cnt,
            TOK, Dm, FF, 1.f, (long long)TOK * FF / 2, (long long)FF * Dm / 2, 0);
    }
    add_ln_kernel<<<TOK, 256>>>(xio, P.moe0, P.moe1, lng, lnb, xio, xh, xl);
}

extern "C" void kernel_launch(void* const* d_in, const int* in_sizes, int n_in,
                              void* d_out, int out_size) {
    (void)in_sizes; (void)n_in; (void)out_size;
    const int*   src           = (const int*)  d_in[0];
    const int*   tgt           = (const int*)  d_in[1];
    const float* emb_src       = (const float*)d_in[2];
    const float* emb_tgt       = (const float*)d_in[3];
    const float* enc_wqkv      = (const float*)d_in[4];
    const float* enc_bqkv      = (const float*)d_in[5];
    const float* enc_wo        = (const float*)d_in[6];
    const float* enc_bo        = (const float*)d_in[7];
    const float* enc_gate_w    = (const float*)d_in[8];
    const float* enc_gate_b    = (const float*)d_in[9];
    const float* enc_w1        = (const float*)d_in[10];
    const float* enc_b1        = (const float*)d_in[11];
    const float* enc_w2        = (const float*)d_in[12];
    const float* enc_b2        = (const float*)d_in[13];
    const float* enc_ln        = (const float*)d_in[14];
    const float* dec_self_wqkv = (const float*)d_in[15];
    const float* dec_self_bqkv = (const float*)d_in[16];
    const float* dec_self_wo   = (const float*)d_in[17];
    const float* dec_self_bo   = (const float*)d_in[18];
    const float* dec_cross_wqkv= (const float*)d_in[19];
    const float* dec_cross_bqkv= (const float*)d_in[20];
    const float* dec_cross_wo  = (const float*)d_in[21];
    const float* dec_cross_bo  = (const float*)d_in[22];
    const float* dec_gate_w    = (const float*)d_in[23];
    const float* dec_gate_b    = (const float*)d_in[24];
    const float* dec_w1        = (const float*)d_in[25];
    const float* dec_b1        = (const float*)d_in[26];
    const float* dec_w2        = (const float*)d_in[27];
    const float* dec_b2        = (const float*)d_in[28];
    const float* dec_ln        = (const float*)d_in[29];
    const float* final_w       = (const float*)d_in[30];
    const float* final_b       = (const float*)d_in[31];
    float* out = (float*)d_out;

    cudaFuncSetAttribute(hgemm16<0>, cudaFuncAttributeMaxDynamicSharedMemorySize, SMEM16_BYTES);
    cudaFuncSetAttribute(hgemm16<1>, cudaFuncAttributeMaxDynamicSharedMemorySize, SMEM16_BYTES);
    cudaFuncSetAttribute(hgemm16<2>, cudaFuncAttributeMaxDynamicSharedMemorySize, SMEM16_BYTES);

    DevPtrs P;
    cudaGetSymbolAddress((void**)&P.x, g_x);
    cudaGetSymbolAddress((void**)&P.y, g_y);
    cudaGetSymbolAddress((void**)&P.xh, g_xh);
    cudaGetSymbolAddress((void**)&P.xl, g_xl);
    cudaGetSymbolAddress((void**)&P.yh, g_yh);
    cudaGetSymbolAddress((void**)&P.yl, g_yl);
    cudaGetSymbolAddress((void**)&P.lin0, g_lin0);
    cudaGetSymbolAddress((void**)&P.lin1, g_lin1);
    cudaGetSymbolAddress((void**)&P.lin2, g_lin2);
    cudaGetSymbolAddress((void**)&P.qph, g_qph);
    cudaGetSymbolAddress((void**)&P.qpl, g_qpl);
    cudaGetSymbolAddress((void**)&P.kph, g_kph);
    cudaGetSymbolAddress((void**)&P.kpl, g_kpl);
    cudaGetSymbolAddress((void**)&P.vth, g_vth);
    cudaGetSymbolAddress((void**)&P.vtl, g_vtl);
    cudaGetSymbolAddress((void**)&P.sc, g_sc);
    cudaGetSymbolAddress((void**)&P.sph, g_sph);
    cudaGetSymbolAddress((void**)&P.spl, g_spl);
    cudaGetSymbolAddress((void**)&P.att, g_att);
    cudaGetSymbolAddress((void**)&P.atth, g_atth);
    cudaGetSymbolAddress((void**)&P.attl, g_attl);
    cudaGetSymbolAddress((void**)&P.proj, g_proj);
    cudaGetSymbolAddress((void**)&P.h1h, g_h1h);
    cudaGetSymbolAddress((void**)&P.h1l, g_h1l);
    cudaGetSymbolAddress((void**)&P.moe0, g_moe0);
    cudaGetSymbolAddress((void**)&P.moe1, g_moe1);
    cudaGetSymbolAddress((void**)&P.gate, g_gate);
    cudaGetSymbolAddress((void**)&P.topw, g_topw);
    cudaGetSymbolAddress((void**)&P.list, g_list);
    cudaGetSymbolAddress((void**)&P.cnt, g_cnt);
    cudaGetSymbolAddress((void**)&P.wth, g_wth);
    cudaGetSymbolAddress((void**)&P.wtl, g_wtl);

    rope_init_kernel<<<(Sn * HD) / 256, 256>>>();

    // ---------- encoder ----------
    embed_kernel<<<(TOK * Dm / 2) / 256, 256>>>(src, emb_src, P.x, P.xh, P.xl);
    for (int l = 0; l < Ln; l++) {
        run_mha(P, P.x, P.xh, P.xl, P.xh, P.xl,
                enc_wqkv + (long long)l * 3 * Dm * Dm, enc_bqkv + l * 3 * Dm,
                enc_wo + (long long)l * Dm * Dm, enc_bo + l * Dm,
                enc_ln + ((l * 2 + 0) * 2 + 0) * Dm, enc_ln + ((l * 2 + 0) * 2 + 1) * Dm, 0);
        run_moe(P, P.x, P.xh, P.xl,
                enc_gate_w + l * Dm * En, enc_gate_b + l * En,
                enc_w1 + (long long)l * En * Dm * FF, enc_b1 + l * En * FF,
                enc_w2 + (long long)l * En * FF * Dm, enc_b2 + l * En * Dm,
                enc_ln + ((l * 2 + 1) * 2 + 0) * Dm, enc_ln + ((l * 2 + 1) * 2 + 1) * Dm);
    }

    // ---------- decoder ----------
    embed_kernel<<<(TOK * Dm / 2) / 256, 256>>>(tgt, emb_tgt, P.y, P.yh, P.yl);
    for (int l = 0; l < Ln; l++) {
        run_mha(P, P.y, P.yh, P.yl, P.yh, P.yl,
                dec_self_wqkv + (long long)l * 3 * Dm * Dm, dec_self_bqkv + l * 3 * Dm,
                dec_self_wo + (long long)l * Dm * Dm, dec_self_bo + l * Dm,
                dec_ln + ((l * 3 + 0) * 2 + 0) * Dm, dec_ln + ((l * 3 + 0) * 2 + 1) * Dm, 1);
        run_mha(P, P.y, P.yh, P.yl, P.xh, P.xl,
                dec_cross_wqkv + (long long)l * 3 * Dm * Dm, dec_cross_bqkv + l * 3 * Dm,
                dec_cross_wo + (long long)l * Dm * Dm, dec_cross_bo + l * Dm,
                dec_ln + ((l * 3 + 1) * 2 + 0) * Dm, dec_ln + ((l * 3 + 1) * 2 + 1) * Dm, 0);
        run_moe(P, P.y, P.yh, P.yl,
                dec_gate_w + l * Dm * En, dec_gate_b + l * En,
                dec_w1 + (long long)l * En * Dm * FF, dec_b1 + l * En * FF,
                dec_w2 + (long long)l * En * FF * Dm, dec_b2 + l * En * Dm,
                dec_ln + ((l * 3 + 2) * 2 + 0) * Dm, dec_ln + ((l * 3 + 2) * 2 + 1) * Dm);
    }

    // ---------- final projection ----------
    tsp(final_w, P.wth, P.wtl, Dm, VT, 1, 0, 0);
    wgemm(P.yh, P.yl, P.wth, P.wtl, final_b, out, TOK, VT, Dm);
}

// round 11
// speedup vs baseline: 1.5018x; 1.0720x over previous
#include <cuda_runtime.h>
#include <cuda_fp16.h>
#include <math.h>
#include <stdint.h>

// ---------------- problem constants ----------------
#define Bn   4
#define Sn   512
#define Dm   1024
#define Hn   16
#define HD   64
#define En   8
#define FF   2048
#define Ln   2
#define VT   32000
#define TOK  (Bn*Sn)      // 2048 tokens
#define BH   (Bn*Hn)      // 64 attention batches

// ---- fp16-pair GEMM tiling: 256 thr, block 128x64, KT=32 (16 pairs), 2 CTA/SM ----
#define KPT  16           // u32 pairs per K-tile
#define PST  20           // smem stride (u32)
#define PASZ (128*PST)    // A array: 2560 u32
#define PBSZ (64*PST)     // B array: 1280 u32
#define STG16 (2*PASZ + 2*PBSZ)   // 7680 u32 = 30720 B per stage
#define NSTAGE 3
#define SMEM16_BYTES (NSTAGE*STG16*4)   // 92160

// ---------------- device scratch (no allocations allowed) ----------------
__device__ float    g_x[TOK*Dm];
__device__ float    g_y[TOK*Dm];
__device__ uint32_t g_xh[TOK*Dm/2], g_xl[TOK*Dm/2];          // fp16 pairs
__device__ uint32_t g_yh[TOK*Dm/2], g_yl[TOK*Dm/2];
__device__ float    g_lin0[TOK*Dm];
__device__ float    g_lin1[TOK*Dm];
__device__ float    g_lin2[TOK*Dm];
__device__ uint32_t g_qph[TOK*Dm/2], g_qpl[TOK*Dm/2];        // Q pairs [bh*512+s][32]
__device__ uint32_t g_kph[TOK*Dm/2], g_kpl[TOK*Dm/2];        // K pairs
__device__ uint32_t g_vth[BH*64*(Sn/2)], g_vtl[BH*64*(Sn/2)];  // V^T pairs [bh][64 d][256]
__device__ float    g_sc[(size_t)BH*Sn*Sn];
__device__ uint32_t g_sph[(size_t)BH*Sn*(Sn/2)], g_spl[(size_t)BH*Sn*(Sn/2)];  // prob pairs
__device__ float    g_att[TOK*Dm];
__device__ uint32_t g_atth[TOK*Dm/2], g_attl[TOK*Dm/2];      // fp16 pairs
__device__ float    g_proj[TOK*Dm];
__device__ uint32_t g_h1h[(size_t)En*TOK*FF/2], g_h1l[(size_t)En*TOK*FF/2];
__device__ float    g_moe0[TOK*Dm];
__device__ float    g_moe1[TOK*Dm];
__device__ float    g_gate[TOK*En];
__device__ float    g_topw[TOK*2];
__device__ int      g_list[En*TOK];
__device__ int      g_cnt[En];
__device__ float    g_cos[Sn*HD];
__device__ float    g_sin[Sn*HD];
__device__ uint32_t g_wth[16777216], g_wtl[16777216];        // weight pairs [N][K/2]

// ---------------- helpers ----------------
__device__ __forceinline__ void sp16pair(float v0, float v1, uint32_t& hp, uint32_t& lp) {
    __half h0 = __float2half_rn(v0);
    __half h1 = __float2half_rn(v1);
    __half l0 = __float2half_rn((v0 - __half2float(h0)) * 2048.f);
    __half l1 = __float2half_rn((v1 - __half2float(h1)) * 2048.f);
    hp = (uint32_t)__half_as_ushort(h0) | ((uint32_t)__half_as_ushort(h1) << 16);
    lp = (uint32_t)__half_as_ushort(l0) | ((uint32_t)__half_as_ushort(l1) << 16);
}
__device__ __forceinline__ uint32_t smem_u32(const void* p) {
    return (uint32_t)__cvta_generic_to_shared(p);
}
__device__ __forceinline__ void cp16(uint32_t dst, const void* src) {
    asm volatile("cp.async.cg.shared.global [%0], [%1], 16;" :: "r"(dst), "l"(src));
}
#define CP_COMMIT() asm volatile("cp.async.commit_group;")
#define CP_WAITG(n) asm volatile("cp.async.wait_group %0;" :: "n"(n))

__device__ __forceinline__ void mma_f16(float* c, const uint32_t* a, const uint32_t* b) {
    asm volatile(
        "mma.sync.aligned.m16n8k16.row.col.f32.f16.f16.f32 "
        "{%0,%1,%2,%3}, {%4,%5,%6,%7}, {%8,%9}, {%0,%1,%2,%3};"
        : "+f"(c[0]), "+f"(c[1]), "+f"(c[2]), "+f"(c[3])
        : "r"(a[0]), "r"(a[1]), "r"(a[2]), "r"(a[3]), "r"(b[0]), "r"(b[1]));
}
#define LDSM4(r0, r1, r2, r3, addr) \
    asm volatile("ldmatrix.sync.aligned.m8n8.x4.shared.b16 {%0,%1,%2,%3}, [%4];" \
                 : "=r"(r0), "=r"(r1), "=r"(r2), "=r"(r3) : "r"(addr))

// =====================================================================
// fp16x3 GEMM: acc = A @ B^T, A [M][K/2] pairs, B [N][K/2] pairs.
// result = (accM + accC/2048)*alpha (+bias).
// 256 thr, 8 warps (4m x 2n), block 128x64, 3-stage cp.async, 2 CTA/SM.
// MODE0: plain fp32 out. MODE1: gather+relu+pack. MODE2: scatter*topw.
// M%128==0, K%32==0. B rows bn..bn+63 must be readable.
// =====================================================================
template<int MODE>
__global__ void __launch_bounds__(256, 2) hgemm16(
    const uint32_t* __restrict__ Ah, const uint32_t* __restrict__ Al,
    const uint32_t* __restrict__ Bh, const uint32_t* __restrict__ Bl,
    const float* __restrict__ bias, float* __restrict__ C,
    uint32_t* __restrict__ Oh, uint32_t* __restrict__ Ol,
    float* __restrict__ out0, float* __restrict__ out1, const float* __restrict__ topw,
    const int* __restrict__ list, const int* __restrict__ cnt,
    int M, int Nstore, int K, float alpha,
    long long sAz, long long sBz, long long sCz)
{
    const int z = blockIdx.z;
    const int bm = blockIdx.y * 128, bn = blockIdx.x * 64;
    int nrows = M;
    const int* lst = nullptr;
    if (MODE >= 1) {
        nrows = cnt[z];
        if (bm >= nrows) return;
        lst = list + z * TOK;
        bias += (long long)z * Nstore;
    }
    Ah += (long long)z * sAz;  Al += (long long)z * sAz;
    Bh += (long long)z * sBz;  Bl += (long long)z * sBz;
    if (MODE == 0) C += (long long)z * sCz;
    if (MODE == 1) { Oh += (long long)z * sCz; Ol += (long long)z * sCz; }

    extern __shared__ uint32_t dsm[];
    __shared__ int ents[128];
    const int tid  = threadIdx.x;
    const int lane = tid & 31;
    const int warp = tid >> 5;
    const int wm = warp >> 1, wn = warp & 1;
    const int g  = lane >> 2, t4 = lane & 3;
    const int lrow = lane & 7, seg = lane >> 3;
    const int Kp = K >> 1;

    if (MODE >= 1 && tid < 128) {
        int gr = bm + tid;
        ents[tid] = (gr < nrows) ? lst[gr] : -1;
    }
    __syncthreads();

    float accM[2][4][4], accC[2][4][4];
#pragma unroll
    for (int i = 0; i < 2; i++)
#pragma unroll
        for (int j = 0; j < 4; j++)
#pragma unroll
            for (int q = 0; q < 4; q++) { accM[i][j][q] = 0.f; accC[i][j][q] = 0.f; }

    // A loader rows (two iterations) and B loader row
    long long arow[2];
#pragma unroll
    for (int i = 0; i < 2; i++) {
        int r = (tid + i * 256) >> 2;
        if (MODE == 1) {
            int e = ents[r];
            arow[i] = (e >= 0) ? (long long)(e >> 1) : 0;
        } else {
            arow[i] = bm + r;
        }
    }
    const int chA = tid & 3;
    const long long brow = bn + (tid >> 2 & 63);
    const int chB = tid & 3;

    auto issue_tile = [&](int kt) {
        uint32_t* AhS = dsm + (kt % NSTAGE) * STG16;
        uint32_t* AlS = AhS + PASZ;
        uint32_t* BhS = AlS + PASZ;
        uint32_t* BlS = BhS + PBSZ;
        const long long kpbase = (long long)kt * KPT;
#pragma unroll
        for (int i = 0; i < 2; i++) {
            int r = (tid + i * 256) >> 2;
            const long long kp0 = kpbase + chA * 4;
            const uint32_t d = r * PST + chA * 4;
            cp16(smem_u32(&AhS[d]), Ah + arow[i] * Kp + kp0);
            cp16(smem_u32(&AlS[d]), Al + arow[i] * Kp + kp0);
        }
        {
            const long long kp0 = kpbase + chB * 4;
            const uint32_t d = (tid >> 2) * PST + chB * 4;
            cp16(smem_u32(&BhS[d]), Bh + brow * Kp + kp0);
            cp16(smem_u32(&BlS[d]), Bl + brow * Kp + kp0);
        }
        CP_COMMIT();
    };

    const int nk = K / 32;
    issue_tile(0);
    if (nk > 1) issue_tile(1);
    for (int kt = 0; kt < nk; kt++) {
        if (kt + 2 < nk)      { issue_tile(kt + 2); CP_WAITG(2); }
        else if (kt + 1 < nk) { CP_WAITG(1); }
        else                  { CP_WAITG(0); }
        __syncthreads();
        const uint32_t* AhS = dsm + (kt % NSTAGE) * STG16;
        const uint32_t* AlS = AhS + PASZ;
        const uint32_t* BhS = AlS + PASZ;
        const uint32_t* BlS = BhS + PBSZ;
        const int moff = wm * 32, noff = wn * 32;
#pragma unroll
        for (int ks = 0; ks < 2; ks++) {
            const int kb = ks * 8;
            uint32_t aH[2][4], aL[2][4], bH[4][2], bL[4][2];
            const int akc = kb + ((seg >> 1) << 2);
#pragma unroll
            for (int mt = 0; mt < 2; mt++) {
                int mrow = moff + mt * 16 + lrow + ((seg & 1) << 3);
                LDSM4(aH[mt][0], aH[mt][1], aH[mt][2], aH[mt][3],
                      smem_u32(&AhS[mrow * PST + akc]));
                LDSM4(aL[mt][0], aL[mt][1], aL[mt][2], aL[mt][3],
                      smem_u32(&AlS[mrow * PST + akc]));
            }
            const int bkc = kb + ((seg & 1) << 2);
#pragma unroll
            for (int nt2 = 0; nt2 < 2; nt2++) {
                int nrow = noff + (nt2 * 2 + (seg >> 1)) * 8 + lrow;
                LDSM4(bH[nt2*2][0], bH[nt2*2][1], bH[nt2*2+1][0], bH[nt2*2+1][1],
                      smem_u32(&BhS[nrow * PST + bkc]));
                LDSM4(bL[nt2*2][0], bL[nt2*2][1], bL[nt2*2+1][0], bL[nt2*2+1][1],
                      smem_u32(&BlS[nrow * PST + bkc]));
            }
#pragma unroll
            for (int mt = 0; mt < 2; mt++)
#pragma unroll
                for (int nt = 0; nt < 4; nt++) {
                    mma_f16(accM[mt][nt], aH[mt], bH[nt]);
                    mma_f16(accC[mt][nt], aH[mt], bL[nt]);
                    mma_f16(accC[mt][nt], aL[mt], bH[nt]);
                }
        }
        __syncthreads();
    }

    // ---- epilogue ----
    const float s = 1.f / 2048.f;
#pragma unroll
    for (int mt = 0; mt < 2; mt++) {
        int lr = wm * 32 + mt * 16 + g;
#pragma unroll
        for (int nt = 0; nt < 4; nt++) {
            int n0 = bn + wn * 32 + nt * 8 + t4 * 2;
            if (n0 >= Nstore) continue;
            float b0v = bias ? bias[n0] : 0.f;
            float b1v = bias ? bias[n0 + 1] : 0.f;
            float v0 = (accM[mt][nt][0] + accC[mt][nt][0] * s) * alpha + b0v;
            float v1 = (accM[mt][nt][1] + accC[mt][nt][1] * s) * alpha + b1v;
            float v2 = (accM[mt][nt][2] + accC[mt][nt][2] * s) * alpha + b0v;
            float v3 = (accM[mt][nt][3] + accC[mt][nt][3] * s) * alpha + b1v;
            if (MODE == 0) {
                long long m0 = bm + lr;
                C[m0 * Nstore + n0] = v0;
                C[m0 * Nstore + n0 + 1] = v1;
                C[(m0 + 8) * Nstore + n0] = v2;
                C[(m0 + 8) * Nstore + n0 + 1] = v3;
            } else if (MODE == 1) {
                if (bm + lr < nrows) {
                    uint32_t hp, lp;
                    sp16pair(fmaxf(v0, 0.f), fmaxf(v1, 0.f), hp, lp);
                    size_t o = (size_t)(bm + lr) * (Nstore >> 1) + (n0 >> 1);
                    Oh[o] = hp; Ol[o] = lp;
                }
                if (bm + lr + 8 < nrows) {
                    uint32_t hp, lp;
                    sp16pair(fmaxf(v2, 0.f), fmaxf(v3, 0.f), hp, lp);
                    size_t o = (size_t)(bm + lr + 8) * (Nstore >> 1) + (n0 >> 1);
                    Oh[o] = hp; Ol[o] = lp;
                }
            } else {
                int e0 = ents[lr], e2 = ents[lr + 8];
                if (e0 >= 0) {
                    float w = topw[e0];
                    float* o = (e0 & 1) ? out1 : out0;
                    long long t = (long long)(e0 >> 1) * Nstore;
                    o[t + n0] = w * v0;
                    o[t + n0 + 1] = w * v1;
                }
                if (e2 >= 0) {
                    float w = topw[e2];
                    float* o = (e2 & 1) ? out1 : out0;
                    long long t = (long long)(e2 >> 1) * Nstore;
                    o[t + n0] = w * v2;
                    o[t + n0 + 1] = w * v3;
                }
            }
        }
    }
}

// =====================================================================
// transpose+split+pack: W [K,N] fp32 -> Wh/Wl [N][K/2] fp16-pair u32.
// =====================================================================
__global__ void tsp_kernel(const float* __restrict__ W,
                           uint32_t* __restrict__ h, uint32_t* __restrict__ l,
                           int K, int N, long long zsrc, long long zdst) {
    __shared__ float t[32][33];
    const long long so = (long long)blockIdx.z * zsrc;
    const long long dz = (long long)blockIdx.z * zdst;
    const int bk = blockIdx.y * 32, bnn = blockIdx.x * 32;
    const int tx = threadIdx.x, ty = threadIdx.y;
#pragma unroll
    for (int r = 0; r < 4; r++)
        t[ty + r * 8][tx] = W[so + (long long)(bk + ty + r * 8) * N + bnn + tx];
    __syncthreads();
    const int Kp = K >> 1;
#pragma unroll
    for (int r = 0; r < 2; r++) {
        int kpl = ty * 2 + r;
        float v0 = t[2 * kpl][tx];
        float v1 = t[2 * kpl + 1][tx];
        uint32_t hp, lp;
        sp16pair(v0, v1, hp, lp);
        long long o = dz + (long long)(bnn + tx) * Kp + (bk >> 1) + kpl;
        h[o] = hp;
        l[o] = lp;
    }
}

// ---------------- RoPE tables ----------------
__global__ void rope_init_kernel() {
    int idx = blockIdx.x * blockDim.x + threadIdx.x;
    if (idx >= Sn * HD) return;
    int s = idx >> 6;
    int j = idx & 63;
    int jj = j & 31;
    double inv = pow(10000.0, -((double)(2 * jj)) / 64.0);
    double ang = (double)s * inv;
    g_cos[idx] = (float)cos(ang);
    g_sin[idx] = (float)sin(ang);
}

// ---------------- embedding gather (raw + fp16 pairs) ----------------
__global__ void embed_kernel(const int* __restrict__ ids, const float* __restrict__ table,
                             float* __restrict__ out,
                             uint32_t* __restrict__ oh, uint32_t* __restrict__ ol) {
    int p = blockIdx.x * blockDim.x + threadIdx.x;
    int t = p >> 9;
    int d2 = p & 511;
    const float2 v = *(const float2*)&table[(long long)ids[t] * Dm + 2 * d2];
    *(float2*)&out[(long long)t * Dm + 2 * d2] = v;
    uint32_t hp, lp;
    sp16pair(v.x, v.y, hp, lp);
    oh[p] = hp;
    ol[p] = lp;
}

// ---------------- fp32 scalar SGEMM (tiny gate GEMM; exact routing) ----------------
__global__ void sgemm_kernel(const float* __restrict__ A, const float* __restrict__ W,
                             const float* __restrict__ bias, float* __restrict__ C,
                             int M, int N, int K) {
    const int tid = threadIdx.x;
    const int bm = blockIdx.y * 64, bn = blockIdx.x * 64;
    __shared__ float As[16][68];
    __shared__ float Ws[16][68];
    float acc[4][4] = {};
    const int ty = tid >> 4, tx = tid & 15;
    for (int k0 = 0; k0 < K; k0 += 16) {
#pragma unroll
        for (int i = 0; i < 4; i++) {
            int e = tid + i * 256;
            int r = e >> 4, kk = e & 15;
            int gr = bm + r, gk = k0 + kk;
            As[kk][r] = (gr < M && gk < K) ? A[(long long)gr * K + gk] : 0.f;
        }
#pragma unroll
        for (int i = 0; i < 4; i++) {
            int e = tid + i * 256;
            int kk = e >> 6, c = e & 63;
            int gk = k0 + kk, gc = bn + c;
            Ws[kk][c] = (gk < K && gc < N) ? W[(long long)gk * N + gc] : 0.f;
        }
        __syncthreads();
#pragma unroll
        for (int kk = 0; kk < 16; kk++) {
            float4 a4 = *(const float4*)&As[kk][ty * 4];
            float4 b4 = *(const float4*)&Ws[kk][tx * 4];
            float av[4] = {a4.x, a4.y, a4.z, a4.w};
            float bv[4] = {b4.x, b4.y, b4.z, b4.w};
#pragma unroll
            for (int i = 0; i < 4; i++)
#pragma unroll
                for (int j = 0; j < 4; j++) acc[i][j] += av[i] * bv[j];
        }
        __syncthreads();
    }
#pragma unroll
    for (int i = 0; i < 4; i++) {
        int r = bm + ty * 4 + i;
        if (r >= M) continue;
#pragma unroll
        for (int j = 0; j < 4; j++) {
            int c = bn + tx * 4 + j;
            if (c >= N) continue;
            C[(long long)r * N + c] = acc[i][j] + (bias ? bias[c] : 0.f);
        }
    }
}

// ---------------- RoPE + permute, fp16 pairs out: [bh*512+s][32 hd-pairs] ----------------
__global__ void rope_pair_kernel(const float* __restrict__ lin,
                                 uint32_t* __restrict__ oh, uint32_t* __restrict__ ol) {
    int idx = blockIdx.x * blockDim.x + threadIdx.x;   // TOK*Dm/2
    int t = idx >> 9;
    int p = idx & 511;
    int h = p >> 5;
    int d2 = p & 31;
    int b = t >> 9;
    int s = t & 511;
    int d0 = 2 * d2, d1 = d0 + 1;
    float v0 = lin[(long long)t * Dm + h * 64 + d0];
    float v1 = lin[(long long)t * Dm + h * 64 + d1];
    float o0, o1;
    {
        float other = (d0 < 32) ? -lin[(long long)t * Dm + h * 64 + d0 + 32]
                                :  lin[(long long)t * Dm + h * 64 + d0 - 32];
        o0 = v0 * g_cos[s * 64 + d0] + other * g_sin[s * 64 + d0];
    }
    {
        float other = (d1 < 32) ? -lin[(long long)t * Dm + h * 64 + d1 + 32]
                                :  lin[(long long)t * Dm + h * 64 + d1 - 32];
        o1 = v1 * g_cos[s * 64 + d1] + other * g_sin[s * 64 + d1];
    }
    long long oi = ((long long)(b * Hn + h) * Sn + s) * 32 + d2;
    uint32_t hp, lp;
    sp16pair(o0, o1, hp, lp);
    oh[oi] = hp;
    ol[oi] = lp;
}

// ---------------- V transpose: lin [t][h*64+d] -> vt [bh][d][s-pairs] (64 rows) ----------------
__global__ void v_transpose_kernel(const float* __restrict__ lin,
                                   uint32_t* __restrict__ oh, uint32_t* __restrict__ ol) {
    __shared__ float sm[64][65];
    const int s0 = blockIdx.x * 64;
    const int bh = blockIdx.y;
    const int b = bh >> 4, h = bh & 15;
    const int tid = threadIdx.x;
    for (int i = tid; i < 64 * 64; i += 256) {
        int si = i >> 6, d = i & 63;
        sm[si][d] = lin[(long long)(b * Sn + s0 + si) * Dm + h * 64 + d];
    }
    __syncthreads();
    for (int i = tid; i < 32 * 64; i += 256) {
        int d = i >> 5, spi = i & 31;
        float v0 = sm[2 * spi][d];
        float v1 = sm[2 * spi + 1][d];
        uint32_t hp, lp;
        sp16pair(v0, v1, hp, lp);
        long long o = ((long long)bh * 64 + d) * (Sn / 2) + (s0 >> 1) + spi;
        oh[o] = hp;
        ol[o] = lp;
    }
}

// ---------------- [b,h,s,hd] -> [tok][Dm/2] pairs ----------------
__global__ void perm_back_kernel(const float* __restrict__ att,
                                 uint32_t* __restrict__ oh, uint32_t* __restrict__ ol) {
    int idx = blockIdx.x * blockDim.x + threadIdx.x;   // TOK*Dm/2 pairs
    int d2 = idx & 31;
    int s = (idx >> 5) & 511;
    int h = (idx >> 14) & 15;
    int b = idx >> 18;
    const float2 v = *(const float2*)&att[(((long long)(b * Hn + h) * Sn + s) * HD) + 2 * d2];
    long long oi = (long long)(b * Sn + s) * (Dm / 2) + h * 32 + d2;
    uint32_t hp, lp;
    sp16pair(v.x, v.y, hp, lp);
    oh[oi] = hp;
    ol[oi] = lp;
}

// ---------------- row softmax (fp16 pairs out) ----------------
__global__ void softmax_pair_kernel(const float* __restrict__ sc,
                                    uint32_t* __restrict__ oh, uint32_t* __restrict__ ol,
                                    int causal) {
    int row = blockIdx.x;
    long long base = ((long long)blockIdx.y * Sn + row) * Sn;
    int tid = threadIdx.x;
    float v0 = sc[base + 2 * tid];
    float v1 = sc[base + 2 * tid + 1];
    if (causal) {
        if (2 * tid > row) v0 = -1e9f;
        if (2 * tid + 1 > row) v1 = -1e9f;
    }
    __shared__ float red[256];
    float m = fmaxf(v0, v1);
    red[tid] = m;
    __syncthreads();
    for (int s = 128; s > 0; s >>= 1) {
        if (tid < s) red[tid] = fmaxf(red[tid], red[tid + s]);
        __syncthreads();
    }
    m = red[0];
    __syncthreads();
    float e0 = expf(v0 - m), e1 = expf(v1 - m);
    red[tid] = e0 + e1;
    __syncthreads();
    for (int s = 128; s > 0; s >>= 1) {
        if (tid < s) red[tid] += red[tid + s];
        __syncthreads();
    }
    float inv = 1.f / red[0];
    uint32_t hp, lp;
    sp16pair(e0 * inv, e1 * inv, hp, lp);
    long long pb = ((long long)blockIdx.y * Sn + row) * (Sn / 2) + tid;
    oh[pb] = hp;
    ol[pb] = lp;
}

// ---------------- fused residual add(+add2) + layernorm (raw + fp16 pairs) ----------------
__global__ void add_ln_kernel(const float* __restrict__ x, const float* __restrict__ a,
                              const float* __restrict__ a2,
                              const float* __restrict__ g, const float* __restrict__ b,
                              float* __restrict__ out,
                              uint32_t* __restrict__ oh, uint32_t* __restrict__ ol) {
    int t = blockIdx.x;
    int tid = threadIdx.x;
    long long base = (long long)t * Dm;
    int c0 = tid * 4;
    float v[4];
#pragma unroll
    for (int i = 0; i < 4; i++) {
        float s = x[base + c0 + i] + a[base + c0 + i];
        if (a2) s += a2[base + c0 + i];
        v[i] = s;
    }
    __shared__ float red[256];
    red[tid] = v[0] + v[1] + v[2] + v[3];
    __syncthreads();
    for (int k = 128; k > 0; k >>= 1) {
        if (tid < k) red[tid] += red[tid + k];
        __syncthreads();
    }
    float mu = red[0] * (1.f / Dm);
    __syncthreads();
    float q = 0.f;
#pragma unroll
    for (int i = 0; i < 4; i++) { float d = v[i] - mu; q += d * d; }
    red[tid] = q;
    __syncthreads();
    for (int k = 128; k > 0; k >>= 1) {
        if (tid < k) red[tid] += red[tid + k];
        __syncthreads();
    }
    float var = red[0] * (1.f / Dm);
    float inv = rsqrtf(var + 1e-5f);
    float o[4];
#pragma unroll
    for (int i = 0; i < 4; i++)
        o[i] = (v[i] - mu) * inv * g[c0 + i] + b[c0 + i];
    *(float4*)&out[base + c0] = make_float4(o[0], o[1], o[2], o[3]);
    long long pb = (long long)t * (Dm / 2) + tid * 2;
    uint32_t hp, lp;
    sp16pair(o[0], o[1], hp, lp);
    oh[pb] = hp;
    ol[pb] = lp;
    sp16pair(o[2], o[3], hp, lp);
    oh[pb + 1] = hp;
    ol[pb + 1] = lp;
}

// ---------------- MoE gating ----------------
__global__ void zero_cnt_kernel(int* c) { if (threadIdx.x < En) c[threadIdx.x] = 0; }

__global__ void gate_route_kernel(const float* __restrict__ logits, float* __restrict__ topw,
                                  int* __restrict__ list, int* __restrict__ cnt) {
    int t = blockIdx.x * blockDim.x + threadIdx.x;
    if (t >= TOK) return;
    float p[En];
    float m = -1e30f;
#pragma unroll
    for (int e = 0; e < En; e++) { p[e] = logits[t * En + e]; m = fmaxf(m, p[e]); }
    float s = 0.f;
#pragma unroll
    for (int e = 0; e < En; e++) { p[e] = expf(p[e] - m); s += p[e]; }
    float invs = 1.f / s;
#pragma unroll
    for (int e = 0; e < En; e++) p[e] *= invs;
    int i0 = 0;
#pragma unroll
    for (int e = 1; e < En; e++) if (p[e] > p[i0]) i0 = e;
    int i1 = (i0 == 0) ? 1 : 0;
#pragma unroll
    for (int e = 0; e < En; e++) if (e != i0 && p[e] > p[i1]) i1 = e;
    float s2 = p[i0] + p[i1];
    topw[t * 2 + 0] = p[i0] / s2;
    topw[t * 2 + 1] = p[i1] / s2;
    int pos = atomicAdd(&cnt[i0], 1);
    list[i0 * TOK + pos] = t * 2 + 0;
    pos = atomicAdd(&cnt[i1], 1);
    list[i1 * TOK + pos] = t * 2 + 1;
}

// ================= host orchestration =================
struct DevPtrs {
    float *x, *y, *lin0, *lin1, *lin2, *sc, *att, *proj, *moe0, *moe1, *gate, *topw;
    uint32_t *xh, *xl, *yh, *yl, *qph, *qpl, *kph, *kpl, *vth, *vtl;
    uint32_t *sph, *spl, *atth, *attl, *h1h, *h1l, *wth, *wtl;
    int *list, *cnt;
};

static void tsp(const float* W, uint32_t* h, uint32_t* l, int K, int N, int batch,
                long long zsrc, long long zdst) {
    dim3 g(N / 32, K / 32, batch);
    tsp_kernel<<<g, dim3(32, 8)>>>(W, h, l, K, N, zsrc, zdst);
}

// plain GEMM: C = Apairs @ Bpairs^T + bias
static void wgemm(const uint32_t* Ah, const uint32_t* Al,
                  const uint32_t* Bh, const uint32_t* Bl,
                  const float* bias, float* C, int M, int N, int K,
                  float alpha = 1.f, int batch = 1, int gridN = -1,
                  long long sA = 0, long long sB = 0, long long sC = 0) {
    if (gridN < 0) gridN = (N + 63) / 64;
    dim3 g(gridN, M / 128, batch);
    hgemm16<0><<<g, 256, SMEM16_BYTES>>>(Ah, Al, Bh, Bl, bias, C,
                                         nullptr, nullptr, nullptr, nullptr, nullptr,
                                         nullptr, nullptr, M, N, K, alpha, sA, sB, sC);
}

static void run_mha(DevPtrs& P, float* xio, uint32_t* xh, uint32_t* xl,
                    const uint32_t* kvh, const uint32_t* kvl,
                    const float* wqkv, const float* bqkv,
                    const float* wo, const float* bo,
                    const float* lng, const float* lnb, int causal) {
    tsp(wqkv, P.wth, P.wtl, Dm, Dm, 3, (long long)Dm * Dm, (long long)Dm * Dm / 2);
    wgemm(xh,  xl,  P.wth,               P.wtl,               bqkv,          P.lin0, TOK, Dm, Dm);
    wgemm(kvh, kvl, P.wth + Dm * Dm / 2, P.wtl + Dm * Dm / 2, bqkv + Dm,     P.lin1, TOK, Dm, Dm);
    wgemm(kvh, kvl, P.wth + Dm * Dm,     P.wtl + Dm * Dm,     bqkv + 2 * Dm, P.lin2, TOK, Dm, Dm);
    int nbp = (TOK * Dm / 2) / 256;
    rope_pair_kernel<<<nbp, 256>>>(P.lin0, P.qph, P.qpl);
    rope_pair_kernel<<<nbp, 256>>>(P.lin1, P.kph, P.kpl);
    v_transpose_kernel<<<dim3(Sn / 64, BH), 256>>>(P.lin2, P.vth, P.vtl);
    // scores = Q @ K^T * scale  (batched over BH)
    wgemm(P.qph, P.qpl, P.kph, P.kpl, nullptr, P.sc, Sn, Sn, HD, 0.125f, BH, -1,
          (long long)Sn * 32, (long long)Sn * 32, (long long)Sn * Sn);
    softmax_pair_kernel<<<dim3(Sn, BH), 256>>>(P.sc, P.sph, P.spl, causal);
    // att = P @ V  (B = V^T, 64 rows, exact single N-tile)
    wgemm(P.sph, P.spl, P.vth, P.vtl, nullptr, P.att, Sn, HD, Sn, 1.f, BH, 1,
          (long long)Sn * (Sn / 2), (long long)64 * (Sn / 2), (long long)Sn * HD);
    perm_back_kernel<<<nbp, 256>>>(P.att, P.atth, P.attl);
    tsp(wo, P.wth, P.wtl, Dm, Dm, 1, 0, 0);
    wgemm(P.atth, P.attl, P.wth, P.wtl, bo, P.proj, TOK, Dm, Dm);
    add_ln_kernel<<<TOK, 256>>>(xio, P.proj, nullptr, lng, lnb, xio, xh, xl);
}

static void run_moe(DevPtrs& P, float* xio, uint32_t* xh, uint32_t* xl,
                    const float* gw, const float* gb,
                    const float* w1, const float* b1, const float* w2, const float* b2,
                    const float* lng, const float* lnb) {
    sgemm_kernel<<<dim3(1, TOK / 64), 256>>>(xio, gw, gb, P.gate, TOK, En, Dm);
    zero_cnt_kernel<<<1, 32>>>(P.cnt);
    gate_route_kernel<<<TOK / 256, 256>>>(P.gate, P.topw, P.list, P.cnt);
    tsp(w1, P.wth, P.wtl, Dm, FF, En, (long long)Dm * FF, (long long)Dm * FF / 2);
    {
        dim3 g(FF / 64, TOK / 128, En);
        hgemm16<1><<<g, 256, SMEM16_BYTES>>>(
            xh, xl, P.wth, P.wtl, b1, nullptr, P.h1h, P.h1l,
            nullptr, nullptr, nullptr, P.list, P.cnt,
            TOK, FF, Dm, 1.f, 0, (long long)Dm * FF / 2, (long long)TOK * FF / 2);
    }
    tsp(w2, P.wth, P.wtl, FF, Dm, En, (long long)FF * Dm, (long long)FF * Dm / 2);
    {
        dim3 g(Dm / 64, TOK / 128, En);
        hgemm16<2><<<g, 256, SMEM16_BYTES>>>(
            P.h1h, P.h1l, P.wth, P.wtl, b2, nullptr, nullptr, nullptr,
            P.moe0, P.moe1, P.topw, P.list, P.cnt,
            TOK, Dm, FF, 1.f, (long long)TOK * FF / 2, (long long)FF * Dm / 2, 0);
    }
    add_ln_kernel<<<TOK, 256>>>(xio, P.moe0, P.moe1, lng, lnb, xio, xh, xl);
}

extern "C" void kernel_launch(void* const* d_in, const int* in_sizes, int n_in,
                              void* d_out, int out_size) {
    (void)in_sizes; (void)n_in; (void)out_size;
    const int*   src           = (const int*)  d_in[0];
    const int*   tgt           = (const int*)  d_in[1];
    const float* emb_src       = (const float*)d_in[2];
    const float* emb_tgt       = (const float*)d_in[3];
    const float* enc_wqkv      = (const float*)d_in[4];
    const float* enc_bqkv      = (const float*)d_in[5];
    const float* enc_wo        = (const float*)d_in[6];
    const float* enc_bo        = (const float*)d_in[7];
    const float* enc_gate_w    = (const float*)d_in[8];
    const float* enc_gate_b    = (const float*)d_in[9];
    const float* enc_w1        = (const float*)d_in[10];
    const float* enc_b1        = (const float*)d_in[11];
    const float* enc_w2        = (const float*)d_in[12];
    const float* enc_b2        = (const float*)d_in[13];
    const float* enc_ln        = (const float*)d_in[14];
    const float* dec_self_wqkv = (const float*)d_in[15];
    const float* dec_self_bqkv = (const float*)d_in[16];
    const float* dec_self_wo   = (const float*)d_in[17];
    const float* dec_self_bo   = (const float*)d_in[18];
    const float* dec_cross_wqkv= (const float*)d_in[19];
    const float* dec_cross_bqkv= (const float*)d_in[20];
    const float* dec_cross_wo  = (const float*)d_in[21];
    const float* dec_cross_bo  = (const float*)d_in[22];
    const float* dec_gate_w    = (const float*)d_in[23];
    const float* dec_gate_b    = (const float*)d_in[24];
    const float* dec_w1        = (const float*)d_in[25];
    const float* dec_b1        = (const float*)d_in[26];
    const float* dec_w2        = (const float*)d_in[27];
    const float* dec_b2        = (const float*)d_in[28];
    const float* dec_ln        = (const float*)d_in[29];
    const float* final_w       = (const float*)d_in[30];
    const float* final_b       = (const float*)d_in[31];
    float* out = (float*)d_out;

    cudaFuncSetAttribute(hgemm16<0>, cudaFuncAttributeMaxDynamicSharedMemorySize, SMEM16_BYTES);
    cudaFuncSetAttribute(hgemm16<1>, cudaFuncAttributeMaxDynamicSharedMemorySize, SMEM16_BYTES);
    cudaFuncSetAttribute(hgemm16<2>, cudaFuncAttributeMaxDynamicSharedMemorySize, SMEM16_BYTES);

    DevPtrs P;
    cudaGetSymbolAddress((void**)&P.x, g_x);
    cudaGetSymbolAddress((void**)&P.y, g_y);
    cudaGetSymbolAddress((void**)&P.xh, g_xh);
    cudaGetSymbolAddress((void**)&P.xl, g_xl);
    cudaGetSymbolAddress((void**)&P.yh, g_yh);
    cudaGetSymbolAddress((void**)&P.yl, g_yl);
    cudaGetSymbolAddress((void**)&P.lin0, g_lin0);
    cudaGetSymbolAddress((void**)&P.lin1, g_lin1);
    cudaGetSymbolAddress((void**)&P.lin2, g_lin2);
    cudaGetSymbolAddress((void**)&P.qph, g_qph);
    cudaGetSymbolAddress((void**)&P.qpl, g_qpl);
    cudaGetSymbolAddress((void**)&P.kph, g_kph);
    cudaGetSymbolAddress((void**)&P.kpl, g_kpl);
    cudaGetSymbolAddress((void**)&P.vth, g_vth);
    cudaGetSymbolAddress((void**)&P.vtl, g_vtl);
    cudaGetSymbolAddress((void**)&P.sc, g_sc);
    cudaGetSymbolAddress((void**)&P.sph, g_sph);
    cudaGetSymbolAddress((void**)&P.spl, g_spl);
    cudaGetSymbolAddress((void**)&P.att, g_att);
    cudaGetSymbolAddress((void**)&P.atth, g_atth);
    cudaGetSymbolAddress((void**)&P.attl, g_attl);
    cudaGetSymbolAddress((void**)&P.proj, g_proj);
    cudaGetSymbolAddress((void**)&P.h1h, g_h1h);
    cudaGetSymbolAddress((void**)&P.h1l, g_h1l);
    cudaGetSymbolAddress((void**)&P.moe0, g_moe0);
    cudaGetSymbolAddress((void**)&P.moe1, g_moe1);
    cudaGetSymbolAddress((void**)&P.gate, g_gate);
    cudaGetSymbolAddress((void**)&P.topw, g_topw);
    cudaGetSymbolAddress((void**)&P.list, g_list);
    cudaGetSymbolAddress((void**)&P.cnt, g_cnt);
    cudaGetSymbolAddress((void**)&P.wth, g_wth);
    cudaGetSymbolAddress((void**)&P.wtl, g_wtl);

    rope_init_kernel<<<(Sn * HD) / 256, 256>>>();

    // ---------- encoder ----------
    embed_kernel<<<(TOK * Dm / 2) / 256, 256>>>(src, emb_src, P.x, P.xh, P.xl);
    for (int l = 0; l < Ln; l++) {
        run_mha(P, P.x, P.xh, P.xl, P.xh, P.xl,
                enc_wqkv + (long long)l * 3 * Dm * Dm, enc_bqkv + l * 3 * Dm,
                enc_wo + (long long)l * Dm * Dm, enc_bo + l * Dm,
                enc_ln + ((l * 2 + 0) * 2 + 0) * Dm, enc_ln + ((l * 2 + 0) * 2 + 1) * Dm, 0);
        run_moe(P, P.x, P.xh, P.xl,
                enc_gate_w + l * Dm * En, enc_gate_b + l * En,
                enc_w1 + (long long)l * En * Dm * FF, enc_b1 + l * En * FF,
                enc_w2 + (long long)l * En * FF * Dm, enc_b2 + l * En * Dm,
                enc_ln + ((l * 2 + 1) * 2 + 0) * Dm, enc_ln + ((l * 2 + 1) * 2 + 1) * Dm);
    }

    // ---------- decoder ----------
    embed_kernel<<<(TOK * Dm / 2) / 256, 256>>>(tgt, emb_tgt, P.y, P.yh, P.yl);
    for (int l = 0; l < Ln; l++) {
        run_mha(P, P.y, P.yh, P.yl, P.yh, P.yl,
                dec_self_wqkv + (long long)l * 3 * Dm * Dm, dec_self_bqkv + l * 3 * Dm,
                dec_self_wo + (long long)l * Dm * Dm, dec_self_bo + l * Dm,
                dec_ln + ((l * 3 + 0) * 2 + 0) * Dm, dec_ln + ((l * 3 + 0) * 2 + 1) * Dm, 1);
        run_mha(P, P.y, P.yh, P.yl, P.xh, P.xl,
                dec_cross_wqkv + (long long)l * 3 * Dm * Dm, dec_cross_bqkv + l * 3 * Dm,
                dec_cross_wo + (long long)l * Dm * Dm, dec_cross_bo + l * Dm,
                dec_ln + ((l * 3 + 1) * 2 + 0) * Dm, dec_ln + ((l * 3 + 1) * 2 + 1) * Dm, 0);
        run_moe(P, P.y, P.yh, P.yl,
                dec_gate_w + l * Dm * En, dec_gate_b + l * En,
                dec_w1 + (long long)l * En * Dm * FF, dec_b1 + l * En * FF,
                dec_w2 + (long long)l * En * FF * Dm, dec_b2 + l * En * Dm,
                dec_ln + ((l * 3 + 2) * 2 + 0) * Dm, dec_ln + ((l * 3 + 2) * 2 + 1) * Dm);
    }

    // ---------- final projection ----------
    tsp(final_w, P.wth, P.wtl, Dm, VT, 1, 0, 0);
    wgemm(P.yh, P.yl, P.wth, P.wtl, final_b, out, TOK, VT, Dm);
}

// round 12
// speedup vs baseline: 1.6044x; 1.0683x over previous
#include <cuda_runtime.h>
#include <cuda_fp16.h>
#include <math.h>
#include <stdint.h>

// ---------------- problem constants ----------------
#define Bn   4
#define Sn   512
#define Dm   1024
#define Hn   16
#define HD   64
#define En   8
#define FF   2048
#define Ln   2
#define VT   32000
#define TOK  (Bn*Sn)      // 2048 tokens
#define BH   (Bn*Hn)      // 64 attention batches

// ---- fp16-pair GEMM tiling: 256 thr, block 128x64, KT=32 (16 pairs), 2 CTA/SM ----
#define KPT  16
#define PST  20
#define PASZ (128*PST)
#define PBSZ (64*PST)
#define STG16 (2*PASZ + 2*PBSZ)
#define NSTAGE 3
#define SMEM16_BYTES (NSTAGE*STG16*4)   // 92160

// ---------------- device scratch ----------------
__device__ float    g_x[TOK*Dm];
__device__ float    g_y[TOK*Dm];
__device__ uint32_t g_xh[TOK*Dm/2], g_xl[TOK*Dm/2];
__device__ uint32_t g_yh[TOK*Dm/2], g_yl[TOK*Dm/2];
__device__ float    g_lin[(size_t)TOK*3*Dm];                   // fused QKV out
__device__ uint32_t g_qph[TOK*Dm/2], g_qpl[TOK*Dm/2];
__device__ uint32_t g_kph[TOK*Dm/2], g_kpl[TOK*Dm/2];
__device__ uint32_t g_vth[BH*64*(Sn/2)], g_vtl[BH*64*(Sn/2)];
__device__ uint32_t g_sph[(size_t)BH*Sn*(Sn/2)], g_spl[(size_t)BH*Sn*(Sn/2)];
__device__ uint32_t g_atth[TOK*Dm/2], g_attl[TOK*Dm/2];
__device__ float    g_proj[TOK*Dm];
__device__ uint32_t g_h1h[(size_t)En*TOK*FF/2], g_h1l[(size_t)En*TOK*FF/2];
__device__ float    g_moe0[TOK*Dm];
__device__ float    g_moe1[TOK*Dm];
__device__ float    g_gate[TOK*En];
__device__ float    g_topw[TOK*2];
__device__ int      g_list[En*TOK];
__device__ int      g_cnt[En];
__device__ float    g_cos[Sn*HD];
__device__ float    g_sin[Sn*HD];
__device__ uint32_t g_wth[16777216], g_wtl[16777216];

// ---------------- helpers ----------------
__device__ __forceinline__ void sp16pair(float v0, float v1, uint32_t& hp, uint32_t& lp) {
    __half h0 = __float2half_rn(v0);
    __half h1 = __float2half_rn(v1);
    __half l0 = __float2half_rn((v0 - __half2float(h0)) * 2048.f);
    __half l1 = __float2half_rn((v1 - __half2float(h1)) * 2048.f);
    hp = (uint32_t)__half_as_ushort(h0) | ((uint32_t)__half_as_ushort(h1) << 16);
    lp = (uint32_t)__half_as_ushort(l0) | ((uint32_t)__half_as_ushort(l1) << 16);
}
__device__ __forceinline__ void up16pair(uint32_t hp, uint32_t lp, float& v0, float& v1) {
    const float s = 1.f / 2048.f;
    v0 = __half2float(__ushort_as_half((unsigned short)(hp & 0xFFFF)))
       + __half2float(__ushort_as_half((unsigned short)(lp & 0xFFFF))) * s;
    v1 = __half2float(__ushort_as_half((unsigned short)(hp >> 16)))
       + __half2float(__ushort_as_half((unsigned short)(lp >> 16))) * s;
}
__device__ __forceinline__ uint32_t smem_u32(const void* p) {
    return (uint32_t)__cvta_generic_to_shared(p);
}
__device__ __forceinline__ void cp16(uint32_t dst, const void* src) {
    asm volatile("cp.async.cg.shared.global [%0], [%1], 16;" :: "r"(dst), "l"(src));
}
#define CP_COMMIT() asm volatile("cp.async.commit_group;")
#define CP_WAITG(n) asm volatile("cp.async.wait_group %0;" :: "n"(n))

__device__ __forceinline__ void mma_f16(float* c, const uint32_t* a, const uint32_t* b) {
    asm volatile(
        "mma.sync.aligned.m16n8k16.row.col.f32.f16.f16.f32 "
        "{%0,%1,%2,%3}, {%4,%5,%6,%7}, {%8,%9}, {%0,%1,%2,%3};"
        : "+f"(c[0]), "+f"(c[1]), "+f"(c[2]), "+f"(c[3])
        : "r"(a[0]), "r"(a[1]), "r"(a[2]), "r"(a[3]), "r"(b[0]), "r"(b[1]));
}
#define LDSM4(r0, r1, r2, r3, addr) \
    asm volatile("ldmatrix.sync.aligned.m8n8.x4.shared.b16 {%0,%1,%2,%3}, [%4];" \
                 : "=r"(r0), "=r"(r1), "=r"(r2), "=r"(r3) : "r"(addr))

// =====================================================================
// fp16-pair GEMM. A [M][K/2] pairs, B [N][K/2] pairs, acc = A@B^T.
// TERMS=3: result = accM + accC/2048 with both cross terms (near-fp32).
// TERMS=2: drop aL*bH (A effectively fp16-rounded; output-only use).
// MODE0: fp32 out. MODE1: gather+relu+pack (z=expert). MODE2: scatter*topw.
// MODE3: AV -> att pairs [tok][Dm/2]. MODE4: QK -> score pairs [z][M][N/2].
// =====================================================================
template<int MODE, int TERMS>
__global__ void __launch_bounds__(256, 2) hgemm16(
    const uint32_t* __restrict__ Ah, const uint32_t* __restrict__ Al,
    const uint32_t* __restrict__ Bh, const uint32_t* __restrict__ Bl,
    const float* __restrict__ bias, float* __restrict__ C,
    uint32_t* __restrict__ Oh, uint32_t* __restrict__ Ol,
    float* __restrict__ out0, float* __restrict__ out1, const float* __restrict__ topw,
    const int* __restrict__ list, const int* __restrict__ cnt,
    int M, int Nstore, int K, float alpha,
    long long sAz, long long sBz, long long sCz)
{
    const int z = blockIdx.z;
    const int bm = blockIdx.y * 128, bn = blockIdx.x * 64;
    int nrows = M;
    const int* lst = nullptr;
    if (MODE == 1 || MODE == 2) {
        nrows = cnt[z];
        if (bm >= nrows) return;
        lst = list + z * TOK;
        bias += (long long)z * Nstore;
    }
    Ah += (long long)z * sAz;  Al += (long long)z * sAz;
    Bh += (long long)z * sBz;  Bl += (long long)z * sBz;
    if (MODE == 0) C += (long long)z * sCz;
    if (MODE == 1 || MODE == 4) { Oh += (long long)z * sCz; Ol += (long long)z * sCz; }

    extern __shared__ uint32_t dsm[];
    __shared__ int ents[128];
    const int tid  = threadIdx.x;
    const int lane = tid & 31;
    const int warp = tid >> 5;
    const int wm = warp >> 1, wn = warp & 1;
    const int g  = lane >> 2, t4 = lane & 3;
    const int lrow = lane & 7, seg = lane >> 3;
    const int Kp = K >> 1;

    if ((MODE == 1 || MODE == 2) && tid < 128) {
        int gr = bm + tid;
        ents[tid] = (gr < nrows) ? lst[gr] : -1;
    }
    __syncthreads();

    float accM[2][4][4], accC[2][4][4];
#pragma unroll
    for (int i = 0; i < 2; i++)
#pragma unroll
        for (int j = 0; j < 4; j++)
#pragma unroll
            for (int q = 0; q < 4; q++) { accM[i][j][q] = 0.f; accC[i][j][q] = 0.f; }

    long long arow[2];
#pragma unroll
    for (int i = 0; i < 2; i++) {
        int r = (tid + i * 256) >> 2;
        if (MODE == 1) {
            int e = ents[r];
            arow[i] = (e >= 0) ? (long long)(e >> 1) : 0;
        } else {
            arow[i] = bm + r;
        }
    }
    const int chA = tid & 3;
    const long long brow = bn + (tid >> 2 & 63);
    const int chB = tid & 3;

    auto issue_tile = [&](int kt) {
        uint32_t* AhS = dsm + (kt % NSTAGE) * STG16;
        uint32_t* AlS = AhS + PASZ;
        uint32_t* BhS = AlS + PASZ;
        uint32_t* BlS = BhS + PBSZ;
        const long long kpbase = (long long)kt * KPT;
#pragma unroll
        for (int i = 0; i < 2; i++) {
            int r = (tid + i * 256) >> 2;
            const long long kp0 = kpbase + chA * 4;
            const uint32_t d = r * PST + chA * 4;
            cp16(smem_u32(&AhS[d]), Ah + arow[i] * Kp + kp0);
            if (TERMS == 3) cp16(smem_u32(&AlS[d]), Al + arow[i] * Kp + kp0);
        }
        {
            const long long kp0 = kpbase + chB * 4;
            const uint32_t d = (tid >> 2) * PST + chB * 4;
            cp16(smem_u32(&BhS[d]), Bh + brow * Kp + kp0);
            cp16(smem_u32(&BlS[d]), Bl + brow * Kp + kp0);
        }
        CP_COMMIT();
    };

    const int nk = K / 32;
    issue_tile(0);
    if (nk > 1) issue_tile(1);
    for (int kt = 0; kt < nk; kt++) {
        if (kt + 2 < nk)      { issue_tile(kt + 2); CP_WAITG(2); }
        else if (kt + 1 < nk) { CP_WAITG(1); }
        else                  { CP_WAITG(0); }
        __syncthreads();
        const uint32_t* AhS = dsm + (kt % NSTAGE) * STG16;
        const uint32_t* AlS = AhS + PASZ;
        const uint32_t* BhS = AlS + PASZ;
        const uint32_t* BlS = BhS + PBSZ;
        const int moff = wm * 32, noff = wn * 32;
#pragma unroll
        for (int ks = 0; ks < 2; ks++) {
            const int kb = ks * 8;
            uint32_t aH[2][4], aL[2][4], bH[4][2], bL[4][2];
            const int akc = kb + ((seg >> 1) << 2);
#pragma unroll
            for (int mt = 0; mt < 2; mt++) {
                int mrow = moff + mt * 16 + lrow + ((seg & 1) << 3);
                LDSM4(aH[mt][0], aH[mt][1], aH[mt][2], aH[mt][3],
                      smem_u32(&AhS[mrow * PST + akc]));
                if (TERMS == 3)
                    LDSM4(aL[mt][0], aL[mt][1], aL[mt][2], aL[mt][3],
                          smem_u32(&AlS[mrow * PST + akc]));
            }
            const int bkc = kb + ((seg & 1) << 2);
#pragma unroll
            for (int nt2 = 0; nt2 < 2; nt2++) {
                int nrow = noff + (nt2 * 2 + (seg >> 1)) * 8 + lrow;
                LDSM4(bH[nt2*2][0], bH[nt2*2][1], bH[nt2*2+1][0], bH[nt2*2+1][1],
                      smem_u32(&BhS[nrow * PST + bkc]));
                LDSM4(bL[nt2*2][0], bL[nt2*2][1], bL[nt2*2+1][0], bL[nt2*2+1][1],
                      smem_u32(&BlS[nrow * PST + bkc]));
            }
#pragma unroll
            for (int mt = 0; mt < 2; mt++)
#pragma unroll
                for (int nt = 0; nt < 4; nt++) {
                    mma_f16(accM[mt][nt], aH[mt], bH[nt]);
                    mma_f16(accC[mt][nt], aH[mt], bL[nt]);
                    if (TERMS == 3) mma_f16(accC[mt][nt], aL[mt], bH[nt]);
                }
        }
        __syncthreads();
    }

    // ---- epilogue ----
    const float s = 1.f / 2048.f;
#pragma unroll
    for (int mt = 0; mt < 2; mt++) {
        int lr = wm * 32 + mt * 16 + g;
#pragma unroll
        for (int nt = 0; nt < 4; nt++) {
            int n0 = bn + wn * 32 + nt * 8 + t4 * 2;
            if (n0 >= Nstore) continue;
            float b0v = bias ? bias[n0] : 0.f;
            float b1v = bias ? bias[n0 + 1] : 0.f;
            float v0 = (accM[mt][nt][0] + accC[mt][nt][0] * s) * alpha + b0v;
            float v1 = (accM[mt][nt][1] + accC[mt][nt][1] * s) * alpha + b1v;
            float v2 = (accM[mt][nt][2] + accC[mt][nt][2] * s) * alpha + b0v;
            float v3 = (accM[mt][nt][3] + accC[mt][nt][3] * s) * alpha + b1v;
            if (MODE == 0) {
                long long m0 = bm + lr;
                C[m0 * Nstore + n0] = v0;
                C[m0 * Nstore + n0 + 1] = v1;
                C[(m0 + 8) * Nstore + n0] = v2;
                C[(m0 + 8) * Nstore + n0 + 1] = v3;
            } else if (MODE == 1) {
                if (bm + lr < nrows) {
                    uint32_t hp, lp;
                    sp16pair(fmaxf(v0, 0.f), fmaxf(v1, 0.f), hp, lp);
                    size_t o = (size_t)(bm + lr) * (Nstore >> 1) + (n0 >> 1);
                    Oh[o] = hp; Ol[o] = lp;
                }
                if (bm + lr + 8 < nrows) {
                    uint32_t hp, lp;
                    sp16pair(fmaxf(v2, 0.f), fmaxf(v3, 0.f), hp, lp);
                    size_t o = (size_t)(bm + lr + 8) * (Nstore >> 1) + (n0 >> 1);
                    Oh[o] = hp; Ol[o] = lp;
                }
            } else if (MODE == 2) {
                int e0 = ents[lr], e2 = ents[lr + 8];
                if (e0 >= 0) {
                    float w = topw[e0];
                    float* o = (e0 & 1) ? out1 : out0;
                    long long t = (long long)(e0 >> 1) * Nstore;
                    o[t + n0] = w * v0;
                    o[t + n0 + 1] = w * v1;
                }
                if (e2 >= 0) {
                    float w = topw[e2];
                    float* o = (e2 & 1) ? out1 : out0;
                    long long t = (long long)(e2 >> 1) * Nstore;
                    o[t + n0] = w * v2;
                    o[t + n0 + 1] = w * v3;
                }
            } else if (MODE == 3) {
                // AV: z = bh; row s = bm+lr; col d = n0 -> att pairs [tok][Dm/2]
                int b = z >> 4, h = z & 15;
                long long tok0 = (long long)(b * Sn + bm + lr) * (Dm / 2) + h * 32 + (n0 >> 1);
                long long tok2 = tok0 + 8LL * (Dm / 2);
                uint32_t hp, lp;
                sp16pair(v0, v1, hp, lp);
                Oh[tok0] = hp; Ol[tok0] = lp;
                sp16pair(v2, v3, hp, lp);
                Oh[tok2] = hp; Ol[tok2] = lp;
            } else {
                // MODE4: QK score pairs [row][N/2]
                long long o0 = (long long)(bm + lr) * (Nstore >> 1) + (n0 >> 1);
                long long o2 = o0 + 8LL * (Nstore >> 1);
                uint32_t hp, lp;
                sp16pair(v0, v1, hp, lp);
                Oh[o0] = hp; Ol[o0] = lp;
                sp16pair(v2, v3, hp, lp);
                Oh[o2] = hp; Ol[o2] = lp;
            }
        }
    }
}

// =====================================================================
// transpose+split+pack: W [K,N] fp32 -> Wh/Wl [N][K/2] fp16-pair u32.
// =====================================================================
__global__ void tsp_kernel(const float* __restrict__ W,
                           uint32_t* __restrict__ h, uint32_t* __restrict__ l,
                           int K, int N, long long zsrc, long long zdst) {
    __shared__ float t[32][33];
    const long long so = (long long)blockIdx.z * zsrc;
    const long long dz = (long long)blockIdx.z * zdst;
    const int bk = blockIdx.y * 32, bnn = blockIdx.x * 32;
    const int tx = threadIdx.x, ty = threadIdx.y;
#pragma unroll
    for (int r = 0; r < 4; r++)
        t[ty + r * 8][tx] = W[so + (long long)(bk + ty + r * 8) * N + bnn + tx];
    __syncthreads();
    const int Kp = K >> 1;
#pragma unroll
    for (int r = 0; r < 2; r++) {
        int kpl = ty * 2 + r;
        uint32_t hp, lp;
        sp16pair(t[2 * kpl][tx], t[2 * kpl + 1][tx], hp, lp);
        long long o = dz + (long long)(bnn + tx) * Kp + (bk >> 1) + kpl;
        h[o] = hp;
        l[o] = lp;
    }
}

// ---------------- RoPE tables ----------------
__global__ void rope_init_kernel() {
    int idx = blockIdx.x * blockDim.x + threadIdx.x;
    if (idx >= Sn * HD) return;
    int s = idx >> 6;
    int j = idx & 63;
    int jj = j & 31;
    double inv = pow(10000.0, -((double)(2 * jj)) / 64.0);
    double ang = (double)s * inv;
    g_cos[idx] = (float)cos(ang);
    g_sin[idx] = (float)sin(ang);
}

// ---------------- embedding gather (raw + fp16 pairs) ----------------
__global__ void embed_kernel(const int* __restrict__ ids, const float* __restrict__ table,
                             float* __restrict__ out,
                             uint32_t* __restrict__ oh, uint32_t* __restrict__ ol) {
    int p = blockIdx.x * blockDim.x + threadIdx.x;
    int t = p >> 9;
    int d2 = p & 511;
    const float2 v = *(const float2*)&table[(long long)ids[t] * Dm + 2 * d2];
    *(float2*)&out[(long long)t * Dm + 2 * d2] = v;
    uint32_t hp, lp;
    sp16pair(v.x, v.y, hp, lp);
    oh[p] = hp;
    ol[p] = lp;
}

// ---------------- fp32 scalar SGEMM (tiny gate GEMM; exact routing) ----------------
__global__ void sgemm_kernel(const float* __restrict__ A, const float* __restrict__ W,
                             const float* __restrict__ bias, float* __restrict__ C,
                             int M, int N, int K) {
    const int tid = threadIdx.x;
    const int bm = blockIdx.y * 64, bn = blockIdx.x * 64;
    __shared__ float As[16][68];
    __shared__ float Ws[16][68];
    float acc[4][4] = {};
    const int ty = tid >> 4, tx = tid & 15;
    for (int k0 = 0; k0 < K; k0 += 16) {
#pragma unroll
        for (int i = 0; i < 4; i++) {
            int e = tid + i * 256;
            int r = e >> 4, kk = e & 15;
            int gr = bm + r, gk = k0 + kk;
            As[kk][r] = (gr < M && gk < K) ? A[(long long)gr * K + gk] : 0.f;
        }
#pragma unroll
        for (int i = 0; i < 4; i++) {
            int e = tid + i * 256;
            int kk = e >> 6, c = e & 63;
            int gk = k0 + kk, gc = bn + c;
            Ws[kk][c] = (gk < K && gc < N) ? W[(long long)gk * N + gc] : 0.f;
        }
        __syncthreads();
#pragma unroll
        for (int kk = 0; kk < 16; kk++) {
            float4 a4 = *(const float4*)&As[kk][ty * 4];
            float4 b4 = *(const float4*)&Ws[kk][tx * 4];
            float av[4] = {a4.x, a4.y, a4.z, a4.w};
            float bv[4] = {b4.x, b4.y, b4.z, b4.w};
#pragma unroll
            for (int i = 0; i < 4; i++)
#pragma unroll
                for (int j = 0; j < 4; j++) acc[i][j] += av[i] * bv[j];
        }
        __syncthreads();
    }
#pragma unroll
    for (int i = 0; i < 4; i++) {
        int r = bm + ty * 4 + i;
        if (r >= M) continue;
#pragma unroll
        for (int j = 0; j < 4; j++) {
            int c = bn + tx * 4 + j;
            if (c >= N) continue;
            C[(long long)r * N + c] = acc[i][j] + (bias ? bias[c] : 0.f);
        }
    }
}

// ---------------- RoPE + permute from fused lin (stride 3*Dm, col offset) ----------------
__global__ void rope_pair_kernel(const float* __restrict__ lin, int coff,
                                 uint32_t* __restrict__ oh, uint32_t* __restrict__ ol) {
    int idx = blockIdx.x * blockDim.x + threadIdx.x;   // TOK*Dm/2
    int t = idx >> 9;
    int p = idx & 511;
    int h = p >> 5;
    int d2 = p & 31;
    int b = t >> 9;
    int s = t & 511;
    int d0 = 2 * d2, d1 = d0 + 1;
    const float* row = lin + (long long)t * (3 * Dm) + coff + h * 64;
    float v0 = row[d0];
    float v1 = row[d1];
    float o0, o1;
    {
        float other = (d0 < 32) ? -row[d0 + 32] : row[d0 - 32];
        o0 = v0 * g_cos[s * 64 + d0] + other * g_sin[s * 64 + d0];
    }
    {
        float other = (d1 < 32) ? -row[d1 + 32] : row[d1 - 32];
        o1 = v1 * g_cos[s * 64 + d1] + other * g_sin[s * 64 + d1];
    }
    long long oi = ((long long)(b * Hn + h) * Sn + s) * 32 + d2;
    uint32_t hp, lp;
    sp16pair(o0, o1, hp, lp);
    oh[oi] = hp;
    ol[oi] = lp;
}

// ---------------- V transpose from fused lin -> vt [bh][d][s-pairs] ----------------
__global__ void v_transpose_kernel(const float* __restrict__ lin,
                                   uint32_t* __restrict__ oh, uint32_t* __restrict__ ol) {
    __shared__ float sm[64][65];
    const int s0 = blockIdx.x * 64;
    const int bh = blockIdx.y;
    const int b = bh >> 4, h = bh & 15;
    const int tid = threadIdx.x;
    for (int i = tid; i < 64 * 64; i += 256) {
        int si = i >> 6, d = i & 63;
        sm[si][d] = lin[(long long)(b * Sn + s0 + si) * (3 * Dm) + 2 * Dm + h * 64 + d];
    }
    __syncthreads();
    for (int i = tid; i < 32 * 64; i += 256) {
        int d = i >> 5, spi = i & 31;
        uint32_t hp, lp;
        sp16pair(sm[2 * spi][d], sm[2 * spi + 1][d], hp, lp);
        long long o = ((long long)bh * 64 + d) * (Sn / 2) + (s0 >> 1) + spi;
        oh[o] = hp;
        ol[o] = lp;
    }
}

// ---------------- row softmax over score pairs, prob pairs out (in place) ----------------
__global__ void softmax_pair_kernel(uint32_t* __restrict__ sh, uint32_t* __restrict__ sl,
                                    int causal) {
    int row = blockIdx.x;
    long long base = ((long long)blockIdx.y * Sn + row) * (Sn / 2);
    int tid = threadIdx.x;
    float v0, v1;
    up16pair(sh[base + tid], sl[base + tid], v0, v1);
    if (causal) {
        if (2 * tid > row) v0 = -1e9f;
        if (2 * tid + 1 > row) v1 = -1e9f;
    }
    __shared__ float red[256];
    float m = fmaxf(v0, v1);
    red[tid] = m;
    __syncthreads();
    for (int s = 128; s > 0; s >>= 1) {
        if (tid < s) red[tid] = fmaxf(red[tid], red[tid + s]);
        __syncthreads();
    }
    m = red[0];
    __syncthreads();
    float e0 = expf(v0 - m), e1 = expf(v1 - m);
    red[tid] = e0 + e1;
    __syncthreads();
    for (int s = 128; s > 0; s >>= 1) {
        if (tid < s) red[tid] += red[tid + s];
        __syncthreads();
    }
    float inv = 1.f / red[0];
    uint32_t hp, lp;
    sp16pair(e0 * inv, e1 * inv, hp, lp);
    sh[base + tid] = hp;
    sl[base + tid] = lp;
}

// ---------------- fused residual add(+add2) + layernorm (raw + fp16 pairs) ----------------
__global__ void add_ln_kernel(const float* __restrict__ x, const float* __restrict__ a,
                              const float* __restrict__ a2,
                              const float* __restrict__ g, const float* __restrict__ b,
                              float* __restrict__ out,
                              uint32_t* __restrict__ oh, uint32_t* __restrict__ ol) {
    int t = blockIdx.x;
    int tid = threadIdx.x;
    long long base = (long long)t * Dm;
    int c0 = tid * 4;
    float v[4];
#pragma unroll
    for (int i = 0; i < 4; i++) {
        float s = x[base + c0 + i] + a[base + c0 + i];
        if (a2) s += a2[base + c0 + i];
        v[i] = s;
    }
    __shared__ float red[256];
    red[tid] = v[0] + v[1] + v[2] + v[3];
    __syncthreads();
    for (int k = 128; k > 0; k >>= 1) {
        if (tid < k) red[tid] += red[tid + k];
        __syncthreads();
    }
    float mu = red[0] * (1.f / Dm);
    __syncthreads();
    float q = 0.f;
#pragma unroll
    for (int i = 0; i < 4; i++) { float d = v[i] - mu; q += d * d; }
    red[tid] = q;
    __syncthreads();
    for (int k = 128; k > 0; k >>= 1) {
        if (tid < k) red[tid] += red[tid + k];
        __syncthreads();
    }
    float var = red[0] * (1.f / Dm);
    float inv = rsqrtf(var + 1e-5f);
    float o[4];
#pragma unroll
    for (int i = 0; i < 4; i++)
        o[i] = (v[i] - mu) * inv * g[c0 + i] + b[c0 + i];
    *(float4*)&out[base + c0] = make_float4(o[0], o[1], o[2], o[3]);
    long long pb = (long long)t * (Dm / 2) + tid * 2;
    uint32_t hp, lp;
    sp16pair(o[0], o[1], hp, lp);
    oh[pb] = hp;
    ol[pb] = lp;
    sp16pair(o[2], o[3], hp, lp);
    oh[pb + 1] = hp;
    ol[pb + 1] = lp;
}

// ---------------- MoE gating ----------------
__global__ void zero_cnt_kernel(int* c) { if (threadIdx.x < En) c[threadIdx.x] = 0; }

__global__ void gate_route_kernel(const float* __restrict__ logits, float* __restrict__ topw,
                                  int* __restrict__ list, int* __restrict__ cnt) {
    int t = blockIdx.x * blockDim.x + threadIdx.x;
    if (t >= TOK) return;
    float p[En];
    float m = -1e30f;
#pragma unroll
    for (int e = 0; e < En; e++) { p[e] = logits[t * En + e]; m = fmaxf(m, p[e]); }
    float s = 0.f;
#pragma unroll
    for (int e = 0; e < En; e++) { p[e] = expf(p[e] - m); s += p[e]; }
    float invs = 1.f / s;
#pragma unroll
    for (int e = 0; e < En; e++) p[e] *= invs;
    int i0 = 0;
#pragma unroll
    for (int e = 1; e < En; e++) if (p[e] > p[i0]) i0 = e;
    int i1 = (i0 == 0) ? 1 : 0;
#pragma unroll
    for (int e = 0; e < En; e++) if (e != i0 && p[e] > p[i1]) i1 = e;
    float s2 = p[i0] + p[i1];
    topw[t * 2 + 0] = p[i0] / s2;
    topw[t * 2 + 1] = p[i1] / s2;
    int pos = atomicAdd(&cnt[i0], 1);
    list[i0 * TOK + pos] = t * 2 + 0;
    pos = atomicAdd(&cnt[i1], 1);
    list[i1 * TOK + pos] = t * 2 + 1;
}

// ================= host orchestration =================
struct DevPtrs {
    float *x, *y, *lin, *proj, *moe0, *moe1, *gate, *topw;
    uint32_t *xh, *xl, *yh, *yl, *qph, *qpl, *kph, *kpl, *vth, *vtl;
    uint32_t *sph, *spl, *atth, *attl, *h1h, *h1l, *wth, *wtl;
    int *list, *cnt;
};

static void tsp(const float* W, uint32_t* h, uint32_t* l, int K, int N, int batch,
                long long zsrc, long long zdst) {
    dim3 g(N / 32, K / 32, batch);
    tsp_kernel<<<g, dim3(32, 8)>>>(W, h, l, K, N, zsrc, zdst);
}

template<int TERMS>
static void wgemm_t(const uint32_t* Ah, const uint32_t* Al,
                    const uint32_t* Bh, const uint32_t* Bl,
                    const float* bias, float* C, int M, int N, int K,
                    float alpha = 1.f, int batch = 1,
                    long long sA = 0, long long sB = 0, long long sC = 0) {
    dim3 g((N + 63) / 64, M / 128, batch);
    hgemm16<0, TERMS><<<g, 256, SMEM16_BYTES>>>(Ah, Al, Bh, Bl, bias, C,
                                                nullptr, nullptr, nullptr, nullptr, nullptr,
                                                nullptr, nullptr, M, N, K, alpha, sA, sB, sC);
}

static void run_mha(DevPtrs& P, float* xio, uint32_t* xh, uint32_t* xl,
                    const uint32_t* kvh, const uint32_t* kvl,
                    const float* wqkv, const float* bqkv,
                    const float* wo, const float* bo,
                    const float* lng, const float* lnb, int causal) {
    // fused QKV: lin[TOK][3*Dm]; Q from xio-pairs, K/V from kv-pairs.
    tsp(wqkv, P.wth, P.wtl, Dm, Dm, 3, (long long)Dm * Dm, (long long)Dm * Dm / 2);
    // Q part (N columns 0..1023)
    {
        dim3 g(Dm / 64, TOK / 128, 1);
        hgemm16<0, 3><<<g, 256, SMEM16_BYTES>>>(xh, xl, P.wth, P.wtl, bqkv, P.lin,
            nullptr, nullptr, nullptr, nullptr, nullptr, nullptr, nullptr,
            TOK, 3 * Dm, Dm, 1.f, 0, 0, 0);
    }
    // K,V parts (columns 1024..3071) — B rows offset by Dm, bias offset, C col offset
    {
        dim3 g(2 * Dm / 64, TOK / 128, 1);
        hgemm16<0, 3><<<g, 256, SMEM16_BYTES>>>(kvh, kvl,
            P.wth + (long long)Dm * Dm / 2, P.wtl + (long long)Dm * Dm / 2,
            bqkv + Dm, P.lin + Dm,
            nullptr, nullptr, nullptr, nullptr, nullptr, nullptr, nullptr,
            TOK, 3 * Dm, Dm, 1.f, 0, 0, 0);
    }
    int nbp = (TOK * Dm / 2) / 256;
    rope_pair_kernel<<<nbp, 256>>>(P.lin, 0,  P.qph, P.qpl);
    rope_pair_kernel<<<nbp, 256>>>(P.lin, Dm, P.kph, P.kpl);
    v_transpose_kernel<<<dim3(Sn / 64, BH), 256>>>(P.lin, P.vth, P.vtl);
    // scores -> pairs (MODE4)
    {
        dim3 g(Sn / 64, Sn / 128, BH);
        hgemm16<4, 3><<<g, 256, SMEM16_BYTES>>>(P.qph, P.qpl, P.kph, P.kpl,
            nullptr, nullptr, P.sph, P.spl, nullptr, nullptr, nullptr, nullptr, nullptr,
            Sn, Sn, HD, 0.125f,
            (long long)Sn * 32, (long long)Sn * 32, (long long)Sn * (Sn / 2));
    }
    softmax_pair_kernel<<<dim3(Sn, BH), 256>>>(P.sph, P.spl, causal);
    // att = P @ V -> att pairs directly (MODE3)
    {
        dim3 g(1, Sn / 128, BH);
        hgemm16<3, 3><<<g, 256, SMEM16_BYTES>>>(P.sph, P.spl, P.vth, P.vtl,
            nullptr, nullptr, P.atth, P.attl, nullptr, nullptr, nullptr, nullptr, nullptr,
            Sn, HD, Sn, 1.f,
            (long long)Sn * (Sn / 2), (long long)64 * (Sn / 2), 0);
    }
    tsp(wo, P.wth, P.wtl, Dm, Dm, 1, 0, 0);
    wgemm_t<3>(P.atth, P.attl, P.wth, P.wtl, bo, P.proj, TOK, Dm, Dm);
    add_ln_kernel<<<TOK, 256>>>(xio, P.proj, nullptr, lng, lnb, xio, xh, xl);
}

static void run_moe(DevPtrs& P, float* xio, uint32_t* xh, uint32_t* xl,
                    const float* gw, const float* gb,
                    const float* w1, const float* b1, const float* w2, const float* b2,
                    const float* lng, const float* lnb) {
    sgemm_kernel<<<dim3(1, TOK / 64), 256>>>(xio, gw, gb, P.gate, TOK, En, Dm);
    zero_cnt_kernel<<<1, 32>>>(P.cnt);
    gate_route_kernel<<<TOK / 256, 256>>>(P.gate, P.topw, P.list, P.cnt);
    tsp(w1, P.wth, P.wtl, Dm, FF, En, (long long)Dm * FF, (long long)Dm * FF / 2);
    {
        dim3 g(FF / 64, TOK / 128, En);
        hgemm16<1, 3><<<g, 256, SMEM16_BYTES>>>(
            xh, xl, P.wth, P.wtl, b1, nullptr, P.h1h, P.h1l,
            nullptr, nullptr, nullptr, P.list, P.cnt,
            TOK, FF, Dm, 1.f, 0, (long long)Dm * FF / 2, (long long)TOK * FF / 2);
    }
    tsp(w2, P.wth, P.wtl, FF, Dm, En, (long long)FF * Dm, (long long)FF * Dm / 2);
    {
        dim3 g(Dm / 64, TOK / 128, En);
        hgemm16<2, 3><<<g, 256, SMEM16_BYTES>>>(
            P.h1h, P.h1l, P.wth, P.wtl, b2, nullptr, nullptr, nullptr,
            P.moe0, P.moe1, P.topw, P.list, P.cnt,
            TOK, Dm, FF, 1.f, (long long)TOK * FF / 2, (long long)FF * Dm / 2, 0);
    }
    add_ln_kernel<<<TOK, 256>>>(xio, P.moe0, P.moe1, lng, lnb, xio, xh, xl);
}

extern "C" void kernel_launch(void* const* d_in, const int* in_sizes, int n_in,
                              void* d_out, int out_size) {
    (void)in_sizes; (void)n_in; (void)out_size;
    const int*   src           = (const int*)  d_in[0];
    const int*   tgt           = (const int*)  d_in[1];
    const float* emb_src       = (const float*)d_in[2];
    const float* emb_tgt       = (const float*)d_in[3];
    const float* enc_wqkv      = (const float*)d_in[4];
    const float* enc_bqkv      = (const float*)d_in[5];
    const float* enc_wo        = (const float*)d_in[6];
    const float* enc_bo        = (const float*)d_in[7];
    const float* enc_gate_w    = (const float*)d_in[8];
    const float* enc_gate_b    = (const float*)d_in[9];
    const float* enc_w1        = (const float*)d_in[10];
    const float* enc_b1        = (const float*)d_in[11];
    const float* enc_w2        = (const float*)d_in[12];
    const float* enc_b2        = (const float*)d_in[13];
    const float* enc_ln        = (const float*)d_in[14];
    const float* dec_self_wqkv = (const float*)d_in[15];
    const float* dec_self_bqkv = (const float*)d_in[16];
    const float* dec_self_wo   = (const float*)d_in[17];
    const float* dec_self_bo   = (const float*)d_in[18];
    const float* dec_cross_wqkv= (const float*)d_in[19];
    const float* dec_cross_bqkv= (const float*)d_in[20];
    const float* dec_cross_wo  = (const float*)d_in[21];
    const float* dec_cross_bo  = (const float*)d_in[22];
    const float* dec_gate_w    = (const float*)d_in[23];
    const float* dec_gate_b    = (const float*)d_in[24];
    const float* dec_w1        = (const float*)d_in[25];
    const float* dec_b1        = (const float*)d_in[26];
    const float* dec_w2        = (const float*)d_in[27];
    const float* dec_b2        = (const float*)d_in[28];
    const float* dec_ln        = (const float*)d_in[29];
    const float* final_w       = (const float*)d_in[30];
    const float* final_b       = (const float*)d_in[31];
    float* out = (float*)d_out;

    cudaFuncSetAttribute(hgemm16<0,3>, cudaFuncAttributeMaxDynamicSharedMemorySize, SMEM16_BYTES);
    cudaFuncSetAttribute(hgemm16<0,2>, cudaFuncAttributeMaxDynamicSharedMemorySize, SMEM16_BYTES);
    cudaFuncSetAttribute(hgemm16<1,3>, cudaFuncAttributeMaxDynamicSharedMemorySize, SMEM16_BYTES);
    cudaFuncSetAttribute(hgemm16<2,3>, cudaFuncAttributeMaxDynamicSharedMemorySize, SMEM16_BYTES);
    cudaFuncSetAttribute(hgemm16<3,3>, cudaFuncAttributeMaxDynamicSharedMemorySize, SMEM16_BYTES);
    cudaFuncSetAttribute(hgemm16<4,3>, cudaFuncAttributeMaxDynamicSharedMemorySize, SMEM16_BYTES);

    DevPtrs P;
    cudaGetSymbolAddress((void**)&P.x, g_x);
    cudaGetSymbolAddress((void**)&P.y, g_y);
    cudaGetSymbolAddress((void**)&P.xh, g_xh);
    cudaGetSymbolAddress((void**)&P.xl, g_xl);
    cudaGetSymbolAddress((void**)&P.yh, g_yh);
    cudaGetSymbolAddress((void**)&P.yl, g_yl);
    cudaGetSymbolAddress((void**)&P.lin, g_lin);
    cudaGetSymbolAddress((void**)&P.qph, g_qph);
    cudaGetSymbolAddress((void**)&P.qpl, g_qpl);
    cudaGetSymbolAddress((void**)&P.kph, g_kph);
    cudaGetSymbolAddress((void**)&P.kpl, g_kpl);
    cudaGetSymbolAddress((void**)&P.vth, g_vth);
    cudaGetSymbolAddress((void**)&P.vtl, g_vtl);
    cudaGetSymbolAddress((void**)&P.sph, g_sph);
    cudaGetSymbolAddress((void**)&P.spl, g_spl);
    cudaGetSymbolAddress((void**)&P.atth, g_atth);
    cudaGetSymbolAddress((void**)&P.attl, g_attl);
    cudaGetSymbolAddress((void**)&P.proj, g_proj);
    cudaGetSymbolAddress((void**)&P.h1h, g_h1h);
    cudaGetSymbolAddress((void**)&P.h1l, g_h1l);
    cudaGetSymbolAddress((void**)&P.moe0, g_moe0);
    cudaGetSymbolAddress((void**)&P.moe1, g_moe1);
    cudaGetSymbolAddress((void**)&P.gate, g_gate);
    cudaGetSymbolAddress((void**)&P.topw, g_topw);
    cudaGetSymbolAddress((void**)&P.list, g_list);
    cudaGetSymbolAddress((void**)&P.cnt, g_cnt);
    cudaGetSymbolAddress((void**)&P.wth, g_wth);
    cudaGetSymbolAddress((void**)&P.wtl, g_wtl);

    rope_init_kernel<<<(Sn * HD) / 256, 256>>>();

    // ---------- encoder ----------
    embed_kernel<<<(TOK * Dm / 2) / 256, 256>>>(src, emb_src, P.x, P.xh, P.xl);
    for (int l = 0; l < Ln; l++) {
        run_mha(P, P.x, P.xh, P.xl, P.xh, P.xl,
                enc_wqkv + (long long)l * 3 * Dm * Dm, enc_bqkv + l * 3 * Dm,
                enc_wo + (long long)l * Dm * Dm, enc_bo + l * Dm,
                enc_ln + ((l * 2 + 0) * 2 + 0) * Dm, enc_ln + ((l * 2 + 0) * 2 + 1) * Dm, 0);
        run_moe(P, P.x, P.xh, P.xl,
                enc_gate_w + l * Dm * En, enc_gate_b + l * En,
                enc_w1 + (long long)l * En * Dm * FF, enc_b1 + l * En * FF,
                enc_w2 + (long long)l * En * FF * Dm, enc_b2 + l * En * Dm,
                enc_ln + ((l * 2 + 1) * 2 + 0) * Dm, enc_ln + ((l * 2 + 1) * 2 + 1) * Dm);
    }

    // ---------- decoder ----------
    embed_kernel<<<(TOK * Dm / 2) / 256, 256>>>(tgt, emb_tgt, P.y, P.yh, P.yl);
    for (int l = 0; l < Ln; l++) {
        run_mha(P, P.y, P.yh, P.yl, P.yh, P.yl,
                dec_self_wqkv + (long long)l * 3 * Dm * Dm, dec_self_bqkv + l * 3 * Dm,
                dec_self_wo + (long long)l * Dm * Dm, dec_self_bo + l * Dm,
                dec_ln + ((l * 3 + 0) * 2 + 0) * Dm, dec_ln + ((l * 3 + 0) * 2 + 1) * Dm, 1);
        run_mha(P, P.y, P.yh, P.yl, P.xh, P.xl,
                dec_cross_wqkv + (long long)l * 3 * Dm * Dm, dec_cross_bqkv + l * 3 * Dm,
                dec_cross_wo + (long long)l * Dm * Dm, dec_cross_bo + l * Dm,
                dec_ln + ((l * 3 + 1) * 2 + 0) * Dm, dec_ln + ((l * 3 + 1) * 2 + 1) * Dm, 0);
        run_moe(P, P.y, P.yh, P.yl,
                dec_gate_w + l * Dm * En, dec_gate_b + l * En,
                dec_w1 + (long long)l * En * Dm * FF, dec_b1 + l * En * FF,
                dec_w2 + (long long)l * En * FF * Dm, dec_b2 + l * En * Dm,
                dec_ln + ((l * 3 + 2) * 2 + 0) * Dm, dec_ln + ((l * 3 + 2) * 2 + 1) * Dm);
    }

    // ---------- final projection (2-term fp16: output-only, no compounding) ----------
    tsp(final_w, P.wth, P.wtl, Dm, VT, 1, 0, 0);
    wgemm_t<2>(P.yh, P.yl, P.wth, P.wtl, final_b, out, TOK, VT, Dm);
}

// round 13
// speedup vs baseline: 1.6941x; 1.0559x over previous
#include <cuda_runtime.h>
#include <cuda_fp16.h>
#include <math.h>
#include <stdint.h>

// ---------------- problem constants ----------------
#define Bn   4
#define Sn   512
#define Dm   1024
#define Hn   16
#define HD   64
#define En   8
#define FF   2048
#define Ln   2
#define VT   32000
#define TOK  (Bn*Sn)      // 2048 tokens
#define BH   (Bn*Hn)      // 64 attention batches

// ---- fp16-pair GEMM tiling: 256 thr, block 128x64, KT=32 (16 pairs), 2 CTA/SM ----
#define KPT  16
#define PST  20
#define PASZ (128*PST)
#define PBSZ (64*PST)
#define STG16 (2*PASZ + 2*PBSZ)
#define NSTAGE 3
#define SMEM16_BYTES (NSTAGE*STG16*4)   // 92160

// ---------------- device scratch ----------------
__device__ float    g_x[TOK*Dm];
__device__ float    g_y[TOK*Dm];
__device__ uint32_t g_xh[TOK*Dm/2], g_xl[TOK*Dm/2];
__device__ uint32_t g_yh[TOK*Dm/2], g_yl[TOK*Dm/2];
__device__ float    g_lin[(size_t)TOK*3*Dm];                   // fused QKV out
__device__ uint32_t g_qph[TOK*Dm/2], g_qpl[TOK*Dm/2];
__device__ uint32_t g_kph[TOK*Dm/2], g_kpl[TOK*Dm/2];
__device__ uint32_t g_vth[BH*64*(Sn/2)], g_vtl[BH*64*(Sn/2)];
__device__ uint32_t g_sph[(size_t)BH*Sn*(Sn/2)], g_spl[(size_t)BH*Sn*(Sn/2)];
__device__ uint32_t g_atth[TOK*Dm/2], g_attl[TOK*Dm/2];
__device__ float    g_proj[TOK*Dm];
__device__ uint32_t g_h1h[(size_t)En*TOK*FF/2], g_h1l[(size_t)En*TOK*FF/2];
__device__ float    g_moe0[TOK*Dm];
__device__ float    g_moe1[TOK*Dm];
__device__ float    g_gate[TOK*En];
__device__ float    g_topw[TOK*2];
__device__ int      g_list[En*TOK];
__device__ int      g_cnt[En];
__device__ float    g_cos[Sn*HD];
__device__ float    g_sin[Sn*HD];
__device__ uint32_t g_wth[16777216], g_wtl[16777216];

// ---------------- helpers ----------------
__device__ __forceinline__ void sp16pair(float v0, float v1, uint32_t& hp, uint32_t& lp) {
    __half h0 = __float2half_rn(v0);
    __half h1 = __float2half_rn(v1);
    __half l0 = __float2half_rn((v0 - __half2float(h0)) * 2048.f);
    __half l1 = __float2half_rn((v1 - __half2float(h1)) * 2048.f);
    hp = (uint32_t)__half_as_ushort(h0) | ((uint32_t)__half_as_ushort(h1) << 16);
    lp = (uint32_t)__half_as_ushort(l0) | ((uint32_t)__half_as_ushort(l1) << 16);
}
__device__ __forceinline__ void up16pair(uint32_t hp, uint32_t lp, float& v0, float& v1) {
    const float s = 1.f / 2048.f;
    v0 = __half2float(__ushort_as_half((unsigned short)(hp & 0xFFFF)))
       + __half2float(__ushort_as_half((unsigned short)(lp & 0xFFFF))) * s;
    v1 = __half2float(__ushort_as_half((unsigned short)(hp >> 16)))
       + __half2float(__ushort_as_half((unsigned short)(lp >> 16))) * s;
}
__device__ __forceinline__ uint32_t smem_u32(const void* p) {
    return (uint32_t)__cvta_generic_to_shared(p);
}
__device__ __forceinline__ void cp16(uint32_t dst, const void* src) {
    asm volatile("cp.async.cg.shared.global [%0], [%1], 16;" :: "r"(dst), "l"(src));
}
#define CP_COMMIT() asm volatile("cp.async.commit_group;")
#define CP_WAITG(n) asm volatile("cp.async.wait_group %0;" :: "n"(n))

__device__ __forceinline__ void mma_f16(float* c, const uint32_t* a, const uint32_t* b) {
    asm volatile(
        "mma.sync.aligned.m16n8k16.row.col.f32.f16.f16.f32 "
        "{%0,%1,%2,%3}, {%4,%5,%6,%7}, {%8,%9}, {%0,%1,%2,%3};"
        : "+f"(c[0]), "+f"(c[1]), "+f"(c[2]), "+f"(c[3])
        : "r"(a[0]), "r"(a[1]), "r"(a[2]), "r"(a[3]), "r"(b[0]), "r"(b[1]));
}
#define LDSM4(r0, r1, r2, r3, addr) \
    asm volatile("ldmatrix.sync.aligned.m8n8.x4.shared.b16 {%0,%1,%2,%3}, [%4];" \
                 : "=r"(r0), "=r"(r1), "=r"(r2), "=r"(r3) : "r"(addr))

// =====================================================================
// fp16-pair GEMM. A [M][K/2] pairs, B [N][K/2] pairs, acc = A@B^T.
// TERMS=3: accM + accC/2048 with both cross terms (near-fp32).
// TERMS=2: drop aL*bH. TERMS=1: pure fp16 (output-only use).
// MODE0: fp32 out. MODE1: gather+relu+pack (z=expert). MODE2: scatter*topw.
// MODE3: AV -> att pairs [tok][Dm/2]. MODE4: QK -> score pairs [z][M][N/2].
// Single __syncthreads per k-tile (wait -> sync -> issue(kt+2) -> compute).
// =====================================================================
template<int MODE, int TERMS>
__global__ void __launch_bounds__(256, 2) hgemm16(
    const uint32_t* __restrict__ Ah, const uint32_t* __restrict__ Al,
    const uint32_t* __restrict__ Bh, const uint32_t* __restrict__ Bl,
    const float* __restrict__ bias, float* __restrict__ C,
    uint32_t* __restrict__ Oh, uint32_t* __restrict__ Ol,
    float* __restrict__ out0, float* __restrict__ out1, const float* __restrict__ topw,
    const int* __restrict__ list, const int* __restrict__ cnt,
    int M, int Nstore, int K, float alpha,
    long long sAz, long long sBz, long long sCz)
{
    const int z = blockIdx.z;
    const int bm = blockIdx.y * 128, bn = blockIdx.x * 64;
    int nrows = M;
    const int* lst = nullptr;
    if (MODE == 1 || MODE == 2) {
        nrows = cnt[z];
        if (bm >= nrows) return;
        lst = list + z * TOK;
        bias += (long long)z * Nstore;
    }
    Ah += (long long)z * sAz;  Al += (long long)z * sAz;
    Bh += (long long)z * sBz;  Bl += (long long)z * sBz;
    if (MODE == 0) C += (long long)z * sCz;
    if (MODE == 1 || MODE == 4) { Oh += (long long)z * sCz; Ol += (long long)z * sCz; }

    extern __shared__ uint32_t dsm[];
    __shared__ int ents[128];
    const int tid  = threadIdx.x;
    const int lane = tid & 31;
    const int warp = tid >> 5;
    const int wm = warp >> 1, wn = warp & 1;
    const int g  = lane >> 2, t4 = lane & 3;
    const int lrow = lane & 7, seg = lane >> 3;
    const int Kp = K >> 1;

    if ((MODE == 1 || MODE == 2) && tid < 128) {
        int gr = bm + tid;
        ents[tid] = (gr < nrows) ? lst[gr] : -1;
    }
    __syncthreads();

    float accM[2][4][4], accC[2][4][4];
#pragma unroll
    for (int i = 0; i < 2; i++)
#pragma unroll
        for (int j = 0; j < 4; j++)
#pragma unroll
            for (int q = 0; q < 4; q++) { accM[i][j][q] = 0.f; accC[i][j][q] = 0.f; }

    long long arow[2];
#pragma unroll
    for (int i = 0; i < 2; i++) {
        int r = (tid + i * 256) >> 2;
        if (MODE == 1) {
            int e = ents[r];
            arow[i] = (e >= 0) ? (long long)(e >> 1) : 0;
        } else {
            arow[i] = bm + r;
        }
    }
    const int chA = tid & 3;
    const long long brow = bn + (tid >> 2 & 63);
    const int chB = tid & 3;

    auto issue_tile = [&](int kt) {
        uint32_t* AhS = dsm + (kt % NSTAGE) * STG16;
        uint32_t* AlS = AhS + PASZ;
        uint32_t* BhS = AlS + PASZ;
        uint32_t* BlS = BhS + PBSZ;
        const long long kpbase = (long long)kt * KPT;
#pragma unroll
        for (int i = 0; i < 2; i++) {
            int r = (tid + i * 256) >> 2;
            const long long kp0 = kpbase + chA * 4;
            const uint32_t d = r * PST + chA * 4;
            cp16(smem_u32(&AhS[d]), Ah + arow[i] * Kp + kp0);
            if (TERMS == 3) cp16(smem_u32(&AlS[d]), Al + arow[i] * Kp + kp0);
        }
        {
            const long long kp0 = kpbase + chB * 4;
            const uint32_t d = (tid >> 2) * PST + chB * 4;
            cp16(smem_u32(&BhS[d]), Bh + brow * Kp + kp0);
            if (TERMS >= 2) cp16(smem_u32(&BlS[d]), Bl + brow * Kp + kp0);
        }
        CP_COMMIT();
    };

    const int nk = K / 32;
    issue_tile(0);
    if (nk > 1) issue_tile(1);
    for (int kt = 0; kt < nk; kt++) {
        if (kt + 1 < nk) { CP_WAITG(1); }
        else             { CP_WAITG(0); }
        __syncthreads();
        if (kt + 2 < nk) issue_tile(kt + 2);
        const uint32_t* AhS = dsm + (kt % NSTAGE) * STG16;
        const uint32_t* AlS = AhS + PASZ;
        const uint32_t* BhS = AlS + PASZ;
        const uint32_t* BlS = BhS + PBSZ;
        const int moff = wm * 32, noff = wn * 32;
#pragma unroll
        for (int ks = 0; ks < 2; ks++) {
            const int kb = ks * 8;
            uint32_t aH[2][4], aL[2][4], bH[4][2], bL[4][2];
            const int akc = kb + ((seg >> 1) << 2);
#pragma unroll
            for (int mt = 0; mt < 2; mt++) {
                int mrow = moff + mt * 16 + lrow + ((seg & 1) << 3);
                LDSM4(aH[mt][0], aH[mt][1], aH[mt][2], aH[mt][3],
                      smem_u32(&AhS[mrow * PST + akc]));
                if (TERMS == 3)
                    LDSM4(aL[mt][0], aL[mt][1], aL[mt][2], aL[mt][3],
                          smem_u32(&AlS[mrow * PST + akc]));
            }
            const int bkc = kb + ((seg & 1) << 2);
#pragma unroll
            for (int nt2 = 0; nt2 < 2; nt2++) {
                int nrow = noff + (nt2 * 2 + (seg >> 1)) * 8 + lrow;
                LDSM4(bH[nt2*2][0], bH[nt2*2][1], bH[nt2*2+1][0], bH[nt2*2+1][1],
                      smem_u32(&BhS[nrow * PST + bkc]));
                if (TERMS >= 2)
                    LDSM4(bL[nt2*2][0], bL[nt2*2][1], bL[nt2*2+1][0], bL[nt2*2+1][1],
                          smem_u32(&BlS[nrow * PST + bkc]));
            }
#pragma unroll
            for (int mt = 0; mt < 2; mt++)
#pragma unroll
                for (int nt = 0; nt < 4; nt++) {
                    mma_f16(accM[mt][nt], aH[mt], bH[nt]);
                    if (TERMS >= 2) mma_f16(accC[mt][nt], aH[mt], bL[nt]);
                    if (TERMS == 3) mma_f16(accC[mt][nt], aL[mt], bH[nt]);
                }
        }
        __syncthreads();
    }

    // ---- epilogue ----
    const float s = 1.f / 2048.f;
#pragma unroll
    for (int mt = 0; mt < 2; mt++) {
        int lr = wm * 32 + mt * 16 + g;
#pragma unroll
        for (int nt = 0; nt < 4; nt++) {
            int n0 = bn + wn * 32 + nt * 8 + t4 * 2;
            if (n0 >= Nstore) continue;
            float b0v = bias ? bias[n0] : 0.f;
            float b1v = bias ? bias[n0 + 1] : 0.f;
            float v0 = (accM[mt][nt][0] + accC[mt][nt][0] * s) * alpha + b0v;
            float v1 = (accM[mt][nt][1] + accC[mt][nt][1] * s) * alpha + b1v;
            float v2 = (accM[mt][nt][2] + accC[mt][nt][2] * s) * alpha + b0v;
            float v3 = (accM[mt][nt][3] + accC[mt][nt][3] * s) * alpha + b1v;
            if (MODE == 0) {
                long long m0 = bm + lr;
                C[m0 * Nstore + n0] = v0;
                C[m0 * Nstore + n0 + 1] = v1;
                C[(m0 + 8) * Nstore + n0] = v2;
                C[(m0 + 8) * Nstore + n0 + 1] = v3;
            } else if (MODE == 1) {
                if (bm + lr < nrows) {
                    uint32_t hp, lp;
                    sp16pair(fmaxf(v0, 0.f), fmaxf(v1, 0.f), hp, lp);
                    size_t o = (size_t)(bm + lr) * (Nstore >> 1) + (n0 >> 1);
                    Oh[o] = hp; Ol[o] = lp;
                }
                if (bm + lr + 8 < nrows) {
                    uint32_t hp, lp;
                    sp16pair(fmaxf(v2, 0.f), fmaxf(v3, 0.f), hp, lp);
                    size_t o = (size_t)(bm + lr + 8) * (Nstore >> 1) + (n0 >> 1);
                    Oh[o] = hp; Ol[o] = lp;
                }
            } else if (MODE == 2) {
                int e0 = ents[lr], e2 = ents[lr + 8];
                if (e0 >= 0) {
                    float w = topw[e0];
                    float* o = (e0 & 1) ? out1 : out0;
                    long long t = (long long)(e0 >> 1) * Nstore;
                    o[t + n0] = w * v0;
                    o[t + n0 + 1] = w * v1;
                }
                if (e2 >= 0) {
                    float w = topw[e2];
                    float* o = (e2 & 1) ? out1 : out0;
                    long long t = (long long)(e2 >> 1) * Nstore;
                    o[t + n0] = w * v2;
                    o[t + n0 + 1] = w * v3;
                }
            } else if (MODE == 3) {
                int b = z >> 4, h = z & 15;
                long long tok0 = (long long)(b * Sn + bm + lr) * (Dm / 2) + h * 32 + (n0 >> 1);
                long long tok2 = tok0 + 8LL * (Dm / 2);
                uint32_t hp, lp;
                sp16pair(v0, v1, hp, lp);
                Oh[tok0] = hp; Ol[tok0] = lp;
                sp16pair(v2, v3, hp, lp);
                Oh[tok2] = hp; Ol[tok2] = lp;
            } else {
                long long o0 = (long long)(bm + lr) * (Nstore >> 1) + (n0 >> 1);
                long long o2 = o0 + 8LL * (Nstore >> 1);
                uint32_t hp, lp;
                sp16pair(v0, v1, hp, lp);
                Oh[o0] = hp; Ol[o0] = lp;
                sp16pair(v2, v3, hp, lp);
                Oh[o2] = hp; Ol[o2] = lp;
            }
        }
    }
}

// =====================================================================
// transpose+split+pack: W [K,N] fp32 -> Wh/Wl [N][K/2] fp16-pair u32.
// =====================================================================
__global__ void tsp_kernel(const float* __restrict__ W,
                           uint32_t* __restrict__ h, uint32_t* __restrict__ l,
                           int K, int N, long long zsrc, long long zdst) {
    __shared__ float t[32][33];
    const long long so = (long long)blockIdx.z * zsrc;
    const long long dz = (long long)blockIdx.z * zdst;
    const int bk = blockIdx.y * 32, bnn = blockIdx.x * 32;
    const int tx = threadIdx.x, ty = threadIdx.y;
#pragma unroll
    for (int r = 0; r < 4; r++)
        t[ty + r * 8][tx] = W[so + (long long)(bk + ty + r * 8) * N + bnn + tx];
    __syncthreads();
    const int Kp = K >> 1;
#pragma unroll
    for (int r = 0; r < 2; r++) {
        int kpl = ty * 2 + r;
        uint32_t hp, lp;
        sp16pair(t[2 * kpl][tx], t[2 * kpl + 1][tx], hp, lp);
        long long o = dz + (long long)(bnn + tx) * Kp + (bk >> 1) + kpl;
        h[o] = hp;
        l[o] = lp;
    }
}

// ---------------- RoPE tables ----------------
__global__ void rope_init_kernel() {
    int idx = blockIdx.x * blockDim.x + threadIdx.x;
    if (idx >= Sn * HD) return;
    int s = idx >> 6;
    int j = idx & 63;
    int jj = j & 31;
    double inv = pow(10000.0, -((double)(2 * jj)) / 64.0);
    double ang = (double)s * inv;
    g_cos[idx] = (float)cos(ang);
    g_sin[idx] = (float)sin(ang);
}

// ---------------- embedding gather (raw + fp16 pairs) ----------------
__global__ void embed_kernel(const int* __restrict__ ids, const float* __restrict__ table,
                             float* __restrict__ out,
                             uint32_t* __restrict__ oh, uint32_t* __restrict__ ol) {
    int p = blockIdx.x * blockDim.x + threadIdx.x;
    int t = p >> 9;
    int d2 = p & 511;
    const float2 v = *(const float2*)&table[(long long)ids[t] * Dm + 2 * d2];
    *(float2*)&out[(long long)t * Dm + 2 * d2] = v;
    uint32_t hp, lp;
    sp16pair(v.x, v.y, hp, lp);
    oh[p] = hp;
    ol[p] = lp;
}

// ---------------- fp32 scalar SGEMM (tiny gate GEMM; exact routing) ----------------
__global__ void sgemm_kernel(const float* __restrict__ A, const float* __restrict__ W,
                             const float* __restrict__ bias, float* __restrict__ C,
                             int M, int N, int K) {
    const int tid = threadIdx.x;
    const int bm = blockIdx.y * 64, bn = blockIdx.x * 64;
    __shared__ float As[16][68];
    __shared__ float Ws[16][68];
    float acc[4][4] = {};
    const int ty = tid >> 4, tx = tid & 15;
    for (int k0 = 0; k0 < K; k0 += 16) {
#pragma unroll
        for (int i = 0; i < 4; i++) {
            int e = tid + i * 256;
            int r = e >> 4, kk = e & 15;
            int gr = bm + r, gk = k0 + kk;
            As[kk][r] = (gr < M && gk < K) ? A[(long long)gr * K + gk] : 0.f;
        }
#pragma unroll
        for (int i = 0; i < 4; i++) {
            int e = tid + i * 256;
            int kk = e >> 6, c = e & 63;
            int gk = k0 + kk, gc = bn + c;
            Ws[kk][c] = (gk < K && gc < N) ? W[(long long)gk * N + gc] : 0.f;
        }
        __syncthreads();
#pragma unroll
        for (int kk = 0; kk < 16; kk++) {
            float4 a4 = *(const float4*)&As[kk][ty * 4];
            float4 b4 = *(const float4*)&Ws[kk][tx * 4];
            float av[4] = {a4.x, a4.y, a4.z, a4.w};
            float bv[4] = {b4.x, b4.y, b4.z, b4.w};
#pragma unroll
            for (int i = 0; i < 4; i++)
#pragma unroll
                for (int j = 0; j < 4; j++) acc[i][j] += av[i] * bv[j];
        }
        __syncthreads();
    }
#pragma unroll
    for (int i = 0; i < 4; i++) {
        int r = bm + ty * 4 + i;
        if (r >= M) continue;
#pragma unroll
        for (int j = 0; j < 4; j++) {
            int c = bn + tx * 4 + j;
            if (c >= N) continue;
            C[(long long)r * N + c] = acc[i][j] + (bias ? bias[c] : 0.f);
        }
    }
}

// ---------------- fused RoPE for Q and K from fused lin ----------------
__global__ void rope_qk_kernel(const float* __restrict__ lin,
                               uint32_t* __restrict__ qh, uint32_t* __restrict__ ql,
                               uint32_t* __restrict__ kh, uint32_t* __restrict__ kl) {
    int idx = blockIdx.x * blockDim.x + threadIdx.x;   // TOK*Dm/2
    int t = idx >> 9;
    int p = idx & 511;
    int h = p >> 5;
    int d2 = p & 31;
    int b = t >> 9;
    int s = t & 511;
    int d0 = 2 * d2, d1 = d0 + 1;
    float c0v = g_cos[s * 64 + d0], s0v = g_sin[s * 64 + d0];
    float c1v = g_cos[s * 64 + d1], s1v = g_sin[s * 64 + d1];
    long long oi = ((long long)(b * Hn + h) * Sn + s) * 32 + d2;
#pragma unroll
    for (int qk = 0; qk < 2; qk++) {
        const float* row = lin + (long long)t * (3 * Dm) + qk * Dm + h * 64;
        float v0 = row[d0];
        float v1 = row[d1];
        float oth0 = (d0 < 32) ? -row[d0 + 32] : row[d0 - 32];
        float oth1 = (d1 < 32) ? -row[d1 + 32] : row[d1 - 32];
        float o0 = v0 * c0v + oth0 * s0v;
        float o1 = v1 * c1v + oth1 * s1v;
        uint32_t hp, lp;
        sp16pair(o0, o1, hp, lp);
        if (qk == 0) { qh[oi] = hp; ql[oi] = lp; }
        else         { kh[oi] = hp; kl[oi] = lp; }
    }
}

// ---------------- V transpose from fused lin -> vt [bh][d][s-pairs] ----------------
__global__ void v_transpose_kernel(const float* __restrict__ lin,
                                   uint32_t* __restrict__ oh, uint32_t* __restrict__ ol) {
    __shared__ float sm[64][65];
    const int s0 = blockIdx.x * 64;
    const int bh = blockIdx.y;
    const int b = bh >> 4, h = bh & 15;
    const int tid = threadIdx.x;
    for (int i = tid; i < 64 * 64; i += 256) {
        int si = i >> 6, d = i & 63;
        sm[si][d] = lin[(long long)(b * Sn + s0 + si) * (3 * Dm) + 2 * Dm + h * 64 + d];
    }
    __syncthreads();
    for (int i = tid; i < 32 * 64; i += 256) {
        int d = i >> 5, spi = i & 31;
        uint32_t hp, lp;
        sp16pair(sm[2 * spi][d], sm[2 * spi + 1][d], hp, lp);
        long long o = ((long long)bh * 64 + d) * (Sn / 2) + (s0 >> 1) + spi;
        oh[o] = hp;
        ol[o] = lp;
    }
}

// ---------------- row softmax over score pairs (in place) ----------------
__global__ void softmax_pair_kernel(uint32_t* __restrict__ sh, uint32_t* __restrict__ sl,
                                    int causal) {
    int row = blockIdx.x;
    long long base = ((long long)blockIdx.y * Sn + row) * (Sn / 2);
    int tid = threadIdx.x;
    float v0, v1;
    up16pair(sh[base + tid], sl[base + tid], v0, v1);
    if (causal) {
        if (2 * tid > row) v0 = -1e9f;
        if (2 * tid + 1 > row) v1 = -1e9f;
    }
    __shared__ float red[256];
    float m = fmaxf(v0, v1);
    red[tid] = m;
    __syncthreads();
    for (int s = 128; s > 0; s >>= 1) {
        if (tid < s) red[tid] = fmaxf(red[tid], red[tid + s]);
        __syncthreads();
    }
    m = red[0];
    __syncthreads();
    float e0 = expf(v0 - m), e1 = expf(v1 - m);
    red[tid] = e0 + e1;
    __syncthreads();
    for (int s = 128; s > 0; s >>= 1) {
        if (tid < s) red[tid] += red[tid + s];
        __syncthreads();
    }
    float inv = 1.f / red[0];
    uint32_t hp, lp;
    sp16pair(e0 * inv, e1 * inv, hp, lp);
    sh[base + tid] = hp;
    sl[base + tid] = lp;
}

// ---------------- fused residual add(+add2) + layernorm ----------------
__global__ void add_ln_kernel(const float* __restrict__ x, const float* __restrict__ a,
                              const float* __restrict__ a2,
                              const float* __restrict__ g, const float* __restrict__ b,
                              float* __restrict__ out,
                              uint32_t* __restrict__ oh, uint32_t* __restrict__ ol) {
    int t = blockIdx.x;
    int tid = threadIdx.x;
    long long base = (long long)t * Dm;
    int c0 = tid * 4;
    float v[4];
#pragma unroll
    for (int i = 0; i < 4; i++) {
        float s = x[base + c0 + i] + a[base + c0 + i];
        if (a2) s += a2[base + c0 + i];
        v[i] = s;
    }
    __shared__ float red[256];
    red[tid] = v[0] + v[1] + v[2] + v[3];
    __syncthreads();
    for (int k = 128; k > 0; k >>= 1) {
        if (tid < k) red[tid] += red[tid + k];
        __syncthreads();
    }
    float mu = red[0] * (1.f / Dm);
    __syncthreads();
    float q = 0.f;
#pragma unroll
    for (int i = 0; i < 4; i++) { float d = v[i] - mu; q += d * d; }
    red[tid] = q;
    __syncthreads();
    for (int k = 128; k > 0; k >>= 1) {
        if (tid < k) red[tid] += red[tid + k];
        __syncthreads();
    }
    float var = red[0] * (1.f / Dm);
    float inv = rsqrtf(var + 1e-5f);
    float o[4];
#pragma unroll
    for (int i = 0; i < 4; i++)
        o[i] = (v[i] - mu) * inv * g[c0 + i] + b[c0 + i];
    *(float4*)&out[base + c0] = make_float4(o[0], o[1], o[2], o[3]);
    long long pb = (long long)t * (Dm / 2) + tid * 2;
    uint32_t hp, lp;
    sp16pair(o[0], o[1], hp, lp);
    oh[pb] = hp;
    ol[pb] = lp;
    sp16pair(o[2], o[3], hp, lp);
    oh[pb + 1] = hp;
    ol[pb + 1] = lp;
}

// ---------------- MoE gating ----------------
__global__ void zero_cnt_kernel(int* c) { if (threadIdx.x < En) c[threadIdx.x] = 0; }

__global__ void gate_route_kernel(const float* __restrict__ logits, float* __restrict__ topw,
                                  int* __restrict__ list, int* __restrict__ cnt) {
    int t = blockIdx.x * blockDim.x + threadIdx.x;
    if (t >= TOK) return;
    float p[En];
    float m = -1e30f;
#pragma unroll
    for (int e = 0; e < En; e++) { p[e] = logits[t * En + e]; m = fmaxf(m, p[e]); }
    float s = 0.f;
#pragma unroll
    for (int e = 0; e < En; e++) { p[e] = expf(p[e] - m); s += p[e]; }
    float invs = 1.f / s;
#pragma unroll
    for (int e = 0; e < En; e++) p[e] *= invs;
    int i0 = 0;
#pragma unroll
    for (int e = 1; e < En; e++) if (p[e] > p[i0]) i0 = e;
    int i1 = (i0 == 0) ? 1 : 0;
#pragma unroll
    for (int e = 0; e < En; e++) if (e != i0 && p[e] > p[i1]) i1 = e;
    float s2 = p[i0] + p[i1];
    topw[t * 2 + 0] = p[i0] / s2;
    topw[t * 2 + 1] = p[i1] / s2;
    int pos = atomicAdd(&cnt[i0], 1);
    list[i0 * TOK + pos] = t * 2 + 0;
    pos = atomicAdd(&cnt[i1], 1);
    list[i1 * TOK + pos] = t * 2 + 1;
}

// ================= host orchestration =================
struct DevPtrs {
    float *x, *y, *lin, *proj, *moe0, *moe1, *gate, *topw;
    uint32_t *xh, *xl, *yh, *yl, *qph, *qpl, *kph, *kpl, *vth, *vtl;
    uint32_t *sph, *spl, *atth, *attl, *h1h, *h1l, *wth, *wtl;
    int *list, *cnt;
};

static void tsp(const float* W, uint32_t* h, uint32_t* l, int K, int N, int batch,
                long long zsrc, long long zdst) {
    dim3 g(N / 32, K / 32, batch);
    tsp_kernel<<<g, dim3(32, 8)>>>(W, h, l, K, N, zsrc, zdst);
}

template<int TERMS>
static void wgemm_t(const uint32_t* Ah, const uint32_t* Al,
                    const uint32_t* Bh, const uint32_t* Bl,
                    const float* bias, float* C, int M, int N, int K,
                    float alpha = 1.f, int batch = 1,
                    long long sA = 0, long long sB = 0, long long sC = 0) {
    dim3 g((N + 63) / 64, M / 128, batch);
    hgemm16<0, TERMS><<<g, 256, SMEM16_BYTES>>>(Ah, Al, Bh, Bl, bias, C,
                                                nullptr, nullptr, nullptr, nullptr, nullptr,
                                                nullptr, nullptr, M, N, K, alpha, sA, sB, sC);
}

static void run_mha(DevPtrs& P, float* xio, uint32_t* xh, uint32_t* xl,
                    const uint32_t* kvh, const uint32_t* kvl,
                    const float* wqkv, const float* bqkv,
                    const float* wo, const float* bo,
                    const float* lng, const float* lnb, int causal) {
    tsp(wqkv, P.wth, P.wtl, Dm, Dm, 3, (long long)Dm * Dm, (long long)Dm * Dm / 2);
    {
        dim3 g(Dm / 64, TOK / 128, 1);
        hgemm16<0, 3><<<g, 256, SMEM16_BYTES>>>(xh, xl, P.wth, P.wtl, bqkv, P.lin,
            nullptr, nullptr, nullptr, nullptr, nullptr, nullptr, nullptr,
            TOK, 3 * Dm, Dm, 1.f, 0, 0, 0);
    }
    {
        dim3 g(2 * Dm / 64, TOK / 128, 1);
        hgemm16<0, 3><<<g, 256, SMEM16_BYTES>>>(kvh, kvl,
            P.wth + (long long)Dm * Dm / 2, P.wtl + (long long)Dm * Dm / 2,
            bqkv + Dm, P.lin + Dm,
            nullptr, nullptr, nullptr, nullptr, nullptr, nullptr, nullptr,
            TOK, 3 * Dm, Dm, 1.f, 0, 0, 0);
    }
    int nbp = (TOK * Dm / 2) / 256;
    rope_qk_kernel<<<nbp, 256>>>(P.lin, P.qph, P.qpl, P.kph, P.kpl);
    v_transpose_kernel<<<dim3(Sn / 64, BH), 256>>>(P.lin, P.vth, P.vtl);
    {
        dim3 g(Sn / 64, Sn / 128, BH);
        hgemm16<4, 3><<<g, 256, SMEM16_BYTES>>>(P.qph, P.qpl, P.kph, P.kpl,
            nullptr, nullptr, P.sph, P.spl, nullptr, nullptr, nullptr, nullptr, nullptr,
            Sn, Sn, HD, 0.125f,
            (long long)Sn * 32, (long long)Sn * 32, (long long)Sn * (Sn / 2));
    }
    softmax_pair_kernel<<<dim3(Sn, BH), 256>>>(P.sph, P.spl, causal);
    {
        dim3 g(1, Sn / 128, BH);
        hgemm16<3, 3><<<g, 256, SMEM16_BYTES>>>(P.sph, P.spl, P.vth, P.vtl,
            nullptr, nullptr, P.atth, P.attl, nullptr, nullptr, nullptr, nullptr, nullptr,
            Sn, HD, Sn, 1.f,
            (long long)Sn * (Sn / 2), (long long)64 * (Sn / 2), 0);
    }
    tsp(wo, P.wth, P.wtl, Dm, Dm, 1, 0, 0);
    wgemm_t<3>(P.atth, P.attl, P.wth, P.wtl, bo, P.proj, TOK, Dm, Dm);
    add_ln_kernel<<<TOK, 256>>>(xio, P.proj, nullptr, lng, lnb, xio, xh, xl);
}

static void run_moe(DevPtrs& P, float* xio, uint32_t* xh, uint32_t* xl,
                    const float* gw, const float* gb,
                    const float* w1, const float* b1, const float* w2, const float* b2,
                    const float* lng, const float* lnb) {
    sgemm_kernel<<<dim3(1, TOK / 64), 256>>>(xio, gw, gb, P.gate, TOK, En, Dm);
    zero_cnt_kernel<<<1, 32>>>(P.cnt);
    gate_route_kernel<<<TOK / 256, 256>>>(P.gate, P.topw, P.list, P.cnt);
    tsp(w1, P.wth, P.wtl, Dm, FF, En, (long long)Dm * FF, (long long)Dm * FF / 2);
    {
        dim3 g(FF / 64, TOK / 128, En);
        hgemm16<1, 3><<<g, 256, SMEM16_BYTES>>>(
            xh, xl, P.wth, P.wtl, b1, nullptr, P.h1h, P.h1l,
            nullptr, nullptr, nullptr, P.list, P.cnt,
            TOK, FF, Dm, 1.f, 0, (long long)Dm * FF / 2, (long long)TOK * FF / 2);
    }
    tsp(w2, P.wth, P.wtl, FF, Dm, En, (long long)FF * Dm, (long long)FF * Dm / 2);
    {
        dim3 g(Dm / 64, TOK / 128, En);
        hgemm16<2, 3><<<g, 256, SMEM16_BYTES>>>(
            P.h1h, P.h1l, P.wth, P.wtl, b2, nullptr, nullptr, nullptr,
            P.moe0, P.moe1, P.topw, P.list, P.cnt,
            TOK, Dm, FF, 1.f, (long long)TOK * FF / 2, (long long)FF * Dm / 2, 0);
    }
    add_ln_kernel<<<TOK, 256>>>(xio, P.moe0, P.moe1, lng, lnb, xio, xh, xl);
}

extern "C" void kernel_launch(void* const* d_in, const int* in_sizes, int n_in,
                              void* d_out, int out_size) {
    (void)in_sizes; (void)n_in; (void)out_size;
    const int*   src           = (const int*)  d_in[0];
    const int*   tgt           = (const int*)  d_in[1];
    const float* emb_src       = (const float*)d_in[2];
    const float* emb_tgt       = (const float*)d_in[3];
    const float* enc_wqkv      = (const float*)d_in[4];
    const float* enc_bqkv      = (const float*)d_in[5];
    const float* enc_wo        = (const float*)d_in[6];
    const float* enc_bo        = (const float*)d_in[7];
    const float* enc_gate_w    = (const float*)d_in[8];
    const float* enc_gate_b    = (const float*)d_in[9];
    const float* enc_w1        = (const float*)d_in[10];
    const float* enc_b1        = (const float*)d_in[11];
    const float* enc_w2        = (const float*)d_in[12];
    const float* enc_b2        = (const float*)d_in[13];
    const float* enc_ln        = (const float*)d_in[14];
    const float* dec_self_wqkv = (const float*)d_in[15];
    const float* dec_self_bqkv = (const float*)d_in[16];
    const float* dec_self_wo   = (const float*)d_in[17];
    const float* dec_self_bo   = (const float*)d_in[18];
    const float* dec_cross_wqkv= (const float*)d_in[19];
    const float* dec_cross_bqkv= (const float*)d_in[20];
    const float* dec_cross_wo  = (const float*)d_in[21];
    const float* dec_cross_bo  = (const float*)d_in[22];
    const float* dec_gate_w    = (const float*)d_in[23];
    const float* dec_gate_b    = (const float*)d_in[24];
    const float* dec_w1        = (const float*)d_in[25];
    const float* dec_b1        = (const float*)d_in[26];
    const float* dec_w2        = (const float*)d_in[27];
    const float* dec_b2        = (const float*)d_in[28];
    const float* dec_ln        = (const float*)d_in[29];
    const float* final_w       = (const float*)d_in[30];
    const float* final_b       = (const float*)d_in[31];
    float* out = (float*)d_out;

    cudaFuncSetAttribute(hgemm16<0,3>, cudaFuncAttributeMaxDynamicSharedMemorySize, SMEM16_BYTES);
    cudaFuncSetAttribute(hgemm16<0,1>, cudaFuncAttributeMaxDynamicSharedMemorySize, SMEM16_BYTES);
    cudaFuncSetAttribute(hgemm16<1,3>, cudaFuncAttributeMaxDynamicSharedMemorySize, SMEM16_BYTES);
    cudaFuncSetAttribute(hgemm16<2,3>, cudaFuncAttributeMaxDynamicSharedMemorySize, SMEM16_BYTES);
    cudaFuncSetAttribute(hgemm16<3,3>, cudaFuncAttributeMaxDynamicSharedMemorySize, SMEM16_BYTES);
    cudaFuncSetAttribute(hgemm16<4,3>, cudaFuncAttributeMaxDynamicSharedMemorySize, SMEM16_BYTES);

    DevPtrs P;
    cudaGetSymbolAddress((void**)&P.x, g_x);
    cudaGetSymbolAddress((void**)&P.y, g_y);
    cudaGetSymbolAddress((void**)&P.xh, g_xh);
    cudaGetSymbolAddress((void**)&P.xl, g_xl);
    cudaGetSymbolAddress((void**)&P.yh, g_yh);
    cudaGetSymbolAddress((void**)&P.yl, g_yl);
    cudaGetSymbolAddress((void**)&P.lin, g_lin);
    cudaGetSymbolAddress((void**)&P.qph, g_qph);
    cudaGetSymbolAddress((void**)&P.qpl, g_qpl);
    cudaGetSymbolAddress((void**)&P.kph, g_kph);
    cudaGetSymbolAddress((void**)&P.kpl, g_kpl);
    cudaGetSymbolAddress((void**)&P.vth, g_vth);
    cudaGetSymbolAddress((void**)&P.vtl, g_vtl);
    cudaGetSymbolAddress((void**)&P.sph, g_sph);
    cudaGetSymbolAddress((void**)&P.spl, g_spl);
    cudaGetSymbolAddress((void**)&P.atth, g_atth);
    cudaGetSymbolAddress((void**)&P.attl, g_attl);
    cudaGetSymbolAddress((void**)&P.proj, g_proj);
    cudaGetSymbolAddress((void**)&P.h1h, g_h1h);
    cudaGetSymbolAddress((void**)&P.h1l, g_h1l);
    cudaGetSymbolAddress((void**)&P.moe0, g_moe0);
    cudaGetSymbolAddress((void**)&P.moe1, g_moe1);
    cudaGetSymbolAddress((void**)&P.gate, g_gate);
    cudaGetSymbolAddress((void**)&P.topw, g_topw);
    cudaGetSymbolAddress((void**)&P.list, g_list);
    cudaGetSymbolAddress((void**)&P.cnt, g_cnt);
    cudaGetSymbolAddress((void**)&P.wth, g_wth);
    cudaGetSymbolAddress((void**)&P.wtl, g_wtl);

    rope_init_kernel<<<(Sn * HD) / 256, 256>>>();

    // ---------- encoder ----------
    embed_kernel<<<(TOK * Dm / 2) / 256, 256>>>(src, emb_src, P.x, P.xh, P.xl);
    for (int l = 0; l < Ln; l++) {
        run_mha(P, P.x, P.xh, P.xl, P.xh, P.xl,
                enc_wqkv + (long long)l * 3 * Dm * Dm, enc_bqkv + l * 3 * Dm,
                enc_wo + (long long)l * Dm * Dm, enc_bo + l * Dm,
                enc_ln + ((l * 2 + 0) * 2 + 0) * Dm, enc_ln + ((l * 2 + 0) * 2 + 1) * Dm, 0);
        run_moe(P, P.x, P.xh, P.xl,
                enc_gate_w + l * Dm * En, enc_gate_b + l * En,
                enc_w1 + (long long)l * En * Dm * FF, enc_b1 + l * En * FF,
                enc_w2 + (long long)l * En * FF * Dm, enc_b2 + l * En * Dm,
                enc_ln + ((l * 2 + 1) * 2 + 0) * Dm, enc_ln + ((l * 2 + 1) * 2 + 1) * Dm);
    }

    // ---------- decoder ----------
    embed_kernel<<<(TOK * Dm / 2) / 256, 256>>>(tgt, emb_tgt, P.y, P.yh, P.yl);
    for (int l = 0; l < Ln; l++) {
        run_mha(P, P.y, P.yh, P.yl, P.yh, P.yl,
                dec_self_wqkv + (long long)l * 3 * Dm * Dm, dec_self_bqkv + l * 3 * Dm,
                dec_self_wo + (long long)l * Dm * Dm, dec_self_bo + l * Dm,
                dec_ln + ((l * 3 + 0) * 2 + 0) * Dm, dec_ln + ((l * 3 + 0) * 2 + 1) * Dm, 1);
        run_mha(P, P.y, P.yh, P.yl, P.xh, P.xl,
                dec_cross_wqkv + (long long)l * 3 * Dm * Dm, dec_cross_bqkv + l * 3 * Dm,
                dec_cross_wo + (long long)l * Dm * Dm, dec_cross_bo + l * Dm,
                dec_ln + ((l * 3 + 1) * 2 + 0) * Dm, dec_ln + ((l * 3 + 1) * 2 + 1) * Dm, 0);
        run_moe(P, P.y, P.yh, P.yl,
                dec_gate_w + l * Dm * En, dec_gate_b + l * En,
                dec_w1 + (long long)l * En * Dm * FF, dec_b1 + l * En * FF,
                dec_w2 + (long long)l * En * FF * Dm, dec_b2 + l * En * Dm,
                dec_ln + ((l * 3 + 2) * 2 + 0) * Dm, dec_ln + ((l * 3 + 2) * 2 + 1) * Dm);
    }

    // ---------- final projection (1-term fp16: output-only, no compounding) ----------
    tsp(final_w, P.wth, P.wtl, Dm, VT, 1, 0, 0);
    wgemm_t<1>(P.yh, P.yl, P.wth, P.wtl, final_b, out, TOK, VT, Dm);
}

// round 14
// speedup vs baseline: 1.7659x; 1.0424x over previous
#include <cuda_runtime.h>
#include <cuda_fp16.h>
#include <math.h>
#include <stdint.h>

// ---------------- problem constants ----------------
#define Bn   4
#define Sn   512
#define Dm   1024
#define Hn   16
#define HD   64
#define En   8
#define FF   2048
#define Ln   2
#define VT   32000
#define TOK  (Bn*Sn)      // 2048 tokens
#define BH   (Bn*Hn)      // 64 attention batches

// ---- fp16-pair GEMM tiling: 256 thr, block 128x64, KT=32 (16 pairs), 2 CTA/SM ----
#define KPT  16
#define PST  20
#define PASZ (128*PST)
#define PBSZ (64*PST)
#define STG16 (2*PASZ + 2*PBSZ)
#define NSTAGE 3
#define SMEM16_BYTES (NSTAGE*STG16*4)   // 92160

// ---------------- device scratch ----------------
__device__ float    g_x[TOK*Dm];
__device__ float    g_y[TOK*Dm];
__device__ uint32_t g_xh[TOK*Dm/2], g_xl[TOK*Dm/2];
__device__ uint32_t g_yh[TOK*Dm/2], g_yl[TOK*Dm/2];
__device__ float    g_lin[(size_t)TOK*3*Dm];                   // fused QKV out
__device__ uint32_t g_qph[TOK*Dm/2], g_qpl[TOK*Dm/2];
__device__ uint32_t g_kph[TOK*Dm/2], g_kpl[TOK*Dm/2];
__device__ uint32_t g_vth[BH*64*(Sn/2)], g_vtl[BH*64*(Sn/2)];
__device__ uint32_t g_sph[(size_t)BH*Sn*(Sn/2)], g_spl[(size_t)BH*Sn*(Sn/2)];
__device__ uint32_t g_atth[TOK*Dm/2], g_attl[TOK*Dm/2];
__device__ float    g_proj[TOK*Dm];
__device__ uint32_t g_h1h[(size_t)En*TOK*FF/2], g_h1l[(size_t)En*TOK*FF/2];
__device__ float    g_moe0[TOK*Dm];
__device__ float    g_moe1[TOK*Dm];
__device__ float    g_gate[TOK*En];
__device__ float    g_topw[TOK*2];
__device__ int      g_list[En*TOK];
__device__ int      g_cnt[En];
__device__ float    g_cos[Sn*HD];
__device__ float    g_sin[Sn*HD];
__device__ uint32_t g_wth[16777216], g_wtl[16777216];

// ---------------- helpers ----------------
__device__ __forceinline__ void sp16pair(float v0, float v1, uint32_t& hp, uint32_t& lp) {
    __half h0 = __float2half_rn(v0);
    __half h1 = __float2half_rn(v1);
    __half l0 = __float2half_rn((v0 - __half2float(h0)) * 2048.f);
    __half l1 = __float2half_rn((v1 - __half2float(h1)) * 2048.f);
    hp = (uint32_t)__half_as_ushort(h0) | ((uint32_t)__half_as_ushort(h1) << 16);
    lp = (uint32_t)__half_as_ushort(l0) | ((uint32_t)__half_as_ushort(l1) << 16);
}
__device__ __forceinline__ void up16pair(uint32_t hp, uint32_t lp, float& v0, float& v1) {
    const float s = 1.f / 2048.f;
    v0 = __half2float(__ushort_as_half((unsigned short)(hp & 0xFFFF)))
       + __half2float(__ushort_as_half((unsigned short)(lp & 0xFFFF))) * s;
    v1 = __half2float(__ushort_as_half((unsigned short)(hp >> 16)))
       + __half2float(__ushort_as_half((unsigned short)(lp >> 16))) * s;
}
__device__ __forceinline__ uint32_t smem_u32(const void* p) {
    return (uint32_t)__cvta_generic_to_shared(p);
}
__device__ __forceinline__ void cp16(uint32_t dst, const void* src) {
    asm volatile("cp.async.cg.shared.global [%0], [%1], 16;" :: "r"(dst), "l"(src));
}
#define CP_COMMIT() asm volatile("cp.async.commit_group;")
#define CP_WAITG(n) asm volatile("cp.async.wait_group %0;" :: "n"(n))

__device__ __forceinline__ void mma_f16(float* c, const uint32_t* a, const uint32_t* b) {
    asm volatile(
        "mma.sync.aligned.m16n8k16.row.col.f32.f16.f16.f32 "
        "{%0,%1,%2,%3}, {%4,%5,%6,%7}, {%8,%9}, {%0,%1,%2,%3};"
        : "+f"(c[0]), "+f"(c[1]), "+f"(c[2]), "+f"(c[3])
        : "r"(a[0]), "r"(a[1]), "r"(a[2]), "r"(a[3]), "r"(b[0]), "r"(b[1]));
}
#define LDSM4(r0, r1, r2, r3, addr) \
    asm volatile("ldmatrix.sync.aligned.m8n8.x4.shared.b16 {%0,%1,%2,%3}, [%4];" \
                 : "=r"(r0), "=r"(r1), "=r"(r2), "=r"(r3) : "r"(addr))

// =====================================================================
// fp16-pair GEMM. A [M][K/2] pairs, B [N][K/2] pairs, acc = A@B^T.
// TERMS=3: accM + accC/2048 with both cross terms (near-fp32).
// TERMS=1: pure fp16 (output-only use).
// MODE0: fp32 out. MODE1: gather+relu+pack (z=expert). MODE2: scatter*topw.
// MODE3: AV -> att pairs [tok][Dm/2]. MODE4: QK -> score pairs [z][M][N/2].
// =====================================================================
template<int MODE, int TERMS>
__global__ void __launch_bounds__(256, 2) hgemm16(
    const uint32_t* __restrict__ Ah, const uint32_t* __restrict__ Al,
    const uint32_t* __restrict__ Bh, const uint32_t* __restrict__ Bl,
    const float* __restrict__ bias, float* __restrict__ C,
    uint32_t* __restrict__ Oh, uint32_t* __restrict__ Ol,
    float* __restrict__ out0, float* __restrict__ out1, const float* __restrict__ topw,
    const int* __restrict__ list, const int* __restrict__ cnt,
    int M, int Nstore, int K, float alpha,
    long long sAz, long long sBz, long long sCz)
{
    const int z = blockIdx.z;
    const int bm = blockIdx.y * 128, bn = blockIdx.x * 64;
    int nrows = M;
    const int* lst = nullptr;
    if (MODE == 1 || MODE == 2) {
        nrows = cnt[z];
        if (bm >= nrows) return;
        lst = list + z * TOK;
        bias += (long long)z * Nstore;
    }
    Ah += (long long)z * sAz;  Al += (long long)z * sAz;
    Bh += (long long)z * sBz;  Bl += (long long)z * sBz;
    if (MODE == 0) C += (long long)z * sCz;
    if (MODE == 1 || MODE == 4) { Oh += (long long)z * sCz; Ol += (long long)z * sCz; }

    extern __shared__ uint32_t dsm[];
    __shared__ int ents[128];
    const int tid  = threadIdx.x;
    const int lane = tid & 31;
    const int warp = tid >> 5;
    const int wm = warp >> 1, wn = warp & 1;
    const int g  = lane >> 2, t4 = lane & 3;
    const int lrow = lane & 7, seg = lane >> 3;
    const int Kp = K >> 1;

    if ((MODE == 1 || MODE == 2) && tid < 128) {
        int gr = bm + tid;
        ents[tid] = (gr < nrows) ? lst[gr] : -1;
    }
    __syncthreads();

    float accM[2][4][4], accC[2][4][4];
#pragma unroll
    for (int i = 0; i < 2; i++)
#pragma unroll
        for (int j = 0; j < 4; j++)
#pragma unroll
            for (int q = 0; q < 4; q++) { accM[i][j][q] = 0.f; accC[i][j][q] = 0.f; }

    long long arow[2];
#pragma unroll
    for (int i = 0; i < 2; i++) {
        int r = (tid + i * 256) >> 2;
        if (MODE == 1) {
            int e = ents[r];
            arow[i] = (e >= 0) ? (long long)(e >> 1) : 0;
        } else {
            arow[i] = bm + r;
        }
    }
    const int chA = tid & 3;
    const long long brow = bn + (tid >> 2 & 63);
    const int chB = tid & 3;

    auto issue_tile = [&](int kt) {
        uint32_t* AhS = dsm + (kt % NSTAGE) * STG16;
        uint32_t* AlS = AhS + PASZ;
        uint32_t* BhS = AlS + PASZ;
        uint32_t* BlS = BhS + PBSZ;
        const long long kpbase = (long long)kt * KPT;
#pragma unroll
        for (int i = 0; i < 2; i++) {
            int r = (tid + i * 256) >> 2;
            const long long kp0 = kpbase + chA * 4;
            const uint32_t d = r * PST + chA * 4;
            cp16(smem_u32(&AhS[d]), Ah + arow[i] * Kp + kp0);
            if (TERMS == 3) cp16(smem_u32(&AlS[d]), Al + arow[i] * Kp + kp0);
        }
        {
            const long long kp0 = kpbase + chB * 4;
            const uint32_t d = (tid >> 2) * PST + chB * 4;
            cp16(smem_u32(&BhS[d]), Bh + brow * Kp + kp0);
            if (TERMS >= 2) cp16(smem_u32(&BlS[d]), Bl + brow * Kp + kp0);
        }
        CP_COMMIT();
    };

    const int nk = K / 32;
    issue_tile(0);
    if (nk > 1) issue_tile(1);
    for (int kt = 0; kt < nk; kt++) {
        if (kt + 1 < nk) { CP_WAITG(1); }
        else             { CP_WAITG(0); }
        __syncthreads();
        if (kt + 2 < nk) issue_tile(kt + 2);
        const uint32_t* AhS = dsm + (kt % NSTAGE) * STG16;
        const uint32_t* AlS = AhS + PASZ;
        const uint32_t* BhS = AlS + PASZ;
        const uint32_t* BlS = BhS + PBSZ;
        const int moff = wm * 32, noff = wn * 32;
#pragma unroll
        for (int ks = 0; ks < 2; ks++) {
            const int kb = ks * 8;
            uint32_t aH[2][4], aL[2][4], bH[4][2], bL[4][2];
            const int akc = kb + ((seg >> 1) << 2);
#pragma unroll
            for (int mt = 0; mt < 2; mt++) {
                int mrow = moff + mt * 16 + lrow + ((seg & 1) << 3);
                LDSM4(aH[mt][0], aH[mt][1], aH[mt][2], aH[mt][3],
                      smem_u32(&AhS[mrow * PST + akc]));
                if (TERMS == 3)
                    LDSM4(aL[mt][0], aL[mt][1], aL[mt][2], aL[mt][3],
                          smem_u32(&AlS[mrow * PST + akc]));
            }
            const int bkc = kb + ((seg & 1) << 2);
#pragma unroll
            for (int nt2 = 0; nt2 < 2; nt2++) {
                int nrow = noff + (nt2 * 2 + (seg >> 1)) * 8 + lrow;
                LDSM4(bH[nt2*2][0], bH[nt2*2][1], bH[nt2*2+1][0], bH[nt2*2+1][1],
                      smem_u32(&BhS[nrow * PST + bkc]));
                if (TERMS >= 2)
                    LDSM4(bL[nt2*2][0], bL[nt2*2][1], bL[nt2*2+1][0], bL[nt2*2+1][1],
                          smem_u32(&BlS[nrow * PST + bkc]));
            }
#pragma unroll
            for (int mt = 0; mt < 2; mt++)
#pragma unroll
                for (int nt = 0; nt < 4; nt++) {
                    mma_f16(accM[mt][nt], aH[mt], bH[nt]);
                    if (TERMS >= 2) mma_f16(accC[mt][nt], aH[mt], bL[nt]);
                    if (TERMS == 3) mma_f16(accC[mt][nt], aL[mt], bH[nt]);
                }
        }
        __syncthreads();
    }

    // ---- epilogue ----
    const float s = 1.f / 2048.f;
#pragma unroll
    for (int mt = 0; mt < 2; mt++) {
        int lr = wm * 32 + mt * 16 + g;
#pragma unroll
        for (int nt = 0; nt < 4; nt++) {
            int n0 = bn + wn * 32 + nt * 8 + t4 * 2;
            if (n0 >= Nstore) continue;
            float b0v = bias ? bias[n0] : 0.f;
            float b1v = bias ? bias[n0 + 1] : 0.f;
            float v0 = (accM[mt][nt][0] + accC[mt][nt][0] * s) * alpha + b0v;
            float v1 = (accM[mt][nt][1] + accC[mt][nt][1] * s) * alpha + b1v;
            float v2 = (accM[mt][nt][2] + accC[mt][nt][2] * s) * alpha + b0v;
            float v3 = (accM[mt][nt][3] + accC[mt][nt][3] * s) * alpha + b1v;
            if (MODE == 0) {
                long long m0 = bm + lr;
                *(float2*)&C[m0 * Nstore + n0]       = make_float2(v0, v1);
                *(float2*)&C[(m0 + 8) * Nstore + n0] = make_float2(v2, v3);
            } else if (MODE == 1) {
                if (bm + lr < nrows) {
                    uint32_t hp, lp;
                    sp16pair(fmaxf(v0, 0.f), fmaxf(v1, 0.f), hp, lp);
                    size_t o = (size_t)(bm + lr) * (Nstore >> 1) + (n0 >> 1);
                    Oh[o] = hp; Ol[o] = lp;
                }
                if (bm + lr + 8 < nrows) {
                    uint32_t hp, lp;
                    sp16pair(fmaxf(v2, 0.f), fmaxf(v3, 0.f), hp, lp);
                    size_t o = (size_t)(bm + lr + 8) * (Nstore >> 1) + (n0 >> 1);
                    Oh[o] = hp; Ol[o] = lp;
                }
            } else if (MODE == 2) {
                int e0 = ents[lr], e2 = ents[lr + 8];
                if (e0 >= 0) {
                    float w = topw[e0];
                    float* o = (e0 & 1) ? out1 : out0;
                    long long t = (long long)(e0 >> 1) * Nstore;
                    *(float2*)&o[t + n0] = make_float2(w * v0, w * v1);
                }
                if (e2 >= 0) {
                    float w = topw[e2];
                    float* o = (e2 & 1) ? out1 : out0;
                    long long t = (long long)(e2 >> 1) * Nstore;
                    *(float2*)&o[t + n0] = make_float2(w * v2, w * v3);
                }
            } else if (MODE == 3) {
                int b = z >> 4, h = z & 15;
                long long tok0 = (long long)(b * Sn + bm + lr) * (Dm / 2) + h * 32 + (n0 >> 1);
                long long tok2 = tok0 + 8LL * (Dm / 2);
                uint32_t hp, lp;
                sp16pair(v0, v1, hp, lp);
                Oh[tok0] = hp; Ol[tok0] = lp;
                sp16pair(v2, v3, hp, lp);
                Oh[tok2] = hp; Ol[tok2] = lp;
            } else {
                long long o0 = (long long)(bm + lr) * (Nstore >> 1) + (n0 >> 1);
                long long o2 = o0 + 8LL * (Nstore >> 1);
                uint32_t hp, lp;
                sp16pair(v0, v1, hp, lp);
                Oh[o0] = hp; Ol[o0] = lp;
                sp16pair(v2, v3, hp, lp);
                Oh[o2] = hp; Ol[o2] = lp;
            }
        }
    }
}

// =====================================================================
// transpose+split+pack: W [K,N] fp32 -> Wh/Wl [N][K/2] fp16-pair u32.
// =====================================================================
__global__ void tsp_kernel(const float* __restrict__ W,
                           uint32_t* __restrict__ h, uint32_t* __restrict__ l,
                           int K, int N, long long zsrc, long long zdst) {
    __shared__ float t[32][33];
    const long long so = (long long)blockIdx.z * zsrc;
    const long long dz = (long long)blockIdx.z * zdst;
    const int bk = blockIdx.y * 32, bnn = blockIdx.x * 32;
    const int tx = threadIdx.x, ty = threadIdx.y;
#pragma unroll
    for (int r = 0; r < 4; r++)
        t[ty + r * 8][tx] = W[so + (long long)(bk + ty + r * 8) * N + bnn + tx];
    __syncthreads();
    const int Kp = K >> 1;
#pragma unroll
    for (int r = 0; r < 2; r++) {
        int kpl = ty * 2 + r;
        uint32_t hp, lp;
        sp16pair(t[2 * kpl][tx], t[2 * kpl + 1][tx], hp, lp);
        long long o = dz + (long long)(bnn + tx) * Kp + (bk >> 1) + kpl;
        h[o] = hp;
        l[o] = lp;
    }
}

// ---------------- RoPE tables ----------------
__global__ void rope_init_kernel() {
    int idx = blockIdx.x * blockDim.x + threadIdx.x;
    if (idx >= Sn * HD) return;
    int s = idx >> 6;
    int j = idx & 63;
    int jj = j & 31;
    double inv = pow(10000.0, -((double)(2 * jj)) / 64.0);
    double ang = (double)s * inv;
    g_cos[idx] = (float)cos(ang);
    g_sin[idx] = (float)sin(ang);
}

// ---------------- embedding gather (raw + fp16 pairs) ----------------
__global__ void embed_kernel(const int* __restrict__ ids, const float* __restrict__ table,
                             float* __restrict__ out,
                             uint32_t* __restrict__ oh, uint32_t* __restrict__ ol) {
    int p = blockIdx.x * blockDim.x + threadIdx.x;
    int t = p >> 9;
    int d2 = p & 511;
    const float2 v = *(const float2*)&table[(long long)ids[t] * Dm + 2 * d2];
    *(float2*)&out[(long long)t * Dm + 2 * d2] = v;
    uint32_t hp, lp;
    sp16pair(v.x, v.y, hp, lp);
    oh[p] = hp;
    ol[p] = lp;
}

// ---------------- fast gate: one warp per token, fp32 exact dot(1024, 8) ----------------
__global__ void gate_kernel(const float* __restrict__ X, const float* __restrict__ gw,
                            const float* __restrict__ gb, float* __restrict__ out) {
    int t = blockIdx.x * 8 + (threadIdx.x >> 5);
    int lane = threadIdx.x & 31;
    float acc[En];
#pragma unroll
    for (int e = 0; e < En; e++) acc[e] = 0.f;
    const float* xr = X + (long long)t * Dm;
    for (int k = lane; k < Dm; k += 32) {
        float xv = xr[k];
#pragma unroll
        for (int e = 0; e < En; e++) acc[e] += xv * gw[k * En + e];
    }
#pragma unroll
    for (int e = 0; e < En; e++) {
#pragma unroll
        for (int o = 16; o > 0; o >>= 1)
            acc[e] += __shfl_down_sync(0xFFFFFFFF, acc[e], o);
    }
    if (lane == 0) {
#pragma unroll
        for (int e = 0; e < En; e++) out[t * En + e] = acc[e] + gb[e];
    }
}

// ---------------- fused RoPE for Q and K from fused lin ----------------
__global__ void rope_qk_kernel(const float* __restrict__ lin,
                               uint32_t* __restrict__ qh, uint32_t* __restrict__ ql,
                               uint32_t* __restrict__ kh, uint32_t* __restrict__ kl) {
    int idx = blockIdx.x * blockDim.x + threadIdx.x;   // TOK*Dm/2
    int t = idx >> 9;
    int p = idx & 511;
    int h = p >> 5;
    int d2 = p & 31;
    int b = t >> 9;
    int s = t & 511;
    int d0 = 2 * d2, d1 = d0 + 1;
    float c0v = g_cos[s * 64 + d0], s0v = g_sin[s * 64 + d0];
    float c1v = g_cos[s * 64 + d1], s1v = g_sin[s * 64 + d1];
    long long oi = ((long long)(b * Hn + h) * Sn + s) * 32 + d2;
#pragma unroll
    for (int qk = 0; qk < 2; qk++) {
        const float* row = lin + (long long)t * (3 * Dm) + qk * Dm + h * 64;
        float v0 = row[d0];
        float v1 = row[d1];
        float oth0 = (d0 < 32) ? -row[d0 + 32] : row[d0 - 32];
        float oth1 = (d1 < 32) ? -row[d1 + 32] : row[d1 - 32];
        float o0 = v0 * c0v + oth0 * s0v;
        float o1 = v1 * c1v + oth1 * s1v;
        uint32_t hp, lp;
        sp16pair(o0, o1, hp, lp);
        if (qk == 0) { qh[oi] = hp; ql[oi] = lp; }
        else         { kh[oi] = hp; kl[oi] = lp; }
    }
}

// ---------------- V transpose from fused lin -> vt [bh][d][s-pairs] ----------------
__global__ void v_transpose_kernel(const float* __restrict__ lin,
                                   uint32_t* __restrict__ oh, uint32_t* __restrict__ ol) {
    __shared__ float sm[64][65];
    const int s0 = blockIdx.x * 64;
    const int bh = blockIdx.y;
    const int b = bh >> 4, h = bh & 15;
    const int tid = threadIdx.x;
    for (int i = tid; i < 64 * 64; i += 256) {
        int si = i >> 6, d = i & 63;
        sm[si][d] = lin[(long long)(b * Sn + s0 + si) * (3 * Dm) + 2 * Dm + h * 64 + d];
    }
    __syncthreads();
    for (int i = tid; i < 32 * 64; i += 256) {
        int d = i >> 5, spi = i & 31;
        uint32_t hp, lp;
        sp16pair(sm[2 * spi][d], sm[2 * spi + 1][d], hp, lp);
        long long o = ((long long)bh * 64 + d) * (Sn / 2) + (s0 >> 1) + spi;
        oh[o] = hp;
        ol[o] = lp;
    }
}

// ---------------- row softmax over score pairs (in place) ----------------
__global__ void softmax_pair_kernel(uint32_t* __restrict__ sh, uint32_t* __restrict__ sl,
                                    int causal) {
    int row = blockIdx.x;
    long long base = ((long long)blockIdx.y * Sn + row) * (Sn / 2);
    int tid = threadIdx.x;
    float v0, v1;
    up16pair(sh[base + tid], sl[base + tid], v0, v1);
    if (causal) {
        if (2 * tid > row) v0 = -1e9f;
        if (2 * tid + 1 > row) v1 = -1e9f;
    }
    __shared__ float red[256];
    float m = fmaxf(v0, v1);
    red[tid] = m;
    __syncthreads();
    for (int s = 128; s > 0; s >>= 1) {
        if (tid < s) red[tid] = fmaxf(red[tid], red[tid + s]);
        __syncthreads();
    }
    m = red[0];
    __syncthreads();
    float e0 = expf(v0 - m), e1 = expf(v1 - m);
    red[tid] = e0 + e1;
    __syncthreads();
    for (int s = 128; s > 0; s >>= 1) {
        if (tid < s) red[tid] += red[tid + s];
        __syncthreads();
    }
    float inv = 1.f / red[0];
    uint32_t hp, lp;
    sp16pair(e0 * inv, e1 * inv, hp, lp);
    sh[base + tid] = hp;
    sl[base + tid] = lp;
}

// ---------------- fused residual add(+add2) + layernorm ----------------
__global__ void add_ln_kernel(const float* __restrict__ x, const float* __restrict__ a,
                              const float* __restrict__ a2,
                              const float* __restrict__ g, const float* __restrict__ b,
                              float* __restrict__ out,
                              uint32_t* __restrict__ oh, uint32_t* __restrict__ ol) {
    int t = blockIdx.x;
    int tid = threadIdx.x;
    long long base = (long long)t * Dm;
    int c0 = tid * 4;
    float v[4];
#pragma unroll
    for (int i = 0; i < 4; i++) {
        float s = x[base + c0 + i] + a[base + c0 + i];
        if (a2) s += a2[base + c0 + i];
        v[i] = s;
    }
    __shared__ float red[256];
    red[tid] = v[0] + v[1] + v[2] + v[3];
    __syncthreads();
    for (int k = 128; k > 0; k >>= 1) {
        if (tid < k) red[tid] += red[tid + k];
        __syncthreads();
    }
    float mu = red[0] * (1.f / Dm);
    __syncthreads();
    float q = 0.f;
#pragma unroll
    for (int i = 0; i < 4; i++) { float d = v[i] - mu; q += d * d; }
    red[tid] = q;
    __syncthreads();
    for (int k = 128; k > 0; k >>= 1) {
        if (tid < k) red[tid] += red[tid + k];
        __syncthreads();
    }
    float var = red[0] * (1.f / Dm);
    float inv = rsqrtf(var + 1e-5f);
    float o[4];
#pragma unroll
    for (int i = 0; i < 4; i++)
        o[i] = (v[i] - mu) * inv * g[c0 + i] + b[c0 + i];
    *(float4*)&out[base + c0] = make_float4(o[0], o[1], o[2], o[3]);
    long long pb = (long long)t * (Dm / 2) + tid * 2;
    uint32_t hp, lp;
    sp16pair(o[0], o[1], hp, lp);
    oh[pb] = hp;
    ol[pb] = lp;
    sp16pair(o[2], o[3], hp, lp);
    oh[pb + 1] = hp;
    ol[pb + 1] = lp;
}

// ---------------- MoE gating ----------------
__global__ void zero_cnt_kernel(int* c) { if (threadIdx.x < En) c[threadIdx.x] = 0; }

__global__ void gate_route_kernel(const float* __restrict__ logits, float* __restrict__ topw,
                                  int* __restrict__ list, int* __restrict__ cnt) {
    int t = blockIdx.x * blockDim.x + threadIdx.x;
    if (t >= TOK) return;
    float p[En];
    float m = -1e30f;
#pragma unroll
    for (int e = 0; e < En; e++) { p[e] = logits[t * En + e]; m = fmaxf(m, p[e]); }
    float s = 0.f;
#pragma unroll
    for (int e = 0; e < En; e++) { p[e] = expf(p[e] - m); s += p[e]; }
    float invs = 1.f / s;
#pragma unroll
    for (int e = 0; e < En; e++) p[e] *= invs;
    int i0 = 0;
#pragma unroll
    for (int e = 1; e < En; e++) if (p[e] > p[i0]) i0 = e;
    int i1 = (i0 == 0) ? 1 : 0;
#pragma unroll
    for (int e = 0; e < En; e++) if (e != i0 && p[e] > p[i1]) i1 = e;
    float s2 = p[i0] + p[i1];
    topw[t * 2 + 0] = p[i0] / s2;
    topw[t * 2 + 1] = p[i1] / s2;
    int pos = atomicAdd(&cnt[i0], 1);
    list[i0 * TOK + pos] = t * 2 + 0;
    pos = atomicAdd(&cnt[i1], 1);
    list[i1 * TOK + pos] = t * 2 + 1;
}

// ================= host orchestration =================
struct DevPtrs {
    float *x, *y, *lin, *proj, *moe0, *moe1, *gate, *topw;
    uint32_t *xh, *xl, *yh, *yl, *qph, *qpl, *kph, *kpl, *vth, *vtl;
    uint32_t *sph, *spl, *atth, *attl, *h1h, *h1l, *wth, *wtl;
    int *list, *cnt;
};

static void tsp(const float* W, uint32_t* h, uint32_t* l, int K, int N, int batch,
                long long zsrc, long long zdst) {
    dim3 g(N / 32, K / 32, batch);
    tsp_kernel<<<g, dim3(32, 8)>>>(W, h, l, K, N, zsrc, zdst);
}

template<int TERMS>
static void wgemm_t(const uint32_t* Ah, const uint32_t* Al,
                    const uint32_t* Bh, const uint32_t* Bl,
                    const float* bias, float* C, int M, int N, int K,
                    float alpha = 1.f, int batch = 1,
                    long long sA = 0, long long sB = 0, long long sC = 0) {
    dim3 g((N + 63) / 64, M / 128, batch);
    hgemm16<0, TERMS><<<g, 256, SMEM16_BYTES>>>(Ah, Al, Bh, Bl, bias, C,
                                                nullptr, nullptr, nullptr, nullptr, nullptr,
                                                nullptr, nullptr, M, N, K, alpha, sA, sB, sC);
}

static void run_mha(DevPtrs& P, float* xio, uint32_t* xh, uint32_t* xl,
                    const uint32_t* kvh, const uint32_t* kvl,
                    const float* wqkv, const float* bqkv,
                    const float* wo, const float* bo,
                    const float* lng, const float* lnb, int causal) {
    tsp(wqkv, P.wth, P.wtl, Dm, Dm, 3, (long long)Dm * Dm, (long long)Dm * Dm / 2);
    if (kvh == xh) {
        // self-attention: one fused N=3072 launch
        dim3 g(3 * Dm / 64, TOK / 128, 1);
        hgemm16<0, 3><<<g, 256, SMEM16_BYTES>>>(xh, xl, P.wth, P.wtl, bqkv, P.lin,
            nullptr, nullptr, nullptr, nullptr, nullptr, nullptr, nullptr,
            TOK, 3 * Dm, Dm, 1.f, 0, 0, 0);
    } else {
        {
            dim3 g(Dm / 64, TOK / 128, 1);
            hgemm16<0, 3><<<g, 256, SMEM16_BYTES>>>(xh, xl, P.wth, P.wtl, bqkv, P.lin,
                nullptr, nullptr, nullptr, nullptr, nullptr, nullptr, nullptr,
                TOK, 3 * Dm, Dm, 1.f, 0, 0, 0);
        }
        {
            dim3 g(2 * Dm / 64, TOK / 128, 1);
            hgemm16<0, 3><<<g, 256, SMEM16_BYTES>>>(kvh, kvl,
                P.wth + (long long)Dm * Dm / 2, P.wtl + (long long)Dm * Dm / 2,
                bqkv + Dm, P.lin + Dm,
                nullptr, nullptr, nullptr, nullptr, nullptr, nullptr, nullptr,
                TOK, 3 * Dm, Dm, 1.f, 0, 0, 0);
        }
    }
    int nbp = (TOK * Dm / 2) / 256;
    rope_qk_kernel<<<nbp, 256>>>(P.lin, P.qph, P.qpl, P.kph, P.kpl);
    v_transpose_kernel<<<dim3(Sn / 64, BH), 256>>>(P.lin, P.vth, P.vtl);
    {
        dim3 g(Sn / 64, Sn / 128, BH);
        hgemm16<4, 3><<<g, 256, SMEM16_BYTES>>>(P.qph, P.qpl, P.kph, P.kpl,
            nullptr, nullptr, P.sph, P.spl, nullptr, nullptr, nullptr, nullptr, nullptr,
            Sn, Sn, HD, 0.125f,
            (long long)Sn * 32, (long long)Sn * 32, (long long)Sn * (Sn / 2));
    }
    softmax_pair_kernel<<<dim3(Sn, BH), 256>>>(P.sph, P.spl, causal);
    {
        dim3 g(1, Sn / 128, BH);
        hgemm16<3, 3><<<g, 256, SMEM16_BYTES>>>(P.sph, P.spl, P.vth, P.vtl,
            nullptr, nullptr, P.atth, P.attl, nullptr, nullptr, nullptr, nullptr, nullptr,
            Sn, HD, Sn, 1.f,
            (long long)Sn * (Sn / 2), (long long)64 * (Sn / 2), 0);
    }
    tsp(wo, P.wth, P.wtl, Dm, Dm, 1, 0, 0);
    wgemm_t<3>(P.atth, P.attl, P.wth, P.wtl, bo, P.proj, TOK, Dm, Dm);
    add_ln_kernel<<<TOK, 256>>>(xio, P.proj, nullptr, lng, lnb, xio, xh, xl);
}

static void run_moe(DevPtrs& P, float* xio, uint32_t* xh, uint32_t* xl,
                    const float* gw, const float* gb,
                    const float* w1, const float* b1, const float* w2, const float* b2,
                    const float* lng, const float* lnb) {
    gate_kernel<<<TOK / 8, 256>>>(xio, gw, gb, P.gate);
    zero_cnt_kernel<<<1, 32>>>(P.cnt);
    gate_route_kernel<<<TOK / 256, 256>>>(P.gate, P.topw, P.list, P.cnt);
    tsp(w1, P.wth, P.wtl, Dm, FF, En, (long long)Dm * FF, (long long)Dm * FF / 2);
    {
        dim3 g(FF / 64, TOK / 128, En);
        hgemm16<1, 3><<<g, 256, SMEM16_BYTES>>>(
            xh, xl, P.wth, P.wtl, b1, nullptr, P.h1h, P.h1l,
            nullptr, nullptr, nullptr, P.list, P.cnt,
            TOK, FF, Dm, 1.f, 0, (long long)Dm * FF / 2, (long long)TOK * FF / 2);
    }
    tsp(w2, P.wth, P.wtl, FF, Dm, En, (long long)FF * Dm, (long long)FF * Dm / 2);
    {
        dim3 g(Dm / 64, TOK / 128, En);
        hgemm16<2, 3><<<g, 256, SMEM16_BYTES>>>(
            P.h1h, P.h1l, P.wth, P.wtl, b2, nullptr, nullptr, nullptr,
            P.moe0, P.moe1, P.topw, P.list, P.cnt,
            TOK, Dm, FF, 1.f, (long long)TOK * FF / 2, (long long)FF * Dm / 2, 0);
    }
    add_ln_kernel<<<TOK, 256>>>(xio, P.moe0, P.moe1, lng, lnb, xio, xh, xl);
}

extern "C" void kernel_launch(void* const* d_in, const int* in_sizes, int n_in,
                              void* d_out, int out_size) {
    (void)in_sizes; (void)n_in; (void)out_size;
    const int*   src           = (const int*)  d_in[0];
    const int*   tgt           = (const int*)  d_in[1];
    const float* emb_src       = (const float*)d_in[2];
    const float* emb_tgt       = (const float*)d_in[3];
    const float* enc_wqkv      = (const float*)d_in[4];
    const float* enc_bqkv      = (const float*)d_in[5];
    const float* enc_wo        = (const float*)d_in[6];
    const float* enc_bo        = (const float*)d_in[7];
    const float* enc_gate_w    = (const float*)d_in[8];
    const float* enc_gate_b    = (const float*)d_in[9];
    const float* enc_w1        = (const float*)d_in[10];
    const float* enc_b1        = (const float*)d_in[11];
    const float* enc_w2        = (const float*)d_in[12];
    const float* enc_b2        = (const float*)d_in[13];
    const float* enc_ln        = (const float*)d_in[14];
    const float* dec_self_wqkv = (const float*)d_in[15];
    const float* dec_self_bqkv = (const float*)d_in[16];
    const float* dec_self_wo   = (const float*)d_in[17];
    const float* dec_self_bo   = (const float*)d_in[18];
    const float* dec_cross_wqkv= (const float*)d_in[19];
    const float* dec_cross_bqkv= (const float*)d_in[20];
    const float* dec_cross_wo  = (const float*)d_in[21];
    const float* dec_cross_bo  = (const float*)d_in[22];
    const float* dec_gate_w    = (const float*)d_in[23];
    const float* dec_gate_b    = (const float*)d_in[24];
    const float* dec_w1        = (const float*)d_in[25];
    const float* dec_b1        = (const float*)d_in[26];
    const float* dec_w2        = (const float*)d_in[27];
    const float* dec_b2        = (const float*)d_in[28];
    const float* dec_ln        = (const float*)d_in[29];
    const float* final_w       = (const float*)d_in[30];
    const float* final_b       = (const float*)d_in[31];
    float* out = (float*)d_out;

    cudaFuncSetAttribute(hgemm16<0,3>, cudaFuncAttributeMaxDynamicSharedMemorySize, SMEM16_BYTES);
    cudaFuncSetAttribute(hgemm16<0,1>, cudaFuncAttributeMaxDynamicSharedMemorySize, SMEM16_BYTES);
    cudaFuncSetAttribute(hgemm16<1,3>, cudaFuncAttributeMaxDynamicSharedMemorySize, SMEM16_BYTES);
    cudaFuncSetAttribute(hgemm16<2,3>, cudaFuncAttributeMaxDynamicSharedMemorySize, SMEM16_BYTES);
    cudaFuncSetAttribute(hgemm16<3,3>, cudaFuncAttributeMaxDynamicSharedMemorySize, SMEM16_BYTES);
    cudaFuncSetAttribute(hgemm16<4,3>, cudaFuncAttributeMaxDynamicSharedMemorySize, SMEM16_BYTES);

    DevPtrs P;
    cudaGetSymbolAddress((void**)&P.x, g_x);
    cudaGetSymbolAddress((void**)&P.y, g_y);
    cudaGetSymbolAddress((void**)&P.xh, g_xh);
    cudaGetSymbolAddress((void**)&P.xl, g_xl);
    cudaGetSymbolAddress((void**)&P.yh, g_yh);
    cudaGetSymbolAddress((void**)&P.yl, g_yl);
    cudaGetSymbolAddress((void**)&P.lin, g_lin);
    cudaGetSymbolAddress((void**)&P.qph, g_qph);
    cudaGetSymbolAddress((void**)&P.qpl, g_qpl);
    cudaGetSymbolAddress((void**)&P.kph, g_kph);
    cudaGetSymbolAddress((void**)&P.kpl, g_kpl);
    cudaGetSymbolAddress((void**)&P.vth, g_vth);
    cudaGetSymbolAddress((void**)&P.vtl, g_vtl);
    cudaGetSymbolAddress((void**)&P.sph, g_sph);
    cudaGetSymbolAddress((void**)&P.spl, g_spl);
    cudaGetSymbolAddress((void**)&P.atth, g_atth);
    cudaGetSymbolAddress((void**)&P.attl, g_attl);
    cudaGetSymbolAddress((void**)&P.proj, g_proj);
    cudaGetSymbolAddress((void**)&P.h1h, g_h1h);
    cudaGetSymbolAddress((void**)&P.h1l, g_h1l);
    cudaGetSymbolAddress((void**)&P.moe0, g_moe0);
    cudaGetSymbolAddress((void**)&P.moe1, g_moe1);
    cudaGetSymbolAddress((void**)&P.gate, g_gate);
    cudaGetSymbolAddress((void**)&P.topw, g_topw);
    cudaGetSymbolAddress((void**)&P.list, g_list);
    cudaGetSymbolAddress((void**)&P.cnt, g_cnt);
    cudaGetSymbolAddress((void**)&P.wth, g_wth);
    cudaGetSymbolAddress((void**)&P.wtl, g_wtl);

    rope_init_kernel<<<(Sn * HD) / 256, 256>>>();

    // ---------- encoder ----------
    embed_kernel<<<(TOK * Dm / 2) / 256, 256>>>(src, emb_src, P.x, P.xh, P.xl);
    for (int l = 0; l < Ln; l++) {
        run_mha(P, P.x, P.xh, P.xl, P.xh, P.xl,
                enc_wqkv + (long long)l * 3 * Dm * Dm, enc_bqkv + l * 3 * Dm,
                enc_wo + (long long)l * Dm * Dm, enc_bo + l * Dm,
                enc_ln + ((l * 2 + 0) * 2 + 0) * Dm, enc_ln + ((l * 2 + 0) * 2 + 1) * Dm, 0);
        run_moe(P, P.x, P.xh, P.xl,
                enc_gate_w + l * Dm * En, enc_gate_b + l * En,
                enc_w1 + (long long)l * En * Dm * FF, enc_b1 + l * En * FF,
                enc_w2 + (long long)l * En * FF * Dm, enc_b2 + l * En * Dm,
                enc_ln + ((l * 2 + 1) * 2 + 0) * Dm, enc_ln + ((l * 2 + 1) * 2 + 1) * Dm);
    }

    // ---------- decoder ----------
    embed_kernel<<<(TOK * Dm / 2) / 256, 256>>>(tgt, emb_tgt, P.y, P.yh, P.yl);
    for (int l = 0; l < Ln; l++) {
        run_mha(P, P.y, P.yh, P.yl, P.yh, P.yl,
                dec_self_wqkv + (long long)l * 3 * Dm * Dm, dec_self_bqkv + l * 3 * Dm,
                dec_self_wo + (long long)l * Dm * Dm, dec_self_bo + l * Dm,
                dec_ln + ((l * 3 + 0) * 2 + 0) * Dm, dec_ln + ((l * 3 + 0) * 2 + 1) * Dm, 1);
        run_mha(P, P.y, P.yh, P.yl, P.xh, P.xl,
                dec_cross_wqkv + (long long)l * 3 * Dm * Dm, dec_cross_bqkv + l * 3 * Dm,
                dec_cross_wo + (long long)l * Dm * Dm, dec_cross_bo + l * Dm,
                dec_ln + ((l * 3 + 1) * 2 + 0) * Dm, dec_ln + ((l * 3 + 1) * 2 + 1) * Dm, 0);
        run_moe(P, P.y, P.yh, P.yl,
                dec_gate_w + l * Dm * En, dec_gate_b + l * En,
                dec_w1 + (long long)l * En * Dm * FF, dec_b1 + l * En * FF,
                dec_w2 + (long long)l * En * FF * Dm, dec_b2 + l * En * Dm,
                dec_ln + ((l * 3 + 2) * 2 + 0) * Dm, dec_ln + ((l * 3 + 2) * 2 + 1) * Dm);
    }

    // ---------- final projection (1-term fp16: output-only, no compounding) ----------
    tsp(final_w, P.wth, P.wtl, Dm, VT, 1, 0, 0);
    wgemm_t<1>(P.yh, P.yl, P.wth, P.wtl, final_b, out, TOK, VT, Dm);
}

// round 15
// speedup vs baseline: 1.8068x; 1.0231x over previous
#include <cuda_runtime.h>
#include <cuda_fp16.h>
#include <math.h>
#include <stdint.h>

// ---------------- problem constants ----------------
#define Bn   4
#define Sn   512
#define Dm   1024
#define Hn   16
#define HD   64
#define En   8
#define FF   2048
#define Ln   2
#define VT   32000
#define TOK  (Bn*Sn)      // 2048 tokens
#define BH   (Bn*Hn)      // 64 attention batches

// ---- fp16-pair GEMM tiling: 256 thr, block 128x64, KT=32 (16 pairs) ----
#define KPT  16
#define PST  20
#define PASZ (128*PST)
#define PBSZ (64*PST)
#define STG16 (2*PASZ + 2*PBSZ)
#define NSTAGE 3
#define SMEM16_BYTES (NSTAGE*STG16*4)   // 92160

// slim TERMS=1 variant: only Ah + Bh per stage
#define STG1S (PASZ + PBSZ)             // 3840 u32
#define SMEM1S_BYTES (NSTAGE*STG1S*4)   // 46080

// ---------------- device scratch ----------------
__device__ float    g_x[TOK*Dm];
__device__ float    g_y[TOK*Dm];
__device__ uint32_t g_xh[TOK*Dm/2], g_xl[TOK*Dm/2];
__device__ uint32_t g_yh[TOK*Dm/2], g_yl[TOK*Dm/2];
__device__ float    g_lin[(size_t)TOK*3*Dm];
__device__ uint32_t g_qph[TOK*Dm/2], g_qpl[TOK*Dm/2];
__device__ uint32_t g_kph[TOK*Dm/2], g_kpl[TOK*Dm/2];
__device__ uint32_t g_vth[BH*64*(Sn/2)], g_vtl[BH*64*(Sn/2)];
__device__ uint32_t g_sph[(size_t)BH*Sn*(Sn/2)], g_spl[(size_t)BH*Sn*(Sn/2)];
__device__ uint32_t g_atth[TOK*Dm/2], g_attl[TOK*Dm/2];
__device__ float    g_proj[TOK*Dm];
__device__ uint32_t g_h1h[(size_t)En*TOK*FF/2], g_h1l[(size_t)En*TOK*FF/2];
__device__ float    g_moe0[TOK*Dm];
__device__ float    g_moe1[TOK*Dm];
__device__ float    g_gate[TOK*En];
__device__ float    g_topw[TOK*2];
__device__ int      g_list[En*TOK];
__device__ int      g_cnt[En];
__device__ float    g_cos[Sn*HD];
__device__ float    g_sin[Sn*HD];
__device__ uint32_t g_wth[16777216], g_wtl[16777216];

// ---------------- helpers ----------------
__device__ __forceinline__ void sp16pair(float v0, float v1, uint32_t& hp, uint32_t& lp) {
    __half h0 = __float2half_rn(v0);
    __half h1 = __float2half_rn(v1);
    __half l0 = __float2half_rn((v0 - __half2float(h0)) * 2048.f);
    __half l1 = __float2half_rn((v1 - __half2float(h1)) * 2048.f);
    hp = (uint32_t)__half_as_ushort(h0) | ((uint32_t)__half_as_ushort(h1) << 16);
    lp = (uint32_t)__half_as_ushort(l0) | ((uint32_t)__half_as_ushort(l1) << 16);
}
__device__ __forceinline__ void up16pair(uint32_t hp, uint32_t lp, float& v0, float& v1) {
    const float s = 1.f / 2048.f;
    v0 = __half2float(__ushort_as_half((unsigned short)(hp & 0xFFFF)))
       + __half2float(__ushort_as_half((unsigned short)(lp & 0xFFFF))) * s;
    v1 = __half2float(__ushort_as_half((unsigned short)(hp >> 16)))
       + __half2float(__ushort_as_half((unsigned short)(lp >> 16))) * s;
}
__device__ __forceinline__ uint32_t smem_u32(const void* p) {
    return (uint32_t)__cvta_generic_to_shared(p);
}
__device__ __forceinline__ void cp16(uint32_t dst, const void* src) {
    asm volatile("cp.async.cg.shared.global [%0], [%1], 16;" :: "r"(dst), "l"(src));
}
#define CP_COMMIT() asm volatile("cp.async.commit_group;")
#define CP_WAITG(n) asm volatile("cp.async.wait_group %0;" :: "n"(n))

__device__ __forceinline__ void mma_f16(float* c, const uint32_t* a, const uint32_t* b) {
    asm volatile(
        "mma.sync.aligned.m16n8k16.row.col.f32.f16.f16.f32 "
        "{%0,%1,%2,%3}, {%4,%5,%6,%7}, {%8,%9}, {%0,%1,%2,%3};"
        : "+f"(c[0]), "+f"(c[1]), "+f"(c[2]), "+f"(c[3])
        : "r"(a[0]), "r"(a[1]), "r"(a[2]), "r"(a[3]), "r"(b[0]), "r"(b[1]));
}
#define LDSM4(r0, r1, r2, r3, addr) \
    asm volatile("ldmatrix.sync.aligned.m8n8.x4.shared.b16 {%0,%1,%2,%3}, [%4];" \
                 : "=r"(r0), "=r"(r1), "=r"(r2), "=r"(r3) : "r"(addr))

// =====================================================================
// fp16-pair GEMM. A [M][K/2] pairs, B [N][K/2] pairs, acc = A@B^T.
// TERMS=3: accM + accC/2048 (near-fp32). TERMS=2: drop aL*bH (A fp16-rounded).
// MODE0: fp32 out. MODE1: gather+relu+pack (z=expert). MODE2: scatter*topw.
// MODE3: AV -> att pairs. MODE4: QK -> score pairs.
// MODE5: like MODE0 but dual-A: tiles with bn>=Dm read A2 (passed via out0/out1).
// =====================================================================
template<int MODE, int TERMS>
__global__ void __launch_bounds__(256, 2) hgemm16(
    const uint32_t* __restrict__ Ah, const uint32_t* __restrict__ Al,
    const uint32_t* __restrict__ Bh, const uint32_t* __restrict__ Bl,
    const float* __restrict__ bias, float* __restrict__ C,
    uint32_t* __restrict__ Oh, uint32_t* __restrict__ Ol,
    float* __restrict__ out0, float* __restrict__ out1, const float* __restrict__ topw,
    const int* __restrict__ list, const int* __restrict__ cnt,
    int M, int Nstore, int K, float alpha,
    long long sAz, long long sBz, long long sCz)
{
    const int z = blockIdx.z;
    const int bm = blockIdx.y * 128, bn = blockIdx.x * 64;
    int nrows = M;
    const int* lst = nullptr;
    if (MODE == 1 || MODE == 2) {
        nrows = cnt[z];
        if (bm >= nrows) return;
        lst = list + z * TOK;
        bias += (long long)z * Nstore;
    }
    if (MODE == 5 && bn >= Dm) {
        Ah = (const uint32_t*)out0;
        Al = (const uint32_t*)out1;
    }
    Ah += (long long)z * sAz;  Al += (long long)z * sAz;
    Bh += (long long)z * sBz;  Bl += (long long)z * sBz;
    if (MODE == 0) C += (long long)z * sCz;
    if (MODE == 1 || MODE == 4) { Oh += (long long)z * sCz; Ol += (long long)z * sCz; }

    extern __shared__ uint32_t dsm[];
    __shared__ int ents[128];
    const int tid  = threadIdx.x;
    const int lane = tid & 31;
    const int warp = tid >> 5;
    const int wm = warp >> 1, wn = warp & 1;
    const int g  = lane >> 2, t4 = lane & 3;
    const int lrow = lane & 7, seg = lane >> 3;
    const int Kp = K >> 1;

    if ((MODE == 1 || MODE == 2) && tid < 128) {
        int gr = bm + tid;
        ents[tid] = (gr < nrows) ? lst[gr] : -1;
    }
    __syncthreads();

    float accM[2][4][4], accC[2][4][4];
#pragma unroll
    for (int i = 0; i < 2; i++)
#pragma unroll
        for (int j = 0; j < 4; j++)
#pragma unroll
            for (int q = 0; q < 4; q++) { accM[i][j][q] = 0.f; accC[i][j][q] = 0.f; }

    long long arow[2];
#pragma unroll
    for (int i = 0; i < 2; i++) {
        int r = (tid + i * 256) >> 2;
        if (MODE == 1) {
            int e = ents[r];
            arow[i] = (e >= 0) ? (long long)(e >> 1) : 0;
        } else {
            arow[i] = bm + r;
        }
    }
    const int chA = tid & 3;
    const long long brow = bn + (tid >> 2 & 63);
    const int chB = tid & 3;

    auto issue_tile = [&](int kt) {
        uint32_t* AhS = dsm + (kt % NSTAGE) * STG16;
        uint32_t* AlS = AhS + PASZ;
        uint32_t* BhS = AlS + PASZ;
        uint32_t* BlS = BhS + PBSZ;
        const long long kpbase = (long long)kt * KPT;
#pragma unroll
        for (int i = 0; i < 2; i++) {
            int r = (tid + i * 256) >> 2;
            const long long kp0 = kpbase + chA * 4;
            const uint32_t d = r * PST + chA * 4;
            cp16(smem_u32(&AhS[d]), Ah + arow[i] * Kp + kp0);
            if (TERMS == 3) cp16(smem_u32(&AlS[d]), Al + arow[i] * Kp + kp0);
        }
        {
            const long long kp0 = kpbase + chB * 4;
            const uint32_t d = (tid >> 2) * PST + chB * 4;
            cp16(smem_u32(&BhS[d]), Bh + brow * Kp + kp0);
            if (TERMS >= 2) cp16(smem_u32(&BlS[d]), Bl + brow * Kp + kp0);
        }
        CP_COMMIT();
    };

    const int nk = K / 32;
    issue_tile(0);
    if (nk > 1) issue_tile(1);
    for (int kt = 0; kt < nk; kt++) {
        if (kt + 1 < nk) { CP_WAITG(1); }
        else             { CP_WAITG(0); }
        __syncthreads();
        if (kt + 2 < nk) issue_tile(kt + 2);
        const uint32_t* AhS = dsm + (kt % NSTAGE) * STG16;
        const uint32_t* AlS = AhS + PASZ;
        const uint32_t* BhS = AlS + PASZ;
        const uint32_t* BlS = BhS + PBSZ;
        const int moff = wm * 32, noff = wn * 32;
#pragma unroll
        for (int ks = 0; ks < 2; ks++) {
            const int kb = ks * 8;
            uint32_t aH[2][4], aL[2][4], bH[4][2], bL[4][2];
            const int akc = kb + ((seg >> 1) << 2);
#pragma unroll
            for (int mt = 0; mt < 2; mt++) {
                int mrow = moff + mt * 16 + lrow + ((seg & 1) << 3);
                LDSM4(aH[mt][0], aH[mt][1], aH[mt][2], aH[mt][3],
                      smem_u32(&AhS[mrow * PST + akc]));
                if (TERMS == 3)
                    LDSM4(aL[mt][0], aL[mt][1], aL[mt][2], aL[mt][3],
                          smem_u32(&AlS[mrow * PST + akc]));
            }
            const int bkc = kb + ((seg & 1) << 2);
#pragma unroll
            for (int nt2 = 0; nt2 < 2; nt2++) {
                int nrow = noff + (nt2 * 2 + (seg >> 1)) * 8 + lrow;
                LDSM4(bH[nt2*2][0], bH[nt2*2][1], bH[nt2*2+1][0], bH[nt2*2+1][1],
                      smem_u32(&BhS[nrow * PST + bkc]));
                if (TERMS >= 2)
                    LDSM4(bL[nt2*2][0], bL[nt2*2][1], bL[nt2*2+1][0], bL[nt2*2+1][1],
                          smem_u32(&BlS[nrow * PST + bkc]));
            }
#pragma unroll
            for (int mt = 0; mt < 2; mt++)
#pragma unroll
                for (int nt = 0; nt < 4; nt++) {
                    mma_f16(accM[mt][nt], aH[mt], bH[nt]);
                    if (TERMS >= 2) mma_f16(accC[mt][nt], aH[mt], bL[nt]);
                    if (TERMS == 3) mma_f16(accC[mt][nt], aL[mt], bH[nt]);
                }
        }
        __syncthreads();
    }

    // ---- epilogue ----
    const float s = 1.f / 2048.f;
#pragma unroll
    for (int mt = 0; mt < 2; mt++) {
        int lr = wm * 32 + mt * 16 + g;
#pragma unroll
        for (int nt = 0; nt < 4; nt++) {
            int n0 = bn + wn * 32 + nt * 8 + t4 * 2;
            if (n0 >= Nstore) continue;
            float b0v = bias ? bias[n0] : 0.f;
            float b1v = bias ? bias[n0 + 1] : 0.f;
            float v0 = (accM[mt][nt][0] + accC[mt][nt][0] * s) * alpha + b0v;
            float v1 = (accM[mt][nt][1] + accC[mt][nt][1] * s) * alpha + b1v;
            float v2 = (accM[mt][nt][2] + accC[mt][nt][2] * s) * alpha + b0v;
            float v3 = (accM[mt][nt][3] + accC[mt][nt][3] * s) * alpha + b1v;
            if (MODE == 0 || MODE == 5) {
                long long m0 = bm + lr;
                *(float2*)&C[m0 * Nstore + n0]       = make_float2(v0, v1);
                *(float2*)&C[(m0 + 8) * Nstore + n0] = make_float2(v2, v3);
            } else if (MODE == 1) {
                if (bm + lr < nrows) {
                    uint32_t hp, lp;
                    sp16pair(fmaxf(v0, 0.f), fmaxf(v1, 0.f), hp, lp);
                    size_t o = (size_t)(bm + lr) * (Nstore >> 1) + (n0 >> 1);
                    Oh[o] = hp; Ol[o] = lp;
                }
                if (bm + lr + 8 < nrows) {
                    uint32_t hp, lp;
                    sp16pair(fmaxf(v2, 0.f), fmaxf(v3, 0.f), hp, lp);
                    size_t o = (size_t)(bm + lr + 8) * (Nstore >> 1) + (n0 >> 1);
                    Oh[o] = hp; Ol[o] = lp;
                }
            } else if (MODE == 2) {
                int e0 = ents[lr], e2 = ents[lr + 8];
                if (e0 >= 0) {
                    float w = topw[e0];
                    float* o = (e0 & 1) ? out1 : out0;
                    long long t = (long long)(e0 >> 1) * Nstore;
                    *(float2*)&o[t + n0] = make_float2(w * v0, w * v1);
                }
                if (e2 >= 0) {
                    float w = topw[e2];
                    float* o = (e2 & 1) ? out1 : out0;
                    long long t = (long long)(e2 >> 1) * Nstore;
                    *(float2*)&o[t + n0] = make_float2(w * v2, w * v3);
                }
            } else if (MODE == 3) {
                int b = z >> 4, h = z & 15;
                long long tok0 = (long long)(b * Sn + bm + lr) * (Dm / 2) + h * 32 + (n0 >> 1);
                long long tok2 = tok0 + 8LL * (Dm / 2);
                uint32_t hp, lp;
                sp16pair(v0, v1, hp, lp);
                Oh[tok0] = hp; Ol[tok0] = lp;
                sp16pair(v2, v3, hp, lp);
                Oh[tok2] = hp; Ol[tok2] = lp;
            } else {
                long long o0 = (long long)(bm + lr) * (Nstore >> 1) + (n0 >> 1);
                long long o2 = o0 + 8LL * (Nstore >> 1);
                uint32_t hp, lp;
                sp16pair(v0, v1, hp, lp);
                Oh[o0] = hp; Ol[o0] = lp;
                sp16pair(v2, v3, hp, lp);
                Oh[o2] = hp; Ol[o2] = lp;
            }
        }
    }
}

// =====================================================================
// slim pure-fp16 GEMM (TERMS=1 equivalent): C = (Ah@Bh^T)*alpha + bias.
// Only hi arrays in smem (15KB/stage), 3 CTAs/SM target.
// =====================================================================
__global__ void __launch_bounds__(256, 3) hgemm16_t1(
    const uint32_t* __restrict__ Ah, const uint32_t* __restrict__ Bh,
    const float* __restrict__ bias, float* __restrict__ C,
    int M, int N, int K, float alpha)
{
    const int bm = blockIdx.y * 128, bn = blockIdx.x * 64;
    extern __shared__ uint32_t dsm[];
    const int tid  = threadIdx.x;
    const int lane = tid & 31;
    const int warp = tid >> 5;
    const int wm = warp >> 1, wn = warp & 1;
    const int g  = lane >> 2, t4 = lane & 3;
    const int lrow = lane & 7, seg = lane >> 3;
    const int Kp = K >> 1;

    float accM[2][4][4];
#pragma unroll
    for (int i = 0; i < 2; i++)
#pragma unroll
        for (int j = 0; j < 4; j++)
#pragma unroll
            for (int q = 0; q < 4; q++) accM[i][j][q] = 0.f;

    const int chA = tid & 3;
    const long long brow = bn + (tid >> 2 & 63);

    auto issue_tile = [&](int kt) {
        uint32_t* AhS = dsm + (kt % NSTAGE) * STG1S;
        uint32_t* BhS = AhS + PASZ;
        const long long kpbase = (long long)kt * KPT;
#pragma unroll
        for (int i = 0; i < 2; i++) {
            int r = (tid + i * 256) >> 2;
            cp16(smem_u32(&AhS[r * PST + chA * 4]),
                 Ah + (long long)(bm + r) * Kp + kpbase + chA * 4);
        }
        cp16(smem_u32(&BhS[(tid >> 2) * PST + chA * 4]),
             Bh + brow * Kp + kpbase + chA * 4);
        CP_COMMIT();
    };

    const int nk = K / 32;
    issue_tile(0);
    if (nk > 1) issue_tile(1);
    for (int kt = 0; kt < nk; kt++) {
        if (kt + 1 < nk) { CP_WAITG(1); }
        else             { CP_WAITG(0); }
        __syncthreads();
        if (kt + 2 < nk) issue_tile(kt + 2);
        const uint32_t* AhS = dsm + (kt % NSTAGE) * STG1S;
        const uint32_t* BhS = AhS + PASZ;
        const int moff = wm * 32, noff = wn * 32;
#pragma unroll
        for (int ks = 0; ks < 2; ks++) {
            const int kb = ks * 8;
            uint32_t aH[2][4], bH[4][2];
            const int akc = kb + ((seg >> 1) << 2);
#pragma unroll
            for (int mt = 0; mt < 2; mt++) {
                int mrow = moff + mt * 16 + lrow + ((seg & 1) << 3);
                LDSM4(aH[mt][0], aH[mt][1], aH[mt][2], aH[mt][3],
                      smem_u32(&AhS[mrow * PST + akc]));
            }
            const int bkc = kb + ((seg & 1) << 2);
#pragma unroll
            for (int nt2 = 0; nt2 < 2; nt2++) {
                int nrow = noff + (nt2 * 2 + (seg >> 1)) * 8 + lrow;
                LDSM4(bH[nt2*2][0], bH[nt2*2][1], bH[nt2*2+1][0], bH[nt2*2+1][1],
                      smem_u32(&BhS[nrow * PST + bkc]));
            }
#pragma unroll
            for (int mt = 0; mt < 2; mt++)
#pragma unroll
                for (int nt = 0; nt < 4; nt++)
                    mma_f16(accM[mt][nt], aH[mt], bH[nt]);
        }
        __syncthreads();
    }

#pragma unroll
    for (int mt = 0; mt < 2; mt++) {
        int lr = wm * 32 + mt * 16 + g;
#pragma unroll
        for (int nt = 0; nt < 4; nt++) {
            int n0 = bn + wn * 32 + nt * 8 + t4 * 2;
            if (n0 >= N) continue;
            float b0v = bias[n0], b1v = bias[n0 + 1];
            long long m0 = bm + lr;
            *(float2*)&C[m0 * N + n0] =
                make_float2(accM[mt][nt][0] * alpha + b0v, accM[mt][nt][1] * alpha + b1v);
            *(float2*)&C[(m0 + 8) * N + n0] =
                make_float2(accM[mt][nt][2] * alpha + b0v, accM[mt][nt][3] * alpha + b1v);
        }
    }
}

// =====================================================================
// transpose+split+pack: W [K,N] fp32 -> Wh/Wl [N][K/2] fp16-pair u32.
// =====================================================================
__global__ void tsp_kernel(const float* __restrict__ W,
                           uint32_t* __restrict__ h, uint32_t* __restrict__ l,
                           int K, int N, long long zsrc, long long zdst) {
    __shared__ float t[32][33];
    const long long so = (long long)blockIdx.z * zsrc;
    const long long dz = (long long)blockIdx.z * zdst;
    const int bk = blockIdx.y * 32, bnn = blockIdx.x * 32;
    const int tx = threadIdx.x, ty = threadIdx.y;
#pragma unroll
    for (int r = 0; r < 4; r++)
        t[ty + r * 8][tx] = W[so + (long long)(bk + ty + r * 8) * N + bnn + tx];
    __syncthreads();
    const int Kp = K >> 1;
#pragma unroll
    for (int r = 0; r < 2; r++) {
        int kpl = ty * 2 + r;
        uint32_t hp, lp;
        sp16pair(t[2 * kpl][tx], t[2 * kpl + 1][tx], hp, lp);
        long long o = dz + (long long)(bnn + tx) * Kp + (bk >> 1) + kpl;
        h[o] = hp;
        l[o] = lp;
    }
}

// ---------------- RoPE tables ----------------
__global__ void rope_init_kernel() {
    int idx = blockIdx.x * blockDim.x + threadIdx.x;
    if (idx >= Sn * HD) return;
    int s = idx >> 6;
    int j = idx & 63;
    int jj = j & 31;
    double inv = pow(10000.0, -((double)(2 * jj)) / 64.0);
    double ang = (double)s * inv;
    g_cos[idx] = (float)cos(ang);
    g_sin[idx] = (float)sin(ang);
}

// ---------------- embedding gather (raw + fp16 pairs) ----------------
__global__ void embed_kernel(const int* __restrict__ ids, const float* __restrict__ table,
                             float* __restrict__ out,
                             uint32_t* __restrict__ oh, uint32_t* __restrict__ ol) {
    int p = blockIdx.x * blockDim.x + threadIdx.x;
    int t = p >> 9;
    int d2 = p & 511;
    const float2 v = *(const float2*)&table[(long long)ids[t] * Dm + 2 * d2];
    *(float2*)&out[(long long)t * Dm + 2 * d2] = v;
    uint32_t hp, lp;
    sp16pair(v.x, v.y, hp, lp);
    oh[p] = hp;
    ol[p] = lp;
}

// ---------------- fast gate: one warp per token ----------------
__global__ void gate_kernel(const float* __restrict__ X, const float* __restrict__ gw,
                            const float* __restrict__ gb, float* __restrict__ out) {
    int t = blockIdx.x * 8 + (threadIdx.x >> 5);
    int lane = threadIdx.x & 31;
    float acc[En];
#pragma unroll
    for (int e = 0; e < En; e++) acc[e] = 0.f;
    const float* xr = X + (long long)t * Dm;
    for (int k = lane; k < Dm; k += 32) {
        float xv = xr[k];
#pragma unroll
        for (int e = 0; e < En; e++) acc[e] += xv * gw[k * En + e];
    }
#pragma unroll
    for (int e = 0; e < En; e++) {
#pragma unroll
        for (int o = 16; o > 0; o >>= 1)
            acc[e] += __shfl_down_sync(0xFFFFFFFF, acc[e], o);
    }
    if (lane == 0) {
#pragma unroll
        for (int e = 0; e < En; e++) out[t * En + e] = acc[e] + gb[e];
    }
}

// ---------------- fused RoPE for Q and K from fused lin ----------------
__global__ void rope_qk_kernel(const float* __restrict__ lin,
                               uint32_t* __restrict__ qh, uint32_t* __restrict__ ql,
                               uint32_t* __restrict__ kh, uint32_t* __restrict__ kl) {
    int idx = blockIdx.x * blockDim.x + threadIdx.x;
    int t = idx >> 9;
    int p = idx & 511;
    int h = p >> 5;
    int d2 = p & 31;
    int b = t >> 9;
    int s = t & 511;
    int d0 = 2 * d2, d1 = d0 + 1;
    float c0v = g_cos[s * 64 + d0], s0v = g_sin[s * 64 + d0];
    float c1v = g_cos[s * 64 + d1], s1v = g_sin[s * 64 + d1];
    long long oi = ((long long)(b * Hn + h) * Sn + s) * 32 + d2;
#pragma unroll
    for (int qk = 0; qk < 2; qk++) {
        const float* row = lin + (long long)t * (3 * Dm) + qk * Dm + h * 64;
        float v0 = row[d0];
        float v1 = row[d1];
        float oth0 = (d0 < 32) ? -row[d0 + 32] : row[d0 - 32];
        float oth1 = (d1 < 32) ? -row[d1 + 32] : row[d1 - 32];
        float o0 = v0 * c0v + oth0 * s0v;
        float o1 = v1 * c1v + oth1 * s1v;
        uint32_t hp, lp;
        sp16pair(o0, o1, hp, lp);
        if (qk == 0) { qh[oi] = hp; ql[oi] = lp; }
        else         { kh[oi] = hp; kl[oi] = lp; }
    }
}

// ---------------- V transpose from fused lin -> vt [bh][d][s-pairs] ----------------
__global__ void v_transpose_kernel(const float* __restrict__ lin,
                                   uint32_t* __restrict__ oh, uint32_t* __restrict__ ol) {
    __shared__ float sm[64][65];
    const int s0 = blockIdx.x * 64;
    const int bh = blockIdx.y;
    const int b = bh >> 4, h = bh & 15;
    const int tid = threadIdx.x;
    for (int i = tid; i < 64 * 64; i += 256) {
        int si = i >> 6, d = i & 63;
        sm[si][d] = lin[(long long)(b * Sn + s0 + si) * (3 * Dm) + 2 * Dm + h * 64 + d];
    }
    __syncthreads();
    for (int i = tid; i < 32 * 64; i += 256) {
        int d = i >> 5, spi = i & 31;
        uint32_t hp, lp;
        sp16pair(sm[2 * spi][d], sm[2 * spi + 1][d], hp, lp);
        long long o = ((long long)bh * 64 + d) * (Sn / 2) + (s0 >> 1) + spi;
        oh[o] = hp;
        ol[o] = lp;
    }
}

// ---------------- row softmax over score pairs (in place) ----------------
__global__ void softmax_pair_kernel(uint32_t* __restrict__ sh, uint32_t* __restrict__ sl,
                                    int causal) {
    int row = blockIdx.x;
    long long base = ((long long)blockIdx.y * Sn + row) * (Sn / 2);
    int tid = threadIdx.x;
    float v0, v1;
    up16pair(sh[base + tid], sl[base + tid], v0, v1);
    if (causal) {
        if (2 * tid > row) v0 = -1e9f;
        if (2 * tid + 1 > row) v1 = -1e9f;
    }
    __shared__ float red[256];
    float m = fmaxf(v0, v1);
    red[tid] = m;
    __syncthreads();
    for (int s = 128; s > 0; s >>= 1) {
        if (tid < s) red[tid] = fmaxf(red[tid], red[tid + s]);
        __syncthreads();
    }
    m = red[0];
    __syncthreads();
    float e0 = expf(v0 - m), e1 = expf(v1 - m);
    red[tid] = e0 + e1;
    __syncthreads();
    for (int s = 128; s > 0; s >>= 1) {
        if (tid < s) red[tid] += red[tid + s];
        __syncthreads();
    }
    float inv = 1.f / red[0];
    uint32_t hp, lp;
    sp16pair(e0 * inv, e1 * inv, hp, lp);
    sh[base + tid] = hp;
    sl[base + tid] = lp;
}

// ---------------- fused residual add(+add2) + layernorm ----------------
__global__ void add_ln_kernel(const float* __restrict__ x, const float* __restrict__ a,
                              const float* __restrict__ a2,
                              const float* __restrict__ g, const float* __restrict__ b,
                              float* __restrict__ out,
                              uint32_t* __restrict__ oh, uint32_t* __restrict__ ol) {
    int t = blockIdx.x;
    int tid = threadIdx.x;
    long long base = (long long)t * Dm;
    int c0 = tid * 4;
    float v[4];
#pragma unroll
    for (int i = 0; i < 4; i++) {
        float s = x[base + c0 + i] + a[base + c0 + i];
        if (a2) s += a2[base + c0 + i];
        v[i] = s;
    }
    __shared__ float red[256];
    red[tid] = v[0] + v[1] + v[2] + v[3];
    __syncthreads();
    for (int k = 128; k > 0; k >>= 1) {
        if (tid < k) red[tid] += red[tid + k];
        __syncthreads();
    }
    float mu = red[0] * (1.f / Dm);
    __syncthreads();
    float q = 0.f;
#pragma unroll
    for (int i = 0; i < 4; i++) { float d = v[i] - mu; q += d * d; }
    red[tid] = q;
    __syncthreads();
    for (int k = 128; k > 0; k >>= 1) {
        if (tid < k) red[tid] += red[tid + k];
        __syncthreads();
    }
    float var = red[0] * (1.f / Dm);
    float inv = rsqrtf(var + 1e-5f);
    float o[4];
#pragma unroll
    for (int i = 0; i < 4; i++)
        o[i] = (v[i] - mu) * inv * g[c0 + i] + b[c0 + i];
    *(float4*)&out[base + c0] = make_float4(o[0], o[1], o[2], o[3]);
    long long pb = (long long)t * (Dm / 2) + tid * 2;
    uint32_t hp, lp;
    sp16pair(o[0], o[1], hp, lp);
    oh[pb] = hp;
    ol[pb] = lp;
    sp16pair(o[2], o[3], hp, lp);
    oh[pb + 1] = hp;
    ol[pb + 1] = lp;
}

// ---------------- MoE gating ----------------
__global__ void zero_cnt_kernel(int* c) { if (threadIdx.x < En) c[threadIdx.x] = 0; }

__global__ void gate_route_kernel(const float* __restrict__ logits, float* __restrict__ topw,
                                  int* __restrict__ list, int* __restrict__ cnt) {
    int t = blockIdx.x * blockDim.x + threadIdx.x;
    if (t >= TOK) return;
    float p[En];
    float m = -1e30f;
#pragma unroll
    for (int e = 0; e < En; e++) { p[e] = logits[t * En + e]; m = fmaxf(m, p[e]); }
    float s = 0.f;
#pragma unroll
    for (int e = 0; e < En; e++) { p[e] = expf(p[e] - m); s += p[e]; }
    float invs = 1.f / s;
#pragma unroll
    for (int e = 0; e < En; e++) p[e] *= invs;
    int i0 = 0;
#pragma unroll
    for (int e = 1; e < En; e++) if (p[e] > p[i0]) i0 = e;
    int i1 = (i0 == 0) ? 1 : 0;
#pragma unroll
    for (int e = 0; e < En; e++) if (e != i0 && p[e] > p[i1]) i1 = e;
    float s2 = p[i0] + p[i1];
    topw[t * 2 + 0] = p[i0] / s2;
    topw[t * 2 + 1] = p[i1] / s2;
    int pos = atomicAdd(&cnt[i0], 1);
    list[i0 * TOK + pos] = t * 2 + 0;
    pos = atomicAdd(&cnt[i1], 1);
    list[i1 * TOK + pos] = t * 2 + 1;
}

// ================= host orchestration =================
struct DevPtrs {
    float *x, *y, *lin, *proj, *moe0, *moe1, *gate, *topw;
    uint32_t *xh, *xl, *yh, *yl, *qph, *qpl, *kph, *kpl, *vth, *vtl;
    uint32_t *sph, *spl, *atth, *attl, *h1h, *h1l, *wth, *wtl;
    int *list, *cnt;
};

static void tsp(const float* W, uint32_t* h, uint32_t* l, int K, int N, int batch,
                long long zsrc, long long zdst) {
    dim3 g(N / 32, K / 32, batch);
    tsp_kernel<<<g, dim3(32, 8)>>>(W, h, l, K, N, zsrc, zdst);
}

template<int TERMS>
static void wgemm_t(const uint32_t* Ah, const uint32_t* Al,
                    const uint32_t* Bh, const uint32_t* Bl,
                    const float* bias, float* C, int M, int N, int K,
                    float alpha = 1.f, int batch = 1,
                    long long sA = 0, long long sB = 0, long long sC = 0) {
    dim3 g((N + 63) / 64, M / 128, batch);
    hgemm16<0, TERMS><<<g, 256, SMEM16_BYTES>>>(Ah, Al, Bh, Bl, bias, C,
                                                nullptr, nullptr, nullptr, nullptr, nullptr,
                                                nullptr, nullptr, M, N, K, alpha, sA, sB, sC);
}

static void run_mha(DevPtrs& P, float* xio, uint32_t* xh, uint32_t* xl,
                    const uint32_t* kvh, const uint32_t* kvl,
                    const float* wqkv, const float* bqkv,
                    const float* wo, const float* bo,
                    const float* lng, const float* lnb, int causal) {
    tsp(wqkv, P.wth, P.wtl, Dm, Dm, 3, (long long)Dm * Dm, (long long)Dm * Dm / 2);
    {
        // fused QKV (N=3072): self uses MODE0; cross uses MODE5 (dual-A)
        dim3 g(3 * Dm / 64, TOK / 128, 1);
        if (kvh == xh) {
            hgemm16<0, 3><<<g, 256, SMEM16_BYTES>>>(xh, xl, P.wth, P.wtl, bqkv, P.lin,
                nullptr, nullptr, nullptr, nullptr, nullptr, nullptr, nullptr,
                TOK, 3 * Dm, Dm, 1.f, 0, 0, 0);
        } else {
            hgemm16<5, 3><<<g, 256, SMEM16_BYTES>>>(xh, xl, P.wth, P.wtl, bqkv, P.lin,
                nullptr, nullptr, (float*)kvh, (float*)kvl, nullptr, nullptr, nullptr,
                TOK, 3 * Dm, Dm, 1.f, 0, 0, 0);
        }
    }
    int nbp = (TOK * Dm / 2) / 256;
    rope_qk_kernel<<<nbp, 256>>>(P.lin, P.qph, P.qpl, P.kph, P.kpl);
    v_transpose_kernel<<<dim3(Sn / 64, BH), 256>>>(P.lin, P.vth, P.vtl);
    {
        dim3 g(Sn / 64, Sn / 128, BH);
        hgemm16<4, 3><<<g, 256, SMEM16_BYTES>>>(P.qph, P.qpl, P.kph, P.kpl,
            nullptr, nullptr, P.sph, P.spl, nullptr, nullptr, nullptr, nullptr, nullptr,
            Sn, Sn, HD, 0.125f,
            (long long)Sn * 32, (long long)Sn * 32, (long long)Sn * (Sn / 2));
    }
    softmax_pair_kernel<<<dim3(Sn, BH), 256>>>(P.sph, P.spl, causal);
    {
        dim3 g(1, Sn / 128, BH);
        hgemm16<3, 3><<<g, 256, SMEM16_BYTES>>>(P.sph, P.spl, P.vth, P.vtl,
            nullptr, nullptr, P.atth, P.attl, nullptr, nullptr, nullptr, nullptr, nullptr,
            Sn, HD, Sn, 1.f,
            (long long)Sn * (Sn / 2), (long long)64 * (Sn / 2), 0);
    }
    tsp(wo, P.wth, P.wtl, Dm, Dm, 1, 0, 0);
    wgemm_t<2>(P.atth, P.attl, P.wth, P.wtl, bo, P.proj, TOK, Dm, Dm);
    add_ln_kernel<<<TOK, 256>>>(xio, P.proj, nullptr, lng, lnb, xio, xh, xl);
}

static void run_moe(DevPtrs& P, float* xio, uint32_t* xh, uint32_t* xl,
                    const float* gw, const float* gb,
                    const float* w1, const float* b1, const float* w2, const float* b2,
                    const float* lng, const float* lnb) {
    gate_kernel<<<TOK / 8, 256>>>(xio, gw, gb, P.gate);
    zero_cnt_kernel<<<1, 32>>>(P.cnt);
    gate_route_kernel<<<TOK / 256, 256>>>(P.gate, P.topw, P.list, P.cnt);
    tsp(w1, P.wth, P.wtl, Dm, FF, En, (long long)Dm * FF, (long long)Dm * FF / 2);
    {
        dim3 g(FF / 64, TOK / 128, En);
        hgemm16<1, 3><<<g, 256, SMEM16_BYTES>>>(
            xh, xl, P.wth, P.wtl, b1, nullptr, P.h1h, P.h1l,
            nullptr, nullptr, nullptr, P.list, P.cnt,
            TOK, FF, Dm, 1.f, 0, (long long)Dm * FF / 2, (long long)TOK * FF / 2);
    }
    tsp(w2, P.wth, P.wtl, FF, Dm, En, (long long)FF * Dm, (long long)FF * Dm / 2);
    {
        dim3 g(Dm / 64, TOK / 128, En);
        hgemm16<2, 3><<<g, 256, SMEM16_BYTES>>>(
            P.h1h, P.h1l, P.wth, P.wtl, b2, nullptr, nullptr, nullptr,
            P.moe0, P.moe1, P.topw, P.list, P.cnt,
            TOK, Dm, FF, 1.f, (long long)TOK * FF / 2, (long long)FF * Dm / 2, 0);
    }
    add_ln_kernel<<<TOK, 256>>>(xio, P.moe0, P.moe1, lng, lnb, xio, xh, xl);
}

extern "C" void kernel_launch(void* const* d_in, const int* in_sizes, int n_in,
                              void* d_out, int out_size) {
    (void)in_sizes; (void)n_in; (void)out_size;
    const int*   src           = (const int*)  d_in[0];
    const int*   tgt           = (const int*)  d_in[1];
    const float* emb_src       = (const float*)d_in[2];
    const float* emb_tgt       = (const float*)d_in[3];
    const float* enc_wqkv      = (const float*)d_in[4];
    const float* enc_bqkv      = (const float*)d_in[5];
    const float* enc_wo        = (const float*)d_in[6];
    const float* enc_bo        = (const float*)d_in[7];
    const float* enc_gate_w    = (const float*)d_in[8];
    const float* enc_gate_b    = (const float*)d_in[9];
    const float* enc_w1        = (const float*)d_in[10];
    const float* enc_b1        = (const float*)d_in[11];
    const float* enc_w2        = (const float*)d_in[12];
    const float* enc_b2        = (const float*)d_in[13];
    const float* enc_ln        = (const float*)d_in[14];
    const float* dec_self_wqkv = (const float*)d_in[15];
    const float* dec_self_bqkv = (const float*)d_in[16];
    const float* dec_self_wo   = (const float*)d_in[17];
    const float* dec_self_bo   = (const float*)d_in[18];
    const float* dec_cross_wqkv= (const float*)d_in[19];
    const float* dec_cross_bqkv= (const float*)d_in[20];
    const float* dec_cross_wo  = (const float*)d_in[21];
    const float* dec_cross_bo  = (const float*)d_in[22];
    const float* dec_gate_w    = (const float*)d_in[23];
    const float* dec_gate_b    = (const float*)d_in[24];
    const float* dec_w1        = (const float*)d_in[25];
    const float* dec_b1        = (const float*)d_in[26];
    const float* dec_w2        = (const float*)d_in[27];
    const float* dec_b2        = (const float*)d_in[28];
    const float* dec_ln        = (const float*)d_in[29];
    const float* final_w       = (const float*)d_in[30];
    const float* final_b       = (const float*)d_in[31];
    float* out = (float*)d_out;

    cudaFuncSetAttribute(hgemm16<0,3>, cudaFuncAttributeMaxDynamicSharedMemorySize, SMEM16_BYTES);
    cudaFuncSetAttribute(hgemm16<0,2>, cudaFuncAttributeMaxDynamicSharedMemorySize, SMEM16_BYTES);
    cudaFuncSetAttribute(hgemm16<5,3>, cudaFuncAttributeMaxDynamicSharedMemorySize, SMEM16_BYTES);
    cudaFuncSetAttribute(hgemm16<1,3>, cudaFuncAttributeMaxDynamicSharedMemorySize, SMEM16_BYTES);
    cudaFuncSetAttribute(hgemm16<2,3>, cudaFuncAttributeMaxDynamicSharedMemorySize, SMEM16_BYTES);
    cudaFuncSetAttribute(hgemm16<3,3>, cudaFuncAttributeMaxDynamicSharedMemorySize, SMEM16_BYTES);
    cudaFuncSetAttribute(hgemm16<4,3>, cudaFuncAttributeMaxDynamicSharedMemorySize, SMEM16_BYTES);
    cudaFuncSetAttribute(hgemm16_t1,   cudaFuncAttributeMaxDynamicSharedMemorySize, SMEM1S_BYTES);

    DevPtrs P;
    cudaGetSymbolAddress((void**)&P.x, g_x);
    cudaGetSymbolAddress((void**)&P.y, g_y);
    cudaGetSymbolAddress((void**)&P.xh, g_xh);
    cudaGetSymbolAddress((void**)&P.xl, g_xl);
    cudaGetSymbolAddress((void**)&P.yh, g_yh);
    cudaGetSymbolAddress((void**)&P.yl, g_yl);
    cudaGetSymbolAddress((void**)&P.lin, g_lin);
    cudaGetSymbolAddress((void**)&P.qph, g_qph);
    cudaGetSymbolAddress((void**)&P.qpl, g_qpl);
    cudaGetSymbolAddress((void**)&P.kph, g_kph);
    cudaGetSymbolAddress((void**)&P.kpl, g_kpl);
    cudaGetSymbolAddress((void**)&P.vth, g_vth);
    cudaGetSymbolAddress((void**)&P.vtl, g_vtl);
    cudaGetSymbolAddress((void**)&P.sph, g_sph);
    cudaGetSymbolAddress((void**)&P.spl, g_spl);
    cudaGetSymbolAddress((void**)&P.atth, g_atth);
    cudaGetSymbolAddress((void**)&P.attl, g_attl);
    cudaGetSymbolAddress((void**)&P.proj, g_proj);
    cudaGetSymbolAddress((void**)&P.h1h, g_h1h);
    cudaGetSymbolAddress((void**)&P.h1l, g_h1l);
    cudaGetSymbolAddress((void**)&P.moe0, g_moe0);
    cudaGetSymbolAddress((void**)&P.moe1, g_moe1);
    cudaGetSymbolAddress((void**)&P.gate, g_gate);
    cudaGetSymbolAddress((void**)&P.topw, g_topw);
    cudaGetSymbolAddress((void**)&P.list, g_list);
    cudaGetSymbolAddress((void**)&P.cnt, g_cnt);
    cudaGetSymbolAddress((void**)&P.wth, g_wth);
    cudaGetSymbolAddress((void**)&P.wtl, g_wtl);

    rope_init_kernel<<<(Sn * HD) / 256, 256>>>();

    // ---------- encoder ----------
    embed_kernel<<<(TOK * Dm / 2) / 256, 256>>>(src, emb_src, P.x, P.xh, P.xl);
    for (int l = 0; l < Ln; l++) {
        run_mha(P, P.x, P.xh, P.xl, P.xh, P.xl,
                enc_wqkv + (long long)l * 3 * Dm * Dm, enc_bqkv + l * 3 * Dm,
                enc_wo + (long long)l * Dm * Dm, enc_bo + l * Dm,
                enc_ln + ((l * 2 + 0) * 2 + 0) * Dm, enc_ln + ((l * 2 + 0) * 2 + 1) * Dm, 0);
        run_moe(P, P.x, P.xh, P.xl,
                enc_gate_w + l * Dm * En, enc_gate_b + l * En,
                enc_w1 + (long long)l * En * Dm * FF, enc_b1 + l * En * FF,
                enc_w2 + (long long)l * En * FF * Dm, enc_b2 + l * En * Dm,
                enc_ln + ((l * 2 + 1) * 2 + 0) * Dm, enc_ln + ((l * 2 + 1) * 2 + 1) * Dm);
    }

    // ---------- decoder ----------
    embed_kernel<<<(TOK * Dm / 2) / 256, 256>>>(tgt, emb_tgt, P.y, P.yh, P.yl);
    for (int l = 0; l < Ln; l++) {
        run_mha(P, P.y, P.yh, P.yl, P.yh, P.yl,
                dec_self_wqkv + (long long)l * 3 * Dm * Dm, dec_self_bqkv + l * 3 * Dm,
                dec_self_wo + (long long)l * Dm * Dm, dec_self_bo + l * Dm,
                dec_ln + ((l * 3 + 0) * 2 + 0) * Dm, dec_ln + ((l * 3 + 0) * 2 + 1) * Dm, 1);
        run_mha(P, P.y, P.yh, P.yl, P.xh, P.xl,
                dec_cross_wqkv + (long long)l * 3 * Dm * Dm, dec_cross_bqkv + l * 3 * Dm,
                dec_cross_wo + (long long)l * Dm * Dm, dec_cross_bo + l * Dm,
                dec_ln + ((l * 3 + 1) * 2 + 0) * Dm, dec_ln + ((l * 3 + 1) * 2 + 1) * Dm, 0);
        run_moe(P, P.y, P.yh, P.yl,
                dec_gate_w + l * Dm * En, dec_gate_b + l * En,
                dec_w1 + (long long)l * En * Dm * FF, dec_b1 + l * En * FF,
                dec_w2 + (long long)l * En * FF * Dm, dec_b2 + l * En * Dm,
                dec_ln + ((l * 3 + 2) * 2 + 0) * Dm, dec_ln + ((l * 3 + 2) * 2 + 1) * Dm);
    }

    // ---------- final projection (slim pure-fp16, 3 CTA/SM) ----------
    tsp(final_w, P.wth, P.wtl, Dm, VT, 1, 0, 0);
    {
        dim3 g(VT / 64, TOK / 128, 1);
        hgemm16_t1<<<g, 256, SMEM1S_BYTES>>>(P.yh, P.wth, final_b, out, TOK, VT, Dm, 1.f);
    }
}

// round 17
// speedup vs baseline: 2.0476x; 1.1333x over previous
#include <cuda_runtime.h>
#include <cuda_fp16.h>
#include <math.h>
#include <stdint.h>

// ---------------- problem constants ----------------
#define Bn   4
#define Sn   512
#define Dm   1024
#define Hn   16
#define HD   64
#define En   8
#define FF   2048
#define Ln   2
#define VT   32000
#define TOK  (Bn*Sn)      // 2048 tokens
#define BH   (Bn*Hn)      // 64 attention batches

// ---- fp16-pair GEMM tiling: 256 thr, block 128x64, KT=32 (16 pairs) ----
#define KPT  16
#define PST  20
#define PASZ (128*PST)
#define PBSZ (64*PST)
#define NSTAGE 3
#define SMEM_T3_BYTES (NSTAGE*(2*PASZ+2*PBSZ)*4)   // 92160
#define SMEM_T2_BYTES (NSTAGE*(PASZ+2*PBSZ)*4)     // 61440

// slim pure-fp16 variant: only Ah + Bh per stage
#define STG1S (PASZ + PBSZ)
#define SMEM1S_BYTES (NSTAGE*STG1S*4)              // 46080

// ---------------- device scratch ----------------
__device__ float    g_x[TOK*Dm];
__device__ float    g_y[TOK*Dm];
__device__ uint32_t g_xh[TOK*Dm/2], g_xl[TOK*Dm/2];
__device__ uint32_t g_yh[TOK*Dm/2], g_yl[TOK*Dm/2];
__device__ float    g_lin[(size_t)TOK*3*Dm];
__device__ uint32_t g_qph[TOK*Dm/2], g_qpl[TOK*Dm/2];
__device__ uint32_t g_kph[TOK*Dm/2], g_kpl[TOK*Dm/2];
__device__ uint32_t g_vth[BH*64*(Sn/2)], g_vtl[BH*64*(Sn/2)];
__device__ uint32_t g_sph[(size_t)BH*Sn*(Sn/2)], g_spl[(size_t)BH*Sn*(Sn/2)];
__device__ uint32_t g_atth[TOK*Dm/2], g_attl[TOK*Dm/2];
__device__ float    g_proj[TOK*Dm];
__device__ uint32_t g_h1h[(size_t)En*TOK*FF/2], g_h1l[(size_t)En*TOK*FF/2];
__device__ float    g_moe0[TOK*Dm];
__device__ float    g_moe1[TOK*Dm];
__device__ float    g_gate[TOK*En];
__device__ float    g_topw[TOK*2];
__device__ int      g_list[En*TOK];
__device__ int      g_cnt[En];
__device__ float    g_cos[Sn*HD];
__device__ float    g_sin[Sn*HD];
__device__ uint32_t g_wth[16777216], g_wtl[16777216];   // weight hi/lo pairs [N][K/2]

// ---------------- helpers ----------------
__device__ __forceinline__ void sp16pair(float v0, float v1, uint32_t& hp, uint32_t& lp) {
    __half h0 = __float2half_rn(v0);
    __half h1 = __float2half_rn(v1);
    __half l0 = __float2half_rn((v0 - __half2float(h0)) * 2048.f);
    __half l1 = __float2half_rn((v1 - __half2float(h1)) * 2048.f);
    hp = (uint32_t)__half_as_ushort(h0) | ((uint32_t)__half_as_ushort(h1) << 16);
    lp = (uint32_t)__half_as_ushort(l0) | ((uint32_t)__half_as_ushort(l1) << 16);
}
__device__ __forceinline__ void up16pair(uint32_t hp, uint32_t lp, float& v0, float& v1) {
    const float s = 1.f / 2048.f;
    v0 = __half2float(__ushort_as_half((unsigned short)(hp & 0xFFFF)))
       + __half2float(__ushort_as_half((unsigned short)(lp & 0xFFFF))) * s;
    v1 = __half2float(__ushort_as_half((unsigned short)(hp >> 16)))
       + __half2float(__ushort_as_half((unsigned short)(lp >> 16))) * s;
}
__device__ __forceinline__ uint32_t smem_u32(const void* p) {
    return (uint32_t)__cvta_generic_to_shared(p);
}
__device__ __forceinline__ void cp16(uint32_t dst, const void* src) {
    asm volatile("cp.async.cg.shared.global [%0], [%1], 16;" :: "r"(dst), "l"(src));
}
#define CP_COMMIT() asm volatile("cp.async.commit_group;")
#define CP_WAITG(n) asm volatile("cp.async.wait_group %0;" :: "n"(n))

__device__ __forceinline__ void mma_f16(float* c, const uint32_t* a, const uint32_t* b) {
    asm volatile(
        "mma.sync.aligned.m16n8k16.row.col.f32.f16.f16.f32 "
        "{%0,%1,%2,%3}, {%4,%5,%6,%7}, {%8,%9}, {%0,%1,%2,%3};"
        : "+f"(c[0]), "+f"(c[1]), "+f"(c[2]), "+f"(c[3])
        : "r"(a[0]), "r"(a[1]), "r"(a[2]), "r"(a[3]), "r"(b[0]), "r"(b[1]));
}
#define LDSM4(r0, r1, r2, r3, addr) \
    asm volatile("ldmatrix.sync.aligned.m8n8.x4.shared.b16 {%0,%1,%2,%3}, [%4];" \
                 : "=r"(r0), "=r"(r1), "=r"(r2), "=r"(r3) : "r"(addr))

// =====================================================================
// fp16-pair GEMM. A [M][K/2] pairs, B [N][K/2] pairs, acc = A@B^T.
// TERMS=3: A hi/lo x B hi/lo (both cross terms; near-fp32).
// TERMS=2: drop aL*bH (A fp16-rounded; A lo never loaded; weights keep hi/lo).
// MODE0: fp32 out. MODE1: gather+relu+pack (z=expert). MODE2: scatter*topw.
// MODE3: AV -> att pairs. MODE4: QK -> score pairs.
// MODE5: like MODE0 but dual-A: tiles with bn>=Dm read A2 (via out0/out1).
// =====================================================================
template<int MODE, int TERMS>
__global__ void __launch_bounds__(256, 2) hgemm16(
    const uint32_t* __restrict__ Ah, const uint32_t* __restrict__ Al,
    const uint32_t* __restrict__ Bh, const uint32_t* __restrict__ Bl,
    const float* __restrict__ bias, float* __restrict__ C,
    uint32_t* __restrict__ Oh, uint32_t* __restrict__ Ol,
    float* __restrict__ out0, float* __restrict__ out1, const float* __restrict__ topw,
    const int* __restrict__ list, const int* __restrict__ cnt,
    int M, int Nstore, int K, float alpha,
    long long sAz, long long sBz, long long sCz)
{
    constexpr int NA  = (TERMS == 3) ? 2 : 1;       // A arrays in smem
    constexpr int STG = NA * PASZ + 2 * PBSZ;
    const int z = blockIdx.z;
    const int bm = blockIdx.y * 128, bn = blockIdx.x * 64;
    int nrows = M;
    const int* lst = nullptr;
    if (MODE == 1 || MODE == 2) {
        nrows = cnt[z];
        if (bm >= nrows) return;
        lst = list + z * TOK;
        bias += (long long)z * Nstore;
    }
    if (MODE == 5 && bn >= Dm) {
        Ah = (const uint32_t*)out0;
        Al = (const uint32_t*)out1;
    }
    Ah += (long long)z * sAz;  Al += (long long)z * sAz;
    Bh += (long long)z * sBz;  Bl += (long long)z * sBz;
    if (MODE == 0) C += (long long)z * sCz;
    if (MODE == 1 || MODE == 4) { Oh += (long long)z * sCz; Ol += (long long)z * sCz; }

    extern __shared__ uint32_t dsm[];
    __shared__ int ents[128];
    const int tid  = threadIdx.x;
    const int lane = tid & 31;
    const int warp = tid >> 5;
    const int wm = warp >> 1, wn = warp & 1;
    const int g  = lane >> 2, t4 = lane & 3;
    const int lrow = lane & 7, seg = lane >> 3;
    const int Kp = K >> 1;

    if ((MODE == 1 || MODE == 2) && tid < 128) {
        int gr = bm + tid;
        ents[tid] = (gr < nrows) ? lst[gr] : -1;
    }
    __syncthreads();

    float accM[2][4][4], accC[2][4][4];
#pragma unroll
    for (int i = 0; i < 2; i++)
#pragma unroll
        for (int j = 0; j < 4; j++)
#pragma unroll
            for (int q = 0; q < 4; q++) { accM[i][j][q] = 0.f; accC[i][j][q] = 0.f; }

    long long arow[2];
#pragma unroll
    for (int i = 0; i < 2; i++) {
        int r = (tid + i * 256) >> 2;
        if (MODE == 1) {
            int e = ents[r];
            arow[i] = (e >= 0) ? (long long)(e >> 1) : 0;
        } else {
            arow[i] = bm + r;
        }
    }
    const int chA = tid & 3;
    const long long brow = bn + (tid >> 2 & 63);

    auto issue_tile = [&](int kt) {
        uint32_t* AhS = dsm + (kt % NSTAGE) * STG;
        uint32_t* AlS = AhS + PASZ;
        uint32_t* BhS = AhS + NA * PASZ;
        uint32_t* BlS = BhS + PBSZ;
        const long long kpbase = (long long)kt * KPT;
#pragma unroll
        for (int i = 0; i < 2; i++) {
            int r = (tid + i * 256) >> 2;
            const long long kp0 = kpbase + chA * 4;
            const uint32_t d = r * PST + chA * 4;
            cp16(smem_u32(&AhS[d]), Ah + arow[i] * Kp + kp0);
            if (TERMS == 3) cp16(smem_u32(&AlS[d]), Al + arow[i] * Kp + kp0);
        }
        {
            const long long kp0 = kpbase + chA * 4;
            const uint32_t d = (tid >> 2) * PST + chA * 4;
            cp16(smem_u32(&BhS[d]), Bh + brow * Kp + kp0);
            cp16(smem_u32(&BlS[d]), Bl + brow * Kp + kp0);
        }
        CP_COMMIT();
    };

    const int nk = K / 32;
    issue_tile(0);
    if (nk > 1) issue_tile(1);
    for (int kt = 0; kt < nk; kt++) {
        if (kt + 1 < nk) { CP_WAITG(1); }
        else             { CP_WAITG(0); }
        __syncthreads();
        if (kt + 2 < nk) issue_tile(kt + 2);
        const uint32_t* AhS = dsm + (kt % NSTAGE) * STG;
        const uint32_t* AlS = AhS + PASZ;
        const uint32_t* BhS = AhS + NA * PASZ;
        const uint32_t* BlS = BhS + PBSZ;
        const int moff = wm * 32, noff = wn * 32;
#pragma unroll
        for (int ks = 0; ks < 2; ks++) {
            const int kb = ks * 8;
            uint32_t aH[2][4], aL[2][4], bH[4][2], bL[4][2];
            const int akc = kb + ((seg >> 1) << 2);
#pragma unroll
            for (int mt = 0; mt < 2; mt++) {
                int mrow = moff + mt * 16 + lrow + ((seg & 1) << 3);
                LDSM4(aH[mt][0], aH[mt][1], aH[mt][2], aH[mt][3],
                      smem_u32(&AhS[mrow * PST + akc]));
                if (TERMS == 3)
                    LDSM4(aL[mt][0], aL[mt][1], aL[mt][2], aL[mt][3],
                          smem_u32(&AlS[mrow * PST + akc]));
            }
            const int bkc = kb + ((seg & 1) << 2);
#pragma unroll
            for (int nt2 = 0; nt2 < 2; nt2++) {
                int nrow = noff + (nt2 * 2 + (seg >> 1)) * 8 + lrow;
                LDSM4(bH[nt2*2][0], bH[nt2*2][1], bH[nt2*2+1][0], bH[nt2*2+1][1],
                      smem_u32(&BhS[nrow * PST + bkc]));
                LDSM4(bL[nt2*2][0], bL[nt2*2][1], bL[nt2*2+1][0], bL[nt2*2+1][1],
                      smem_u32(&BlS[nrow * PST + bkc]));
            }
#pragma unroll
            for (int mt = 0; mt < 2; mt++)
#pragma unroll
                for (int nt = 0; nt < 4; nt++) {
                    mma_f16(accM[mt][nt], aH[mt], bH[nt]);
                    mma_f16(accC[mt][nt], aH[mt], bL[nt]);
                    if (TERMS == 3) mma_f16(accC[mt][nt], aL[mt], bH[nt]);
                }
        }
        __syncthreads();
    }

    // ---- epilogue ----
    const float s = 1.f / 2048.f;
#pragma unroll
    for (int mt = 0; mt < 2; mt++) {
        int lr = wm * 32 + mt * 16 + g;
#pragma unroll
        for (int nt = 0; nt < 4; nt++) {
            int n0 = bn + wn * 32 + nt * 8 + t4 * 2;
            if (n0 >= Nstore) continue;
            float b0v = bias ? bias[n0] : 0.f;
            float b1v = bias ? bias[n0 + 1] : 0.f;
            float v0 = (accM[mt][nt][0] + accC[mt][nt][0] * s) * alpha + b0v;
            float v1 = (accM[mt][nt][1] + accC[mt][nt][1] * s) * alpha + b1v;
            float v2 = (accM[mt][nt][2] + accC[mt][nt][2] * s) * alpha + b0v;
            float v3 = (accM[mt][nt][3] + accC[mt][nt][3] * s) * alpha + b1v;
            if (MODE == 0 || MODE == 5) {
                long long m0 = bm + lr;
                *(float2*)&C[m0 * Nstore + n0]       = make_float2(v0, v1);
                *(float2*)&C[(m0 + 8) * Nstore + n0] = make_float2(v2, v3);
            } else if (MODE == 1) {
                if (bm + lr < nrows) {
                    uint32_t hp, lp;
                    sp16pair(fmaxf(v0, 0.f), fmaxf(v1, 0.f), hp, lp);
                    size_t o = (size_t)(bm + lr) * (Nstore >> 1) + (n0 >> 1);
                    Oh[o] = hp; Ol[o] = lp;
                }
                if (bm + lr + 8 < nrows) {
                    uint32_t hp, lp;
                    sp16pair(fmaxf(v2, 0.f), fmaxf(v3, 0.f), hp, lp);
                    size_t o = (size_t)(bm + lr + 8) * (Nstore >> 1) + (n0 >> 1);
                    Oh[o] = hp; Ol[o] = lp;
                }
            } else if (MODE == 2) {
                int e0 = ents[lr], e2 = ents[lr + 8];
                if (e0 >= 0) {
                    float w = topw[e0];
                    float* o = (e0 & 1) ? out1 : out0;
                    long long t = (long long)(e0 >> 1) * Nstore;
                    *(float2*)&o[t + n0] = make_float2(w * v0, w * v1);
                }
                if (e2 >= 0) {
                    float w = topw[e2];
                    float* o = (e2 & 1) ? out1 : out0;
                    long long t = (long long)(e2 >> 1) * Nstore;
                    *(float2*)&o[t + n0] = make_float2(w * v2, w * v3);
                }
            } else if (MODE == 3) {
                int b = z >> 4, h = z & 15;
                long long tok0 = (long long)(b * Sn + bm + lr) * (Dm / 2) + h * 32 + (n0 >> 1);
                long long tok2 = tok0 + 8LL * (Dm / 2);
                uint32_t hp, lp;
                sp16pair(v0, v1, hp, lp);
                Oh[tok0] = hp; Ol[tok0] = lp;
                sp16pair(v2, v3, hp, lp);
                Oh[tok2] = hp; Ol[tok2] = lp;
            } else {
                long long o0 = (long long)(bm + lr) * (Nstore >> 1) + (n0 >> 1);
                long long o2 = o0 + 8LL * (Nstore >> 1);
                uint32_t hp, lp;
                sp16pair(v0, v1, hp, lp);
                Oh[o0] = hp; Ol[o0] = lp;
                sp16pair(v2, v3, hp, lp);
                Oh[o2] = hp; Ol[o2] = lp;
            }
        }
    }
}

// =====================================================================
// slim pure-fp16 GEMM: C = (Ah@Bh^T)*alpha + bias. 3 CTAs/SM.
// =====================================================================
__global__ void __launch_bounds__(256, 3) hgemm16_t1(
    const uint32_t* __restrict__ Ah, const uint32_t* __restrict__ Bh,
    const float* __restrict__ bias, float* __restrict__ C,
    int M, int N, int K, float alpha)
{
    const int bm = blockIdx.y * 128, bn = blockIdx.x * 64;
    extern __shared__ uint32_t dsm[];
    const int tid  = threadIdx.x;
    const int lane = tid & 31;
    const int warp = tid >> 5;
    const int wm = warp >> 1, wn = warp & 1;
    const int g  = lane >> 2, t4 = lane & 3;
    const int lrow = lane & 7, seg = lane >> 3;
    const int Kp = K >> 1;

    float accM[2][4][4];
#pragma unroll
    for (int i = 0; i < 2; i++)
#pragma unroll
        for (int j = 0; j < 4; j++)
#pragma unroll
            for (int q = 0; q < 4; q++) accM[i][j][q] = 0.f;

    const int chA = tid & 3;
    const long long brow = bn + (tid >> 2 & 63);

    auto issue_tile = [&](int kt) {
        uint32_t* AhS = dsm + (kt % NSTAGE) * STG1S;
        uint32_t* BhS = AhS + PASZ;
        const long long kpbase = (long long)kt * KPT;
#pragma unroll
        for (int i = 0; i < 2; i++) {
            int r = (tid + i * 256) >> 2;
            cp16(smem_u32(&AhS[r * PST + chA * 4]),
                 Ah + (long long)(bm + r) * Kp + kpbase + chA * 4);
        }
        cp16(smem_u32(&BhS[(tid >> 2) * PST + chA * 4]),
             Bh + brow * Kp + kpbase + chA * 4);
        CP_COMMIT();
    };

    const int nk = K / 32;
    issue_tile(0);
    if (nk > 1) issue_tile(1);
    for (int kt = 0; kt < nk; kt++) {
        if (kt + 1 < nk) { CP_WAITG(1); }
        else             { CP_WAITG(0); }
        __syncthreads();
        if (kt + 2 < nk) issue_tile(kt + 2);
        const uint32_t* AhS = dsm + (kt % NSTAGE) * STG1S;
        const uint32_t* BhS = AhS + PASZ;
        const int moff = wm * 32, noff = wn * 32;
#pragma unroll
        for (int ks = 0; ks < 2; ks++) {
            const int kb = ks * 8;
            uint32_t aH[2][4], bH[4][2];
            const int akc = kb + ((seg >> 1) << 2);
#pragma unroll
            for (int mt = 0; mt < 2; mt++) {
                int mrow = moff + mt * 16 + lrow + ((seg & 1) << 3);
                LDSM4(aH[mt][0], aH[mt][1], aH[mt][2], aH[mt][3],
                      smem_u32(&AhS[mrow * PST + akc]));
            }
            const int bkc = kb + ((seg & 1) << 2);
#pragma unroll
            for (int nt2 = 0; nt2 < 2; nt2++) {
                int nrow = noff + (nt2 * 2 + (seg >> 1)) * 8 + lrow;
                LDSM4(bH[nt2*2][0], bH[nt2*2][1], bH[nt2*2+1][0], bH[nt2*2+1][1],
                      smem_u32(&BhS[nrow * PST + bkc]));
            }
#pragma unroll
            for (int mt = 0; mt < 2; mt++)
#pragma unroll
                for (int nt = 0; nt < 4; nt++)
                    mma_f16(accM[mt][nt], aH[mt], bH[nt]);
        }
        __syncthreads();
    }

#pragma unroll
    for (int mt = 0; mt < 2; mt++) {
        int lr = wm * 32 + mt * 16 + g;
#pragma unroll
        for (int nt = 0; nt < 4; nt++) {
            int n0 = bn + wn * 32 + nt * 8 + t4 * 2;
            if (n0 >= N) continue;
            float b0v = bias[n0], b1v = bias[n0 + 1];
            long long m0 = bm + lr;
            *(float2*)&C[m0 * N + n0] =
                make_float2(accM[mt][nt][0] * alpha + b0v, accM[mt][nt][1] * alpha + b1v);
            *(float2*)&C[(m0 + 8) * N + n0] =
                make_float2(accM[mt][nt][2] * alpha + b0v, accM[mt][nt][3] * alpha + b1v);
        }
    }
}

// =====================================================================
// transpose+split+pack: W [K,N] fp32 -> Wh/Wl [N][K/2] fp16-pair u32.
// =====================================================================
__global__ void tsp_kernel(const float* __restrict__ W,
                           uint32_t* __restrict__ h, uint32_t* __restrict__ l,
                           int K, int N, long long zsrc, long long zdst) {
    __shared__ float t[32][33];
    const long long so = (long long)blockIdx.z * zsrc;
    const long long dz = (long long)blockIdx.z * zdst;
    const int bk = blockIdx.y * 32, bnn = blockIdx.x * 32;
    const int tx = threadIdx.x, ty = threadIdx.y;
#pragma unroll
    for (int r = 0; r < 4; r++)
        t[ty + r * 8][tx] = W[so + (long long)(bk + ty + r * 8) * N + bnn + tx];
    __syncthreads();
    const int Kp = K >> 1;
#pragma unroll
    for (int r = 0; r < 2; r++) {
        int kpl = ty * 2 + r;
        uint32_t hp, lp;
        sp16pair(t[2 * kpl][tx], t[2 * kpl + 1][tx], hp, lp);
        long long o = dz + (long long)(bnn + tx) * Kp + (bk >> 1) + kpl;
        h[o] = hp;
        l[o] = lp;
    }
}

// ---------------- RoPE tables ----------------
__global__ void rope_init_kernel() {
    int idx = blockIdx.x * blockDim.x + threadIdx.x;
    if (idx >= Sn * HD) return;
    int s = idx >> 6;
    int j = idx & 63;
    int jj = j & 31;
    double inv = pow(10000.0, -((double)(2 * jj)) / 64.0);
    double ang = (double)s * inv;
    g_cos[idx] = (float)cos(ang);
    g_sin[idx] = (float)sin(ang);
}

// ---------------- embedding gather (raw + fp16 pairs) ----------------
__global__ void embed_kernel(const int* __restrict__ ids, const float* __restrict__ table,
                             float* __restrict__ out,
                             uint32_t* __restrict__ oh, uint32_t* __restrict__ ol) {
    int p = blockIdx.x * blockDim.x + threadIdx.x;
    int t = p >> 9;
    int d2 = p & 511;
    const float2 v = *(const float2*)&table[(long long)ids[t] * Dm + 2 * d2];
    *(float2*)&out[(long long)t * Dm + 2 * d2] = v;
    uint32_t hp, lp;
    sp16pair(v.x, v.y, hp, lp);
    oh[p] = hp;
    ol[p] = lp;
}

// ---------------- fast gate: one warp per token ----------------
__global__ void gate_kernel(const float* __restrict__ X, const float* __restrict__ gw,
                            const float* __restrict__ gb, float* __restrict__ out) {
    int t = blockIdx.x * 8 + (threadIdx.x >> 5);
    int lane = threadIdx.x & 31;
    float acc[En];
#pragma unroll
    for (int e = 0; e < En; e++) acc[e] = 0.f;
    const float* xr = X + (long long)t * Dm;
    for (int k = lane; k < Dm; k += 32) {
        float xv = xr[k];
#pragma unroll
        for (int e = 0; e < En; e++) acc[e] += xv * gw[k * En + e];
    }
#pragma unroll
    for (int e = 0; e < En; e++) {
#pragma unroll
        for (int o = 16; o > 0; o >>= 1)
            acc[e] += __shfl_down_sync(0xFFFFFFFF, acc[e], o);
    }
    if (lane == 0) {
#pragma unroll
        for (int e = 0; e < En; e++) out[t * En + e] = acc[e] + gb[e];
    }
}

// ---------------- fused RoPE for Q and K from fused lin ----------------
__global__ void rope_qk_kernel(const float* __restrict__ lin,
                               uint32_t* __restrict__ qh, uint32_t* __restrict__ ql,
                               uint32_t* __restrict__ kh, uint32_t* __restrict__ kl) {
    int idx = blockIdx.x * blockDim.x + threadIdx.x;
    int t = idx >> 9;
    int p = idx & 511;
    int h = p >> 5;
    int d2 = p & 31;
    int b = t >> 9;
    int s = t & 511;
    int d0 = 2 * d2, d1 = d0 + 1;
    float c0v = g_cos[s * 64 + d0], s0v = g_sin[s * 64 + d0];
    float c1v = g_cos[s * 64 + d1], s1v = g_sin[s * 64 + d1];
    long long oi = ((long long)(b * Hn + h) * Sn + s) * 32 + d2;
#pragma unroll
    for (int qk = 0; qk < 2; qk++) {
        const float* row = lin + (long long)t * (3 * Dm) + qk * Dm + h * 64;
        float v0 = row[d0];
        float v1 = row[d1];
        float oth0 = (d0 < 32) ? -row[d0 + 32] : row[d0 - 32];
        float oth1 = (d1 < 32) ? -row[d1 + 32] : row[d1 - 32];
        float o0 = v0 * c0v + oth0 * s0v;
        float o1 = v1 * c1v + oth1 * s1v;
        uint32_t hp, lp;
        sp16pair(o0, o1, hp, lp);
        if (qk == 0) { qh[oi] = hp; ql[oi] = lp; }
        else         { kh[oi] = hp; kl[oi] = lp; }
    }
}

// ---------------- V transpose from fused lin -> vt [bh][d][s-pairs] ----------------
__global__ void v_transpose_kernel(const float* __restrict__ lin,
                                   uint32_t* __restrict__ oh, uint32_t* __restrict__ ol) {
    __shared__ float sm[64][65];
    const int s0 = blockIdx.x * 64;
    const int bh = blockIdx.y;
    const int b = bh >> 4, h = bh & 15;
    const int tid = threadIdx.x;
    for (int i = tid; i < 64 * 64; i += 256) {
        int si = i >> 6, d = i & 63;
        sm[si][d] = lin[(long long)(b * Sn + s0 + si) * (3 * Dm) + 2 * Dm + h * 64 + d];
    }
    __syncthreads();
    for (int i = tid; i < 32 * 64; i += 256) {
        int d = i >> 5, spi = i & 31;
        uint32_t hp, lp;
        sp16pair(sm[2 * spi][d], sm[2 * spi + 1][d], hp, lp);
        long long o = ((long long)bh * 64 + d) * (Sn / 2) + (s0 >> 1) + spi;
        oh[o] = hp;
        ol[o] = lp;
    }
}

// ---------------- row softmax over score pairs (in place) ----------------
__global__ void softmax_pair_kernel(uint32_t* __restrict__ sh, uint32_t* __restrict__ sl,
                                    int causal) {
    int row = blockIdx.x;
    long long base = ((long long)blockIdx.y * Sn + row) * (Sn / 2);
    int tid = threadIdx.x;
    float v0, v1;
    up16pair(sh[base + tid], sl[base + tid], v0, v1);
    if (causal) {
        if (2 * tid > row) v0 = -1e9f;
        if (2 * tid + 1 > row) v1 = -1e9f;
    }
    __shared__ float red[256];
    float m = fmaxf(v0, v1);
    red[tid] = m;
    __syncthreads();
    for (int s = 128; s > 0; s >>= 1) {
        if (tid < s) red[tid] = fmaxf(red[tid], red[tid + s]);
        __syncthreads();
    }
    m = red[0];
    __syncthreads();
    float e0 = expf(v0 - m), e1 = expf(v1 - m);
    red[tid] = e0 + e1;
    __syncthreads();
    for (int s = 128; s > 0; s >>= 1) {
        if (tid < s) red[tid] += red[tid + s];
        __syncthreads();
    }
    float inv = 1.f / red[0];
    uint32_t hp, lp;
    sp16pair(e0 * inv, e1 * inv, hp, lp);
    sh[base + tid] = hp;
    sl[base + tid] = lp;
}

// ---------------- fused residual add(+add2) + layernorm ----------------
__global__ void add_ln_kernel(const float* __restrict__ x, const float* __restrict__ a,
                              const float* __restrict__ a2,
                              const float* __restrict__ g, const float* __restrict__ b,
                              float* __restrict__ out,
                              uint32_t* __restrict__ oh, uint32_t* __restrict__ ol) {
    int t = blockIdx.x;
    int tid = threadIdx.x;
    long long base = (long long)t * Dm;
    int c0 = tid * 4;
    float v[4];
#pragma unroll
    for (int i = 0; i < 4; i++) {
        float s = x[base + c0 + i] + a[base + c0 + i];
        if (a2) s += a2[base + c0 + i];
        v[i] = s;
    }
    __shared__ float red[256];
    red[tid] = v[0] + v[1] + v[2] + v[3];
    __syncthreads();
    for (int k = 128; k > 0; k >>= 1) {
        if (tid < k) red[tid] += red[tid + k];
        __syncthreads();
    }
    float mu = red[0] * (1.f / Dm);
    __syncthreads();
    float q = 0.f;
#pragma unroll
    for (int i = 0; i < 4; i++) { float d = v[i] - mu; q += d * d; }
    red[tid] = q;
    __syncthreads();
    for (int k = 128; k > 0; k >>= 1) {
        if (tid < k) red[tid] += red[tid + k];
        __syncthreads();
    }
    float var = red[0] * (1.f / Dm);
    float inv = rsqrtf(var + 1e-5f);
    float o[4];
#pragma unroll
    for (int i = 0; i < 4; i++)
        o[i] = (v[i] - mu) * inv * g[c0 + i] + b[c0 + i];
    *(float4*)&out[base + c0] = make_float4(o[0], o[1], o[2], o[3]);
    long long pb = (long long)t * (Dm / 2) + tid * 2;
    uint32_t hp, lp;
    sp16pair(o[0], o[1], hp, lp);
    oh[pb] = hp;
    ol[pb] = lp;
    sp16pair(o[2], o[3], hp, lp);
    oh[pb + 1] = hp;
    ol[pb + 1] = lp;
}

// ---------------- MoE gating ----------------
__global__ void zero_cnt_kernel(int* c) { if (threadIdx.x < En) c[threadIdx.x] = 0; }

__global__ void gate_route_kernel(const float* __restrict__ logits, float* __restrict__ topw,
                                  int* __restrict__ list, int* __restrict__ cnt) {
    int t = blockIdx.x * blockDim.x + threadIdx.x;
    if (t >= TOK) return;
    float p[En];
    float m = -1e30f;
#pragma unroll
    for (int e = 0; e < En; e++) { p[e] = logits[t * En + e]; m = fmaxf(m, p[e]); }
    float s = 0.f;
#pragma unroll
    for (int e = 0; e < En; e++) { p[e] = expf(p[e] - m); s += p[e]; }
    float invs = 1.f / s;
#pragma unroll
    for (int e = 0; e < En; e++) p[e] *= invs;
    int i0 = 0;
#pragma unroll
    for (int e = 1; e < En; e++) if (p[e] > p[i0]) i0 = e;
    int i1 = (i0 == 0) ? 1 : 0;
#pragma unroll
    for (int e = 0; e < En; e++) if (e != i0 && p[e] > p[i1]) i1 = e;
    float s2 = p[i0] + p[i1];
    topw[t * 2 + 0] = p[i0] / s2;
    topw[t * 2 + 1] = p[i1] / s2;
    int pos = atomicAdd(&cnt[i0], 1);
    list[i0 * TOK + pos] = t * 2 + 0;
    pos = atomicAdd(&cnt[i1], 1);
    list[i1 * TOK + pos] = t * 2 + 1;
}

// ================= host orchestration =================
struct DevPtrs {
    float *x, *y, *lin, *proj, *moe0, *moe1, *gate, *topw;
    uint32_t *xh, *xl, *yh, *yl, *qph, *qpl, *kph, *kpl, *vth, *vtl;
    uint32_t *sph, *spl, *atth, *attl, *h1h, *h1l, *wth, *wtl;
    int *list, *cnt;
};

static void tsp(const float* W, uint32_t* h, uint32_t* l, int K, int N, int batch,
                long long zsrc, long long zdst) {
    dim3 g(N / 32, K / 32, batch);
    tsp_kernel<<<g, dim3(32, 8)>>>(W, h, l, K, N, zsrc, zdst);
}

static void run_mha(DevPtrs& P, float* xio, uint32_t* xh, uint32_t* xl,
                    const uint32_t* kvh, const uint32_t* kvl,
                    const float* wqkv, const float* bqkv,
                    const float* wo, const float* bo,
                    const float* lng, const float* lnb, int causal) {
    tsp(wqkv, P.wth, P.wtl, Dm, Dm, 3, (long long)Dm * Dm, (long long)Dm * Dm / 2);
    {
        // fused QKV (N=3072), TERMS=2 (A hi only, weights hi/lo)
        dim3 g(3 * Dm / 64, TOK / 128, 1);
        if (kvh == xh) {
            hgemm16<0, 2><<<g, 256, SMEM_T2_BYTES>>>(xh, xl, P.wth, P.wtl, bqkv, P.lin,
                nullptr, nullptr, nullptr, nullptr, nullptr, nullptr, nullptr,
                TOK, 3 * Dm, Dm, 1.f, 0, 0, 0);
        } else {
            hgemm16<5, 2><<<g, 256, SMEM_T2_BYTES>>>(xh, xl, P.wth, P.wtl, bqkv, P.lin,
                nullptr, nullptr, (float*)kvh, (float*)kvl, nullptr, nullptr, nullptr,
                TOK, 3 * Dm, Dm, 1.f, 0, 0, 0);
        }
    }
    int nbp = (TOK * Dm / 2) / 256;
    rope_qk_kernel<<<nbp, 256>>>(P.lin, P.qph, P.qpl, P.kph, P.kpl);
    v_transpose_kernel<<<dim3(Sn / 64, BH), 256>>>(P.lin, P.vth, P.vtl);
    {
        dim3 g(Sn / 64, Sn / 128, BH);
        hgemm16<4, 3><<<g, 256, SMEM_T3_BYTES>>>(P.qph, P.qpl, P.kph, P.kpl,
            nullptr, nullptr, P.sph, P.spl, nullptr, nullptr, nullptr, nullptr, nullptr,
            Sn, Sn, HD, 0.125f,
            (long long)Sn * 32, (long long)Sn * 32, (long long)Sn * (Sn / 2));
    }
    softmax_pair_kernel<<<dim3(Sn, BH), 256>>>(P.sph, P.spl, causal);
    {
        dim3 g(1, Sn / 128, BH);
        hgemm16<3, 3><<<g, 256, SMEM_T3_BYTES>>>(P.sph, P.spl, P.vth, P.vtl,
            nullptr, nullptr, P.atth, P.attl, nullptr, nullptr, nullptr, nullptr, nullptr,
            Sn, HD, Sn, 1.f,
            (long long)Sn * (Sn / 2), (long long)64 * (Sn / 2), 0);
    }
    tsp(wo, P.wth, P.wtl, Dm, Dm, 1, 0, 0);
    {
        dim3 g(Dm / 64, TOK / 128, 1);
        hgemm16<0, 2><<<g, 256, SMEM_T2_BYTES>>>(P.atth, P.attl, P.wth, P.wtl, bo, P.proj,
            nullptr, nullptr, nullptr, nullptr, nullptr, nullptr, nullptr,
            TOK, Dm, Dm, 1.f, 0, 0, 0);
    }
    add_ln_kernel<<<TOK, 256>>>(xio, P.proj, nullptr, lng, lnb, xio, xh, xl);
}

static void run_moe(DevPtrs& P, float* xio, uint32_t* xh, uint32_t* xl,
                    const float* gw, const float* gb,
                    const float* w1, const float* b1, const float* w2, const float* b2,
                    const float* lng, const float* lnb) {
    gate_kernel<<<TOK / 8, 256>>>(xio, gw, gb, P.gate);
    zero_cnt_kernel<<<1, 32>>>(P.cnt);
    gate_route_kernel<<<TOK / 256, 256>>>(P.gate, P.topw, P.list, P.cnt);
    tsp(w1, P.wth, P.wtl, Dm, FF, En, (long long)Dm * FF, (long long)Dm * FF / 2);
    {
        dim3 g(FF / 64, TOK / 128, En);
        hgemm16<1, 2><<<g, 256, SMEM_T2_BYTES>>>(
            xh, xl, P.wth, P.wtl, b1, nullptr, P.h1h, P.h1l,
            nullptr, nullptr, nullptr, P.list, P.cnt,
            TOK, FF, Dm, 1.f, 0, (long long)Dm * FF / 2, (long long)TOK * FF / 2);
    }
    tsp(w2, P.wth, P.wtl, FF, Dm, En, (long long)FF * Dm, (long long)FF * Dm / 2);
    {
        dim3 g(Dm / 64, TOK / 128, En);
        hgemm16<2, 2><<<g, 256, SMEM_T2_BYTES>>>(
            P.h1h, P.h1l, P.wth, P.wtl, b2, nullptr, nullptr, nullptr,
            P.moe0, P.moe1, P.topw, P.list, P.cnt,
            TOK, Dm, FF, 1.f, (long long)TOK * FF / 2, (long long)FF * Dm / 2, 0);
    }
    add_ln_kernel<<<TOK, 256>>>(xio, P.moe0, P.moe1, lng, lnb, xio, xh, xl);
}

extern "C" void kernel_launch(void* const* d_in, const int* in_sizes, int n_in,
                              void* d_out, int out_size) {
    (void)in_sizes; (void)n_in; (void)out_size;
    const int*   src           = (const int*)  d_in[0];
    const int*   tgt           = (const int*)  d_in[1];
    const float* emb_src       = (const float*)d_in[2];
    const float* emb_tgt       = (const float*)d_in[3];
    const float* enc_wqkv      = (const float*)d_in[4];
    const float* enc_bqkv      = (const float*)d_in[5];
    const float* enc_wo        = (const float*)d_in[6];
    const float* enc_bo        = (const float*)d_in[7];
    const float* enc_gate_w    = (const float*)d_in[8];
    const float* enc_gate_b    = (const float*)d_in[9];
    const float* enc_w1        = (const float*)d_in[10];
    const float* enc_b1        = (const float*)d_in[11];
    const float* enc_w2        = (const float*)d_in[12];
    const float* enc_b2        = (const float*)d_in[13];
    const float* enc_ln        = (const float*)d_in[14];
    const float* dec_self_wqkv = (const float*)d_in[15];
    const float* dec_self_bqkv = (const float*)d_in[16];
    const float* dec_self_wo   = (const float*)d_in[17];
    const float* dec_self_bo   = (const float*)d_in[18];
    const float* dec_cross_wqkv= (const float*)d_in[19];
    const float* dec_cross_bqkv= (const float*)d_in[20];
    const float* dec_cross_wo  = (const float*)d_in[21];
    const float* dec_cross_bo  = (const float*)d_in[22];
    const float* dec_gate_w    = (const float*)d_in[23];
    const float* dec_gate_b    = (const float*)d_in[24];
    const float* dec_w1        = (const float*)d_in[25];
    const float* dec_b1        = (const float*)d_in[26];
    const float* dec_w2        = (const float*)d_in[27];
    const float* dec_b2        = (const float*)d_in[28];
    const float* dec_ln        = (const float*)d_in[29];
    const float* final_w       = (const float*)d_in[30];
    const float* final_b       = (const float*)d_in[31];
    float* out = (float*)d_out;

    cudaFuncSetAttribute(hgemm16<0,2>, cudaFuncAttributeMaxDynamicSharedMemorySize, SMEM_T2_BYTES);
    cudaFuncSetAttribute(hgemm16<5,2>, cudaFuncAttributeMaxDynamicSharedMemorySize, SMEM_T2_BYTES);
    cudaFuncSetAttribute(hgemm16<1,2>, cudaFuncAttributeMaxDynamicSharedMemorySize, SMEM_T2_BYTES);
    cudaFuncSetAttribute(hgemm16<2,2>, cudaFuncAttributeMaxDynamicSharedMemorySize, SMEM_T2_BYTES);
    cudaFuncSetAttribute(hgemm16<3,3>, cudaFuncAttributeMaxDynamicSharedMemorySize, SMEM_T3_BYTES);
    cudaFuncSetAttribute(hgemm16<4,3>, cudaFuncAttributeMaxDynamicSharedMemorySize, SMEM_T3_BYTES);
    cudaFuncSetAttribute(hgemm16_t1,   cudaFuncAttributeMaxDynamicSharedMemorySize, SMEM1S_BYTES);

    DevPtrs P;
    cudaGetSymbolAddress((void**)&P.x, g_x);
    cudaGetSymbolAddress((void**)&P.y, g_y);
    cudaGetSymbolAddress((void**)&P.xh, g_xh);
    cudaGetSymbolAddress((void**)&P.xl, g_xl);
    cudaGetSymbolAddress((void**)&P.yh, g_yh);
    cudaGetSymbolAddress((void**)&P.yl, g_yl);
    cudaGetSymbolAddress((void**)&P.lin, g_lin);
    cudaGetSymbolAddress((void**)&P.qph, g_qph);
    cudaGetSymbolAddress((void**)&P.qpl, g_qpl);
    cudaGetSymbolAddress((void**)&P.kph, g_kph);
    cudaGetSymbolAddress((void**)&P.kpl, g_kpl);
    cudaGetSymbolAddress((void**)&P.vth, g_vth);
    cudaGetSymbolAddress((void**)&P.vtl, g_vtl);
    cudaGetSymbolAddress((void**)&P.sph, g_sph);
    cudaGetSymbolAddress((void**)&P.spl, g_spl);
    cudaGetSymbolAddress((void**)&P.atth, g_atth);
    cudaGetSymbolAddress((void**)&P.attl, g_attl);
    cudaGetSymbolAddress((void**)&P.proj, g_proj);
    cudaGetSymbolAddress((void**)&P.h1h, g_h1h);
    cudaGetSymbolAddress((void**)&P.h1l, g_h1l);
    cudaGetSymbolAddress((void**)&P.moe0, g_moe0);
    cudaGetSymbolAddress((void**)&P.moe1, g_moe1);
    cudaGetSymbolAddress((void**)&P.gate, g_gate);
    cudaGetSymbolAddress((void**)&P.topw, g_topw);
    cudaGetSymbolAddress((void**)&P.list, g_list);
    cudaGetSymbolAddress((void**)&P.cnt, g_cnt);
    cudaGetSymbolAddress((void**)&P.wth, g_wth);
    cudaGetSymbolAddress((void**)&P.wtl, g_wtl);

    rope_init_kernel<<<(Sn * HD) / 256, 256>>>();

    // ---------- encoder ----------
    embed_kernel<<<(TOK * Dm / 2) / 256, 256>>>(src, emb_src, P.x, P.xh, P.xl);
    for (int l = 0; l < Ln; l++) {
        run_mha(P, P.x, P.xh, P.xl, P.xh, P.xl,
                enc_wqkv + (long long)l * 3 * Dm * Dm, enc_bqkv + l * 3 * Dm,
                enc_wo + (long long)l * Dm * Dm, enc_bo + l * Dm,
                enc_ln + ((l * 2 + 0) * 2 + 0) * Dm, enc_ln + ((l * 2 + 0) * 2 + 1) * Dm, 0);
        run_moe(P, P.x, P.xh, P.xl,
                enc_gate_w + l * Dm * En, enc_gate_b + l * En,
                enc_w1 + (long long)l * En * Dm * FF, enc_b1 + l * En * FF,
                enc_w2 + (long long)l * En * FF * Dm, enc_b2 + l * En * Dm,
                enc_ln + ((l * 2 + 1) * 2 + 0) * Dm, enc_ln + ((l * 2 + 1) * 2 + 1) * Dm);
    }

    // ---------- decoder ----------
    embed_kernel<<<(TOK * Dm / 2) / 256, 256>>>(tgt, emb_tgt, P.y, P.yh, P.yl);
    for (int l = 0; l < Ln; l++) {
        run_mha(P, P.y, P.yh, P.yl, P.yh, P.yl,
                dec_self_wqkv + (long long)l * 3 * Dm * Dm, dec_self_bqkv + l * 3 * Dm,
                dec_self_wo + (long long)l * Dm * Dm, dec_self_bo + l * Dm,
                dec_ln + ((l * 3 + 0) * 2 + 0) * Dm, dec_ln + ((l * 3 + 0) * 2 + 1) * Dm, 1);
        run_mha(P, P.y, P.yh, P.yl, P.xh, P.xl,
                dec_cross_wqkv + (long long)l * 3 * Dm * Dm, dec_cross_bqkv + l * 3 * Dm,
                dec_cross_wo + (long long)l * Dm * Dm, dec_cross_bo + l * Dm,
                dec_ln + ((l * 3 + 1) * 2 + 0) * Dm, dec_ln + ((l * 3 + 1) * 2 + 1) * Dm, 0);
        run_moe(P, P.y, P.yh, P.yl,
                dec_gate_w + l * Dm * En, dec_gate_b + l * En,
                dec_w1 + (long long)l * En * Dm * FF, dec_b1 + l * En * FF,
                dec_w2 + (long long)l * En * FF * Dm, dec_b2 + l * En * Dm,
                dec_ln + ((l * 3 + 2) * 2 + 0) * Dm, dec_ln + ((l * 3 + 2) * 2 + 1) * Dm);
    }

    // ---------- final projection (slim pure-fp16) ----------
    tsp(final_w, P.wth, P.wtl, Dm, VT, 1, 0, 0);
    {
        dim3 g(VT / 64, TOK / 128, 1);
        hgemm16_t1<<<g, 256, SMEM1S_BYTES>>>(P.yh, P.wth, final_b, out, TOK, VT, Dm, 1.f);
    }
}